// round 2
// baseline (speedup 1.0000x reference)
#include <cuda_runtime.h>

#define Bb   8
#define Pp   8192
#define CIN  64
#define KK   32
#define Mm   2048            // Pp/4
#define NROWS (Bb*Mm*KK)     // 524288
#define C0P  80              // 67 padded to 80
#define BN_EPS 1e-5f

// ---------------- scratch (device globals; no allocation) ----------------
__device__ __align__(128) float g_featsT[(size_t)Bb*Pp*CIN];      // 16 MB
__device__ __align__(128) float g_x0[(size_t)NROWS*C0P];          // 168 MB
__device__ __align__(128) float g_y1[(size_t)NROWS*64];           // 134 MB
__device__ __align__(128) float g_y2[(size_t)NROWS*64];           // 134 MB
__device__ __align__(128) float g_y3[(size_t)NROWS*128];          // 268 MB
__device__ __align__(128) float g_W1t[C0P*64];
__device__ __align__(128) float g_W2t[64*64];
__device__ __align__(128) float g_W3t[64*128];
__device__ double g_sum[3][128];
__device__ double g_sq[3][128];
__device__ float  g_s[3][128];
__device__ float  g_t[3][128];

// ---------------- prep: zero stats, transpose weights (zero-padded) ------
__global__ void prep_kernel(const float* __restrict__ W1,
                            const float* __restrict__ W2,
                            const float* __restrict__ W3)
{
    int tid = blockIdx.x * blockDim.x + threadIdx.x;
    if (tid < 384) { ((double*)g_sum)[tid] = 0.0; ((double*)g_sq)[tid] = 0.0; }
    if (tid < C0P*64) {            // W1t[k][c] , k in [0,80)
        int k = tid >> 6, c = tid & 63;
        g_W1t[tid] = (k < 67) ? W1[c*67 + k] : 0.f;
    }
    if (tid < 64*64) {             // W2t[k][c]
        int k = tid >> 6, c = tid & 63;
        g_W2t[tid] = W2[c*64 + k];
    }
    if (tid < 64*128) {            // W3t[k][c]
        int k = tid >> 7, c = tid & 127;
        g_W3t[tid] = W3[c*64 + k];
    }
}

// ---------------- feats (B,C,P) -> featsT (B,P,C) ------------------------
__global__ void transpose_kernel(const float* __restrict__ f)
{
    __shared__ float tile[32][33];
    int b  = blockIdx.z;
    int c0 = blockIdx.y * 32;
    int p0 = blockIdx.x * 32;
    int tx = threadIdx.x, ty = threadIdx.y;
    #pragma unroll
    for (int i = ty; i < 32; i += 8)
        tile[i][tx] = f[((size_t)b*CIN + c0 + i)*Pp + p0 + tx];
    __syncthreads();
    #pragma unroll
    for (int i = ty; i < 32; i += 8)
        g_featsT[((size_t)b*Pp + p0 + i)*CIN + c0 + tx] = tile[tx][i];
}

// ---------------- KNN + gather -------------------------------------------
__device__ __forceinline__ unsigned long long mkkey(float v, unsigned p)
{
    unsigned bb = __float_as_uint(v);
    bb = (bb & 0x80000000u) ? ~bb : (bb | 0x80000000u);
    return (((unsigned long long)bb) << 32) | p;
}

__global__ void __launch_bounds__(256) knn_gather_kernel(const float* __restrict__ xyz,
                                                         float* __restrict__ centers_out)
{
    int bm = blockIdx.x;
    int b  = bm >> 11;
    int m  = bm & 2047;
    __shared__ float ctr[3];
    __shared__ int   sel[KK];
    __shared__ unsigned long long red[8];
    __shared__ unsigned long long bestk_s;
    int tid = threadIdx.x;

    if (tid == 0) {
        int ci = (m == 2047) ? 8191
               : (int)(__fmul_rn(8191.0f, __fdiv_rn((float)m, 2047.0f)));
        const float* cp = xyz + ((size_t)b*Pp + ci)*3;
        float cx = cp[0], cy = cp[1], cz = cp[2];
        ctr[0] = cx; ctr[1] = cy; ctr[2] = cz;
        float* co = centers_out + (size_t)bm*3;
        co[0] = cx; co[1] = cy; co[2] = cz;
    }
    __syncthreads();
    float cx = ctr[0], cy = ctr[1], cz = ctr[2];
    float cn = __fadd_rn(__fadd_rn(__fmul_rn(cx,cx), __fmul_rn(cy,cy)), __fmul_rn(cz,cz));

    float d[32];
    #pragma unroll
    for (int j = 0; j < 32; j++) {
        int p = tid + j*256;
        const float* xp = xyz + ((size_t)b*Pp + p)*3;
        float x = xp[0], y = xp[1], z = xp[2];
        float xn = __fadd_rn(__fadd_rn(__fmul_rn(x,x), __fmul_rn(y,y)), __fmul_rn(z,z));
        float dt = __fadd_rn(__fadd_rn(__fmul_rn(cx,x), __fmul_rn(cy,y)), __fmul_rn(cz,z));
        d[j] = __fsub_rn(__fadd_rn(cn, xn), __fmul_rn(2.0f, dt));
    }

    unsigned long long loc = 0xFFFFFFFFFFFFFFFFULL;
    #pragma unroll
    for (int j = 0; j < 32; j++) {
        unsigned long long kk = mkkey(d[j], (unsigned)(tid + j*256));
        loc = (loc < kk) ? loc : kk;
    }

    for (int r = 0; r < KK; r++) {
        unsigned long long v = loc;
        #pragma unroll
        for (int o = 16; o > 0; o >>= 1) {
            unsigned long long u = __shfl_xor_sync(0xffffffffu, v, o);
            v = (v < u) ? v : u;
        }
        if ((tid & 31) == 0) red[tid >> 5] = v;
        __syncthreads();
        if (tid < 32) {
            unsigned long long w = (tid < 8) ? red[tid] : 0xFFFFFFFFFFFFFFFFULL;
            #pragma unroll
            for (int o = 4; o > 0; o >>= 1) {
                unsigned long long u = __shfl_xor_sync(0xffffffffu, w, o);
                w = (w < u) ? w : u;
            }
            if (tid == 0) bestk_s = w;
        }
        __syncthreads();
        unsigned selp = (unsigned)(bestk_s & 0xffffffffu);
        if (tid == 0) sel[r] = (int)selp;
        if ((selp & 255u) == (unsigned)tid) {
            int jj = (int)(selp >> 8);
            #pragma unroll
            for (int j = 0; j < 32; j++)
                if (j == jj) d[j] = __int_as_float(0x7f800000);
            loc = 0xFFFFFFFFFFFFFFFFULL;
            #pragma unroll
            for (int j = 0; j < 32; j++) {
                unsigned long long kk = mkkey(d[j], (unsigned)(tid + j*256));
                loc = (loc < kk) ? loc : kk;
            }
        }
        __syncthreads();
    }

    // gather: x0[n][0..2]=local_xyz, [3..66]=feats, [67..79]=0
    size_t rbase = (size_t)bm * KK;
    for (int q = tid; q < KK*C0P; q += 256) {
        int k = q / C0P, c = q % C0P;
        int p = sel[k];
        float v;
        if (c < 3)       v = xyz[((size_t)b*Pp + p)*3 + c] - ctr[c];
        else if (c < 67) v = g_featsT[((size_t)b*Pp + p)*CIN + (c - 3)];
        else             v = 0.f;
        g_x0[(rbase + k)*C0P + c] = v;
    }
}

// ---------------- fused GEMM (+input BN/ReLU) + channel stats ------------
template<int LAYER>
__global__ void __launch_bounds__(256) gemm_kernel(const float* __restrict__ bias)
{
    constexpr int CK   = (LAYER == 0) ? C0P : 64;
    constexpr int CO   = (LAYER == 2) ? 128 : 64;
    constexpr int ROWS = (LAYER == 2) ? 128 : 256;
    constexpr int CG = CO / 8;
    constexpr int CHUNKS = CK / 16;
    constexpr int AJ = ROWS * 16 / (256 * 4);     // float4 A-loads per thread
    constexpr int WJ = 16 * CO / (256 * 4);       // float4 W-loads per thread

    const float* __restrict__ A = (LAYER == 0) ? g_x0 : ((LAYER == 1) ? g_y1 : g_y2);
    const float* __restrict__ Wt = (LAYER == 0) ? g_W1t : ((LAYER == 1) ? g_W2t : g_W3t);
    float* __restrict__ Y = (LAYER == 0) ? g_y1 : ((LAYER == 1) ? g_y2 : g_y3);

    __shared__ __align__(16) float As[16 * ROWS];
    __shared__ __align__(16) float Ws[16 * CO];
    __shared__ float ssum[CO], ssq[CO];
    __shared__ float sS[CK], sT[CK];

    int tid = threadIdx.x;
    size_t rowBase = (size_t)blockIdx.x * ROWS;

    if (tid < CO) { ssum[tid] = 0.f; ssq[tid] = 0.f; }
    if (LAYER > 0 && tid < CK) { sS[tid] = g_s[LAYER-1][tid]; sT[tid] = g_t[LAYER-1][tid]; }
    __syncthreads();

    float acc[8][8];
    #pragma unroll
    for (int i = 0; i < 8; i++)
        #pragma unroll
        for (int j = 0; j < 8; j++) acc[i][j] = 0.f;

    const int arow = tid & (ROWS - 1);
    const int abase = tid / ROWS;
    const int rg = tid / CG, cg = tid % CG;

    for (int ch = 0; ch < CHUNKS; ch++) {
        #pragma unroll
        for (int j = 0; j < AJ; j++) {
            int c4 = j * (256 / ROWS) + abase;  // 0..3
            float4 av = *(const float4*)&A[(rowBase + arow)*CK + ch*16 + c4*4];
            if (LAYER > 0) {
                int k0 = ch*16 + c4*4;
                av.x = fmaxf(fmaf(av.x, sS[k0+0], sT[k0+0]), 0.f);
                av.y = fmaxf(fmaf(av.y, sS[k0+1], sT[k0+1]), 0.f);
                av.z = fmaxf(fmaf(av.z, sS[k0+2], sT[k0+2]), 0.f);
                av.w = fmaxf(fmaf(av.w, sS[k0+3], sT[k0+3]), 0.f);
            }
            As[(c4*4+0)*ROWS + arow] = av.x;
            As[(c4*4+1)*ROWS + arow] = av.y;
            As[(c4*4+2)*ROWS + arow] = av.z;
            As[(c4*4+3)*ROWS + arow] = av.w;
        }
        #pragma unroll
        for (int j = 0; j < WJ; j++) {
            int f = tid + j*256;
            *(float4*)&Ws[f*4] = *(const float4*)&Wt[(size_t)ch*16*CO + f*4];
        }
        __syncthreads();

        #pragma unroll
        for (int k = 0; k < 16; k++) {
            float4 a0 = *(const float4*)&As[k*ROWS + rg*8];
            float4 a1 = *(const float4*)&As[k*ROWS + rg*8 + 4];
            float4 w0 = *(const float4*)&Ws[k*CO + cg*8];
            float4 w1 = *(const float4*)&Ws[k*CO + cg*8 + 4];
            float a[8] = {a0.x,a0.y,a0.z,a0.w,a1.x,a1.y,a1.z,a1.w};
            float w[8] = {w0.x,w0.y,w0.z,w0.w,w1.x,w1.y,w1.z,w1.w};
            #pragma unroll
            for (int i = 0; i < 8; i++)
                #pragma unroll
                for (int jj = 0; jj < 8; jj++)
                    acc[i][jj] = fmaf(a[i], w[jj], acc[i][jj]);
        }
        __syncthreads();
    }

    // epilogue: add bias, write Y, accumulate channel stats
    float bj[8];
    #pragma unroll
    for (int j = 0; j < 8; j++) bj[j] = bias[cg*8 + j];
    float colsum[8], colsq[8];
    #pragma unroll
    for (int j = 0; j < 8; j++) { colsum[j] = 0.f; colsq[j] = 0.f; }

    #pragma unroll
    for (int i = 0; i < 8; i++) {
        size_t n = rowBase + (size_t)rg*8 + i;
        float v[8];
        #pragma unroll
        for (int j = 0; j < 8; j++) {
            v[j] = acc[i][j] + bj[j];
            colsum[j] += v[j];
            colsq[j]  = fmaf(v[j], v[j], colsq[j]);
        }
        float4 o0 = make_float4(v[0], v[1], v[2], v[3]);
        float4 o1 = make_float4(v[4], v[5], v[6], v[7]);
        *(float4*)&Y[n*CO + cg*8]     = o0;
        *(float4*)&Y[n*CO + cg*8 + 4] = o1;
    }
    #pragma unroll
    for (int j = 0; j < 8; j++) {
        atomicAdd(&ssum[cg*8 + j], colsum[j]);
        atomicAdd(&ssq [cg*8 + j], colsq[j]);
    }
    __syncthreads();
    if (tid < CO) {
        atomicAdd(&g_sum[LAYER][tid], (double)ssum[tid]);
        atomicAdd(&g_sq [LAYER][tid], (double)ssq [tid]);
    }
}

// ---------------- BN stats -> scale/shift --------------------------------
__global__ void finalize_kernel(int L, const float* __restrict__ g,
                                const float* __restrict__ beta, int Co)
{
    int c = threadIdx.x;
    if (c >= Co) return;
    double inv = 1.0 / (double)NROWS;
    double mu  = g_sum[L][c] * inv;
    double var = g_sq[L][c] * inv - mu*mu;
    if (var < 0.0) var = 0.0;
    float s = g[c] / sqrtf((float)var + BN_EPS);
    g_s[L][c] = s;
    g_t[L][c] = fmaf(-(float)mu, s, beta[c]);
}

// ---------------- BN+ReLU+maxpool over K, transposed write ---------------
__global__ void maxpool_kernel(float* __restrict__ out)
{
    int bm = blockIdx.x;
    int c  = threadIdx.x;   // 128
    float s = g_s[2][c], t = g_t[2][c];
    size_t rbase = (size_t)bm * KK;
    float mx = 0.f;         // relu(...) >= 0, so 0 == max of relu'ed values lower bound
    #pragma unroll
    for (int k = 0; k < KK; k++) {
        float v = fmaf(g_y3[(rbase + k)*128 + c], s, t);
        mx = fmaxf(mx, v);
    }
    int b = bm >> 11, m = bm & 2047;
    out[(size_t)Bb*Mm*3 + (size_t)b*(128*Mm) + (size_t)c*Mm + m] = mx;
}

// ---------------- launch ---------------------------------------------------
extern "C" void kernel_launch(void* const* d_in, const int* in_sizes, int n_in,
                              void* d_out, int out_size)
{
    (void)in_sizes; (void)n_in; (void)out_size;
    const float* xyz  = (const float*)d_in[0];
    const float* feats= (const float*)d_in[1];
    const float* W1   = (const float*)d_in[2];
    const float* b1   = (const float*)d_in[3];
    const float* g1   = (const float*)d_in[4];
    const float* be1  = (const float*)d_in[5];
    const float* W2   = (const float*)d_in[6];
    const float* b2   = (const float*)d_in[7];
    const float* g2   = (const float*)d_in[8];
    const float* be2  = (const float*)d_in[9];
    const float* W3   = (const float*)d_in[10];
    const float* b3   = (const float*)d_in[11];
    const float* g3   = (const float*)d_in[12];
    const float* be3  = (const float*)d_in[13];
    float* out = (float*)d_out;

    prep_kernel<<<32, 256>>>(W1, W2, W3);
    transpose_kernel<<<dim3(Pp/32, CIN/32, Bb), dim3(32, 8)>>>(feats);
    knn_gather_kernel<<<Bb*Mm, 256>>>(xyz, out);

    gemm_kernel<0><<<NROWS/256, 256>>>(b1);
    finalize_kernel<<<1, 64>>>(0, g1, be1, 64);
    gemm_kernel<1><<<NROWS/256, 256>>>(b2);
    finalize_kernel<<<1, 64>>>(1, g2, be2, 64);
    gemm_kernel<2><<<NROWS/128, 256>>>(b3);
    finalize_kernel<<<1, 128>>>(2, g3, be3, 128);

    maxpool_kernel<<<Bb*Mm, 128>>>(out);
}

// round 3
// speedup vs baseline: 1.1704x; 1.1704x over previous
#include <cuda_runtime.h>

#define Bb   8
#define Pp   8192
#define CIN  64
#define KK   32
#define Mm   2048            // Pp/4
#define NROWS (Bb*Mm*KK)     // 524288
#define C0P  68              // 67 padded to 68: [feats 64 | xyz 3 | 0]
#define BN_EPS 1e-5f

// ---------------- scratch (device globals; no allocation) ----------------
__device__ __align__(128) float g_featsT[(size_t)Bb*Pp*CIN];      // 16 MB
__device__ __align__(128) float g_x0[(size_t)NROWS*C0P];          // 143 MB
__device__ __align__(128) float g_y1[(size_t)NROWS*64];           // 134 MB
__device__ __align__(128) float g_y2[(size_t)NROWS*64];           // 134 MB
__device__ __align__(128) int   g_max[(size_t)Bb*128*Mm];         // 8 MB (encoded)
__device__ __align__(128) float g_W1t[C0P*64];
__device__ __align__(128) float g_W2t[64*64];
__device__ __align__(128) float g_W3t[64*128];
__device__ double g_sum[3][128];
__device__ double g_sq[3][128];
__device__ float  g_s[3][128];
__device__ float  g_t[3][128];

// packed f32x2 helpers
#define PACK2(dst, lo, hi)  asm("mov.b64 %0, {%1,%2};" : "=l"(dst) : "f"(lo), "f"(hi))
#define UNPACK2(lo, hi, v)  asm("mov.b64 {%0,%1}, %2;" : "=f"(lo), "=f"(hi) : "l"(v))
#define FMA2(acc, a, b)     asm("fma.rn.f32x2 %0, %1, %2, %3;" : "=l"(acc) : "l"(a), "l"(b), "l"(acc))

// ---------------- prep: zero stats, transpose weights (padded) -----------
__global__ void prep_kernel(const float* __restrict__ W1,
                            const float* __restrict__ W2,
                            const float* __restrict__ W3)
{
    int tid = blockIdx.x * blockDim.x + threadIdx.x;
    if (tid < 384) { ((double*)g_sum)[tid] = 0.0; ((double*)g_sq)[tid] = 0.0; }
    if (tid < C0P*64) {            // W1t[k][c]: k<64->feats weights, 64..66->xyz, 67->0
        int k = tid >> 6, c = tid & 63;
        float v = 0.f;
        if (k < 64)      v = W1[c*67 + (k + 3)];
        else if (k < 67) v = W1[c*67 + (k - 64)];
        g_W1t[tid] = v;
    }
    if (tid < 64*64) {
        int k = tid >> 6, c = tid & 63;
        g_W2t[tid] = W2[c*64 + k];
    }
    if (tid < 64*128) {
        int k = tid >> 7, c = tid & 127;
        g_W3t[tid] = W3[c*64 + k];
    }
}

// ---------------- feats (B,C,P) -> featsT (B,P,C) ------------------------
__global__ void transpose_kernel(const float* __restrict__ f)
{
    __shared__ float tile[32][33];
    int b  = blockIdx.z;
    int c0 = blockIdx.y * 32;
    int p0 = blockIdx.x * 32;
    int tx = threadIdx.x, ty = threadIdx.y;
    #pragma unroll
    for (int i = ty; i < 32; i += 8)
        tile[i][tx] = f[((size_t)b*CIN + c0 + i)*Pp + p0 + tx];
    __syncthreads();
    #pragma unroll
    for (int i = ty; i < 32; i += 8)
        g_featsT[((size_t)b*Pp + p0 + i)*CIN + c0 + tx] = tile[tx][i];
}

// ---------------- KNN (radix-select on u64 keys) + gather -----------------
__global__ void __launch_bounds__(256) knn_gather_kernel(const float* __restrict__ xyz,
                                                         float* __restrict__ centers_out)
{
    int bm = blockIdx.x;
    int b  = bm >> 11;
    int m  = bm & 2047;
    __shared__ float ctr[3];
    __shared__ unsigned int hist[256];
    __shared__ unsigned long long s_prefix;
    __shared__ int s_remaining;
    __shared__ int sel[KK];
    __shared__ int s_cnt;
    int tid = threadIdx.x;

    if (tid == 0) {
        int ci = (m == 2047) ? 8191
               : (int)(__fmul_rn(8191.0f, __fdiv_rn((float)m, 2047.0f)));
        const float* cp = xyz + ((size_t)b*Pp + ci)*3;
        float cx = cp[0], cy = cp[1], cz = cp[2];
        ctr[0] = cx; ctr[1] = cy; ctr[2] = cz;
        float* co = centers_out + (size_t)bm*3;
        co[0] = cx; co[1] = cy; co[2] = cz;
        s_prefix = 0ULL; s_remaining = KK; s_cnt = 0;
    }
    __syncthreads();
    float cx = ctr[0], cy = ctr[1], cz = ctr[2];
    float cn = __fadd_rn(__fadd_rn(__fmul_rn(cx,cx), __fmul_rn(cy,cy)), __fmul_rn(cz,cz));

    // mapped (order-preserving) distance bits, point p = tid + j*256
    unsigned int dm[32];
    #pragma unroll
    for (int j = 0; j < 32; j++) {
        int p = tid + j*256;
        const float* xp = xyz + ((size_t)b*Pp + p)*3;
        float x = xp[0], y = xp[1], z = xp[2];
        float xn = __fadd_rn(__fadd_rn(__fmul_rn(x,x), __fmul_rn(y,y)), __fmul_rn(z,z));
        float dt = __fadd_rn(__fadd_rn(__fmul_rn(cx,x), __fmul_rn(cy,y)), __fmul_rn(cz,z));
        float d  = __fsub_rn(__fadd_rn(cn, xn), __fmul_rn(2.0f, dt));
        unsigned u = __float_as_uint(d);
        dm[j] = (u & 0x80000000u) ? ~u : (u | 0x80000000u);
    }

    // 8 passes x 8 bits over key = (dm << 32) | idx  -> exact 32nd-smallest key
    for (int pass = 0; pass < 8; pass++) {
        hist[tid] = 0;
        __syncthreads();
        unsigned long long pref = s_prefix;
        int sh = 56 - 8*pass;
        #pragma unroll
        for (int j = 0; j < 32; j++) {
            unsigned long long key =
                (((unsigned long long)dm[j]) << 32) | (unsigned)(tid + j*256);
            bool match = (pass == 0) || ((key >> (sh + 8)) == pref);
            if (match) atomicAdd(&hist[(unsigned)(key >> sh) & 255u], 1u);
        }
        __syncthreads();
        if (tid < 32) {
            int lane = tid;
            unsigned cum[8];
            unsigned run = 0;
            #pragma unroll
            for (int i = 0; i < 8; i++) { run += hist[lane*8 + i]; cum[i] = run; }
            unsigned tot = run;
            unsigned off = tot;
            #pragma unroll
            for (int dd = 1; dd < 32; dd <<= 1) {
                unsigned v = __shfl_up_sync(0xffffffffu, off, dd);
                if (lane >= dd) off += v;
            }
            off -= tot;                      // exclusive prefix across lanes
            unsigned rem = (unsigned)s_remaining;
            #pragma unroll
            for (int i = 0; i < 8; i++) {
                unsigned prev = off + (i ? cum[i-1] : 0u);
                unsigned cu   = off + cum[i];
                if (prev < rem && cu >= rem) {
                    s_prefix = (s_prefix << 8) | (unsigned)(lane*8 + i);
                    s_remaining = (int)(rem - prev);
                }
            }
        }
        __syncthreads();
    }
    unsigned long long thr = s_prefix;   // exact 32nd-smallest key

    #pragma unroll
    for (int j = 0; j < 32; j++) {
        unsigned long long key =
            (((unsigned long long)dm[j]) << 32) | (unsigned)(tid + j*256);
        if (key <= thr) {
            int s = atomicAdd(&s_cnt, 1);
            sel[s] = tid + j*256;
        }
    }
    __syncthreads();

    // gather: x0[n][0..63]=feats, [64..66]=local_xyz, [67]=0
    size_t rbase = (size_t)bm * KK;
    for (int q = tid; q < KK*C0P; q += 256) {
        int k = q / C0P, c = q - k*C0P;
        int p = sel[k];
        float v;
        if (c < 64)      v = g_featsT[((size_t)b*Pp + p)*CIN + c];
        else if (c < 67) v = xyz[((size_t)b*Pp + p)*3 + (c - 64)] - ctr[c - 64];
        else             v = 0.f;
        g_x0[(rbase + k)*C0P + c] = v;
    }
}

// ---------------- fused GEMM (+input BN/ReLU) + stats (+max for L2) ------
template<int LAYER>
__global__ void __launch_bounds__(256) gemm_kernel(const float* __restrict__ bias)
{
    constexpr int CK   = (LAYER == 0) ? 64 : 64;   // main-chunk K (L0 has +4 tail)
    constexpr int LDA  = (LAYER == 0) ? C0P : 64;
    constexpr int CO   = (LAYER == 2) ? 128 : 64;
    constexpr int ROWS = (LAYER == 2) ? 128 : 256;
    constexpr int CG = CO / 8;
    constexpr int CHUNKS = CK / 16;
    constexpr int AJ = ROWS * 16 / (256 * 4);
    constexpr int WJ = 16 * CO / (256 * 4);

    const float* __restrict__ A  = (LAYER == 0) ? g_x0 : ((LAYER == 1) ? g_y1 : g_y2);
    const float* __restrict__ Wt = (LAYER == 0) ? g_W1t : ((LAYER == 1) ? g_W2t : g_W3t);
    float* __restrict__ Y = (LAYER == 0) ? g_y1 : g_y2;

    __shared__ __align__(16) float As[16 * ROWS];
    __shared__ __align__(16) float Ws[16 * CO];
    __shared__ float ssum[CO], ssq[CO];
    __shared__ float sS[64], sT[64];
    __shared__ int smax[(LAYER == 2) ? 512 : 1];

    int tid = threadIdx.x;
    size_t rowBase = (size_t)blockIdx.x * ROWS;

    if (tid < CO) { ssum[tid] = 0.f; ssq[tid] = 0.f; }
    if (LAYER > 0 && tid < 64) { sS[tid] = g_s[LAYER-1][tid]; sT[tid] = g_t[LAYER-1][tid]; }
    if (LAYER == 2) { for (int t = tid; t < 512; t += 256) smax[t] = (int)0x80000000; }
    __syncthreads();

    unsigned long long acc[8][4];
    #pragma unroll
    for (int i = 0; i < 8; i++)
        #pragma unroll
        for (int j = 0; j < 4; j++) acc[i][j] = 0ULL;

    const int arow  = tid & (ROWS - 1);
    const int abase = tid / ROWS;
    const int rg = tid / CG, cg = tid % CG;

    auto mma_step = [&](const float* AsK, const float* WsK) {
        float4 a0 = *(const float4*)(AsK + rg*8);
        float4 a1 = *(const float4*)(AsK + rg*8 + 4);
        float4 w0 = *(const float4*)(WsK + cg*8);
        float4 w1 = *(const float4*)(WsK + cg*8 + 4);
        unsigned long long wp0, wp1, wp2, wp3;
        PACK2(wp0, w0.x, w0.y); PACK2(wp1, w0.z, w0.w);
        PACK2(wp2, w1.x, w1.y); PACK2(wp3, w1.z, w1.w);
        float a[8] = {a0.x,a0.y,a0.z,a0.w,a1.x,a1.y,a1.z,a1.w};
        #pragma unroll
        for (int i = 0; i < 8; i++) {
            unsigned long long ap;
            PACK2(ap, a[i], a[i]);
            FMA2(acc[i][0], ap, wp0);
            FMA2(acc[i][1], ap, wp1);
            FMA2(acc[i][2], ap, wp2);
            FMA2(acc[i][3], ap, wp3);
        }
    };

    #pragma unroll
    for (int ch = 0; ch < CHUNKS; ch++) {
        #pragma unroll
        for (int j = 0; j < AJ; j++) {
            int c4 = j * (256 / ROWS) + abase;
            float4 av = *(const float4*)&A[(rowBase + arow)*LDA + ch*16 + c4*4];
            if (LAYER > 0) {
                int k0 = ch*16 + c4*4;
                av.x = fmaxf(fmaf(av.x, sS[k0+0], sT[k0+0]), 0.f);
                av.y = fmaxf(fmaf(av.y, sS[k0+1], sT[k0+1]), 0.f);
                av.z = fmaxf(fmaf(av.z, sS[k0+2], sT[k0+2]), 0.f);
                av.w = fmaxf(fmaf(av.w, sS[k0+3], sT[k0+3]), 0.f);
            }
            As[(c4*4+0)*ROWS + arow] = av.x;
            As[(c4*4+1)*ROWS + arow] = av.y;
            As[(c4*4+2)*ROWS + arow] = av.z;
            As[(c4*4+3)*ROWS + arow] = av.w;
        }
        #pragma unroll
        for (int j = 0; j < WJ; j++) {
            int f = tid + j*256;
            *(float4*)&Ws[f*4] = *(const float4*)&Wt[(size_t)ch*16*CO + f*4];
        }
        __syncthreads();
        #pragma unroll
        for (int k = 0; k < 16; k++)
            mma_step(&As[k*ROWS], &Ws[k*CO]);
        __syncthreads();
    }

    if (LAYER == 0) {   // 4-wide K tail (cols 64..67; 67 is zero pad)
        float4 av = *(const float4*)&A[(rowBase + tid)*LDA + 64];
        As[0*ROWS + tid] = av.x;
        As[1*ROWS + tid] = av.y;
        As[2*ROWS + tid] = av.z;
        As[3*ROWS + tid] = av.w;
        Ws[tid] = Wt[64*64 + tid];      // rows 64..67 of W1t (4*64 floats)
        __syncthreads();
        #pragma unroll
        for (int k = 0; k < 4; k++)
            mma_step(&As[k*ROWS], &Ws[k*CO]);
        __syncthreads();
    }

    // epilogue
    float bj[8];
    #pragma unroll
    for (int j = 0; j < 8; j++) bj[j] = bias[cg*8 + j];
    float colsum[8], colsq[8], colmax[8];
    #pragma unroll
    for (int j = 0; j < 8; j++) { colsum[j] = 0.f; colsq[j] = 0.f; colmax[j] = -3.4e38f; }

    #pragma unroll
    for (int i = 0; i < 8; i++) {
        float v[8];
        #pragma unroll
        for (int j = 0; j < 4; j++) {
            float lo, hi;
            UNPACK2(lo, hi, acc[i][j]);
            v[j*2] = lo + bj[j*2];
            v[j*2+1] = hi + bj[j*2+1];
        }
        #pragma unroll
        for (int j = 0; j < 8; j++) {
            colsum[j] += v[j];
            colsq[j]  = fmaf(v[j], v[j], colsq[j]);
            if (LAYER == 2) colmax[j] = fmaxf(colmax[j], v[j]);
        }
        if (LAYER < 2) {
            size_t n = rowBase + (size_t)rg*8 + i;
            *(float4*)&Y[n*CO + cg*8]     = make_float4(v[0], v[1], v[2], v[3]);
            *(float4*)&Y[n*CO + cg*8 + 4] = make_float4(v[4], v[5], v[6], v[7]);
        }
    }
    #pragma unroll
    for (int j = 0; j < 8; j++) {
        atomicAdd(&ssum[cg*8 + j], colsum[j]);
        atomicAdd(&ssq [cg*8 + j], colsq[j]);
    }
    if (LAYER == 2) {
        int q = rg >> 2;      // ROWS=128: rows rg*8..rg*8+7 all in 32-row group q
        #pragma unroll
        for (int j = 0; j < 8; j++) {
            int ik = __float_as_int(colmax[j]);
            ik ^= ((ik >> 31) & 0x7fffffff);
            atomicMax(&smax[q*128 + cg*8 + j], ik);
        }
    }
    __syncthreads();
    if (tid < CO) {
        atomicAdd(&g_sum[LAYER][tid], (double)ssum[tid]);
        atomicAdd(&g_sq [LAYER][tid], (double)ssq [tid]);
    }
    if (LAYER == 2) {
        for (int t = tid; t < 512; t += 256) {
            int qq = t >> 7, c = t & 127;
            int bmv = (int)(rowBase >> 5) + qq;
            int bb = bmv >> 11, mm = bmv & 2047;
            g_max[((size_t)bb*128 + c)*2048 + mm] = smax[t];
        }
    }
}

// ---------------- BN stats -> scale/shift --------------------------------
__global__ void finalize_kernel(int L, const float* __restrict__ g,
                                const float* __restrict__ beta, int Co)
{
    int c = threadIdx.x;
    if (c >= Co) return;
    double inv = 1.0 / (double)NROWS;
    double mu  = g_sum[L][c] * inv;
    double var = g_sq[L][c] * inv - mu*mu;
    if (var < 0.0) var = 0.0;
    float s = g[c] / sqrtf((float)var + BN_EPS);
    g_s[L][c] = s;
    g_t[L][c] = fmaf(-(float)mu, s, beta[c]);
}

// ---------------- BN+ReLU on pre-pooled max, transposed layout -----------
__global__ void maxpool_kernel(float* __restrict__ out)
{
    int i = blockIdx.x * blockDim.x + threadIdx.x;   // over B*128*M = 2M
    int c = (i >> 11) & 127;
    float s = g_s[2][c], t = g_t[2][c];
    int key = g_max[i];
    key ^= ((key >> 31) & 0x7fffffff);
    float y = __int_as_float(key);
    out[(size_t)Bb*Mm*3 + i] = fmaxf(fmaf(y, s, t), 0.f);
}

// ---------------- launch ---------------------------------------------------
extern "C" void kernel_launch(void* const* d_in, const int* in_sizes, int n_in,
                              void* d_out, int out_size)
{
    (void)in_sizes; (void)n_in; (void)out_size;
    const float* xyz  = (const float*)d_in[0];
    const float* feats= (const float*)d_in[1];
    const float* W1   = (const float*)d_in[2];
    const float* b1   = (const float*)d_in[3];
    const float* g1   = (const float*)d_in[4];
    const float* be1  = (const float*)d_in[5];
    const float* W2   = (const float*)d_in[6];
    const float* b2   = (const float*)d_in[7];
    const float* g2   = (const float*)d_in[8];
    const float* be2  = (const float*)d_in[9];
    const float* W3   = (const float*)d_in[10];
    const float* b3   = (const float*)d_in[11];
    const float* g3   = (const float*)d_in[12];
    const float* be3  = (const float*)d_in[13];
    float* out = (float*)d_out;

    prep_kernel<<<32, 256>>>(W1, W2, W3);
    transpose_kernel<<<dim3(Pp/32, CIN/32, Bb), dim3(32, 8)>>>(feats);
    knn_gather_kernel<<<Bb*Mm, 256>>>(xyz, out);

    gemm_kernel<0><<<NROWS/256, 256>>>(b1);
    finalize_kernel<<<1, 64>>>(0, g1, be1, 64);
    gemm_kernel<1><<<NROWS/256, 256>>>(b2);
    finalize_kernel<<<1, 64>>>(1, g2, be2, 64);
    gemm_kernel<2><<<NROWS/128, 256>>>(b3);
    finalize_kernel<<<1, 128>>>(2, g3, be3, 128);

    maxpool_kernel<<<(Bb*Mm*128)/256, 256>>>(out);
}

// round 4
// speedup vs baseline: 1.5215x; 1.2999x over previous
#include <cuda_runtime.h>

#define Bb   8
#define Pp   8192
#define CIN  64
#define KK   32
#define Mm   2048            // Pp/4
#define NROWS (Bb*Mm*KK)     // 524288
#define BN_EPS 1e-5f

// ---------------- scratch (device globals; no allocation) ----------------
__device__ __align__(128) float g_featsT[(size_t)Bb*Pp*CIN];      // 16 MB
__device__ __align__(128) int   g_sel[(size_t)NROWS];             // 2 MB
__device__ __align__(128) float g_y1[(size_t)NROWS*64];           // 134 MB
__device__ __align__(128) float g_y2[(size_t)NROWS*64];           // 134 MB
__device__ __align__(128) int   g_max[(size_t)Bb*128*Mm];         // 8 MB (encoded)
__device__ __align__(128) float g_W1t[68*64];                     // [feats64|xyz3|0]
__device__ __align__(128) float g_W2t[64*64];
__device__ __align__(128) float g_W3t[64*128];
__device__ double g_sum[3][128];
__device__ double g_sq[3][128];
__device__ float  g_s[3][128];
__device__ float  g_t[3][128];

// packed f32x2 helpers
#define PACK2(dst, lo, hi)  asm("mov.b64 %0, {%1,%2};" : "=l"(dst) : "f"(lo), "f"(hi))
#define UNPACK2(lo, hi, v)  asm("mov.b64 {%0,%1}, %2;" : "=f"(lo), "=f"(hi) : "l"(v))
#define FMA2(acc, a, b)     asm("fma.rn.f32x2 %0, %1, %2, %3;" : "=l"(acc) : "l"(a), "l"(b), "l"(acc))

// ---------------- prep: zero stats, transpose weights (padded) -----------
__global__ void prep_kernel(const float* __restrict__ W1,
                            const float* __restrict__ W2,
                            const float* __restrict__ W3)
{
    int tid = blockIdx.x * blockDim.x + threadIdx.x;
    if (tid < 384) { ((double*)g_sum)[tid] = 0.0; ((double*)g_sq)[tid] = 0.0; }
    if (tid < 68*64) {             // W1t[k][c]: k<64->feats, 64..66->xyz, 67->0
        int k = tid >> 6, c = tid & 63;
        float v = 0.f;
        if (k < 64)      v = W1[c*67 + (k + 3)];
        else if (k < 67) v = W1[c*67 + (k - 64)];
        g_W1t[tid] = v;
    }
    if (tid < 64*64) {
        int k = tid >> 6, c = tid & 63;
        g_W2t[tid] = W2[c*64 + k];
    }
    if (tid < 64*128) {
        int k = tid >> 7, c = tid & 127;
        g_W3t[tid] = W3[c*64 + k];
    }
}

// ---------------- feats (B,C,P) -> featsT (B,P,C) ------------------------
__global__ void transpose_kernel(const float* __restrict__ f)
{
    __shared__ float tile[32][33];
    int b  = blockIdx.z;
    int c0 = blockIdx.y * 32;
    int p0 = blockIdx.x * 32;
    int tx = threadIdx.x, ty = threadIdx.y;
    #pragma unroll
    for (int i = ty; i < 32; i += 8)
        tile[i][tx] = f[((size_t)b*CIN + c0 + i)*Pp + p0 + tx];
    __syncthreads();
    #pragma unroll
    for (int i = ty; i < 32; i += 8)
        g_featsT[((size_t)b*Pp + p0 + i)*CIN + c0 + tx] = tile[tx][i];
}

// ---------------- KNN: 4-pass radix-select on 32-bit distance ------------
__global__ void __launch_bounds__(256) knn_kernel(const float* __restrict__ xyz,
                                                  float* __restrict__ centers_out)
{
    int bm = blockIdx.x;
    int b  = bm >> 11;
    int m  = bm & 2047;
    __shared__ float ctr[3];
    __shared__ unsigned int hist[256];
    __shared__ unsigned int s_prefix;
    __shared__ int s_remaining;
    __shared__ int s_cnt;
    __shared__ int s_min;
    __shared__ int s_last;
    int tid  = threadIdx.x;
    int lane = tid & 31;

    if (tid == 0) {
        int ci = (m == 2047) ? 8191
               : (int)(__fmul_rn(8191.0f, __fdiv_rn((float)m, 2047.0f)));
        const float* cp = xyz + ((size_t)b*Pp + ci)*3;
        float cx = cp[0], cy = cp[1], cz = cp[2];
        ctr[0] = cx; ctr[1] = cy; ctr[2] = cz;
        float* co = centers_out + (size_t)bm*3;
        co[0] = cx; co[1] = cy; co[2] = cz;
        s_prefix = 0u; s_remaining = KK; s_cnt = 0; s_last = -1;
    }
    __syncthreads();
    float cx = ctr[0], cy = ctr[1], cz = ctr[2];
    float cn = __fadd_rn(__fadd_rn(__fmul_rn(cx,cx), __fmul_rn(cy,cy)), __fmul_rn(cz,cz));

    // order-preserving mapped distance bits; point p = tid + j*256
    unsigned int dm[32];
    #pragma unroll
    for (int j = 0; j < 32; j++) {
        int p = tid + j*256;
        const float* xp = xyz + ((size_t)b*Pp + p)*3;
        float x = xp[0], y = xp[1], z = xp[2];
        float xn = __fadd_rn(__fadd_rn(__fmul_rn(x,x), __fmul_rn(y,y)), __fmul_rn(z,z));
        float dt = __fadd_rn(__fadd_rn(__fmul_rn(cx,x), __fmul_rn(cy,y)), __fmul_rn(cz,z));
        float d  = __fsub_rn(__fadd_rn(cn, xn), __fmul_rn(2.0f, dt));
        unsigned u = __float_as_uint(d);
        dm[j] = (u & 0x80000000u) ? ~u : (u | 0x80000000u);
    }

    // 4 passes x 8 bits -> exact 32nd-smallest distance value D*
    for (int pass = 0; pass < 4; pass++) {
        hist[tid] = 0;
        __syncthreads();
        unsigned pref = s_prefix;
        int sh = 24 - 8*pass;
        #pragma unroll
        for (int j = 0; j < 32; j++) {
            bool ok = (pass == 0) || ((dm[j] >> (sh + 8)) == pref);
            unsigned bkt = (dm[j] >> sh) & 255u;
            unsigned mask = __ballot_sync(0xffffffffu, ok);
            if (ok) {
                unsigned peers = __match_any_sync(mask, bkt);
                if ((peers & ((1u << lane) - 1u)) == 0u)   // lowest peer lane
                    atomicAdd(&hist[bkt], __popc(peers));
            }
        }
        __syncthreads();
        if (tid < 32) {
            unsigned cum[8];
            unsigned run = 0;
            #pragma unroll
            for (int i = 0; i < 8; i++) { run += hist[tid*8 + i]; cum[i] = run; }
            unsigned tot = run;
            unsigned off = tot;
            #pragma unroll
            for (int dd = 1; dd < 32; dd <<= 1) {
                unsigned v = __shfl_up_sync(0xffffffffu, off, dd);
                if (lane >= dd) off += v;
            }
            off -= tot;                      // exclusive prefix across lanes
            unsigned rem = (unsigned)s_remaining;
            #pragma unroll
            for (int i = 0; i < 8; i++) {
                unsigned prev = off + (i ? cum[i-1] : 0u);
                unsigned cu   = off + cum[i];
                if (prev < rem && cu >= rem) {
                    s_prefix = (s_prefix << 8) | (unsigned)(tid*8 + i);
                    s_remaining = (int)(rem - prev);
                }
            }
        }
        __syncthreads();
    }
    unsigned thr = s_prefix;      // exact K-th smallest distance bits
    int rem = s_remaining;        // how many to take among dm == thr (>=1)

    int* selg = g_sel + (size_t)bm * KK;
    #pragma unroll
    for (int j = 0; j < 32; j++) {
        if (dm[j] < thr) {
            int s = atomicAdd(&s_cnt, 1);
            selg[s] = tid + j*256;
        }
    }
    __syncthreads();
    int base = s_cnt;             // == KK - rem
    // ties: pick 'rem' smallest indices among dm == thr (usually rem == 1)
    for (int r = 0; r < rem; r++) {
        if (tid == 0) s_min = 0x7fffffff;
        __syncthreads();
        int last = s_last;
        #pragma unroll
        for (int j = 0; j < 32; j++) {
            int p = tid + j*256;
            if (dm[j] == thr && p > last) atomicMin(&s_min, p);
        }
        __syncthreads();
        if (tid == 0) { selg[base + r] = s_min; s_last = s_min; }
        __syncthreads();
    }
}

// ------- fused GEMM: gather(L0) / BN+ReLU(L1,L2) + stats (+max for L2) ----
template<int LAYER>
__global__ void __launch_bounds__(256) gemm_kernel(const float* __restrict__ bias,
                                                   const float* __restrict__ xyz,
                                                   const float* __restrict__ centers)
{
    constexpr int CO   = (LAYER == 2) ? 128 : 64;
    constexpr int ROWS = (LAYER == 2) ? 128 : 256;
    constexpr int CG = CO / 8;
    constexpr int CHUNKS = 4;                    // main K = 64 (L0 has +4 tail)
    constexpr int AJ = ROWS * 16 / (256 * 4);    // float4 A-loads per thread
    constexpr int WJ = 16 * CO / (256 * 4);      // float4 W-loads per thread

    const float* __restrict__ A  = (LAYER == 1) ? g_y1 : g_y2;   // unused for L0
    const float* __restrict__ Wt = (LAYER == 0) ? g_W1t : ((LAYER == 1) ? g_W2t : g_W3t);
    float* __restrict__ Y = (LAYER == 0) ? g_y1 : g_y2;

    __shared__ __align__(16) float As[2][16 * ROWS];
    __shared__ __align__(16) float Ws[2][16 * CO];
    __shared__ float ssum[CO], ssq[CO];
    __shared__ float sS[64], sT[64];
    __shared__ int s_sel[(LAYER == 0) ? ROWS : 1];
    __shared__ int smax[(LAYER == 2) ? 512 : 1];

    int tid = threadIdx.x;
    size_t rowBase = (size_t)blockIdx.x * ROWS;
    const int bBat = (int)(rowBase >> 16);       // 65536 rows per batch

    if (tid < CO) { ssum[tid] = 0.f; ssq[tid] = 0.f; }
    if (LAYER > 0 && tid < 64) { sS[tid] = g_s[LAYER-1][tid]; sT[tid] = g_t[LAYER-1][tid]; }
    if (LAYER == 0) {
        for (int t = tid; t < ROWS; t += 256) s_sel[t] = g_sel[rowBase + t];
    }
    if (LAYER == 2) { for (int t = tid; t < 512; t += 256) smax[t] = (int)0x80000000; }
    __syncthreads();

    unsigned long long acc[8][4];
    #pragma unroll
    for (int i = 0; i < 8; i++)
        #pragma unroll
        for (int j = 0; j < 4; j++) acc[i][j] = 0ULL;

    const int arow  = tid & (ROWS - 1);
    const int abase = tid / ROWS;
    const int rg = tid / CG, cg = tid % CG;

    float4 pA[AJ];
    float4 pW[WJ];

    auto loadA = [&](int ch) {
        #pragma unroll
        for (int j = 0; j < AJ; j++) {
            int c4 = j * (256 / ROWS) + abase;
            if (LAYER == 0) {
                int p = s_sel[arow];
                pA[j] = *(const float4*)&g_featsT[(((size_t)bBat << 13) + p)*CIN
                                                  + ch*16 + c4*4];
            } else {
                pA[j] = *(const float4*)&A[(rowBase + arow)*64 + ch*16 + c4*4];
            }
        }
    };
    auto loadW = [&](int ch) {
        #pragma unroll
        for (int j = 0; j < WJ; j++) {
            int f = tid + j*256;
            pW[j] = *(const float4*)&Wt[(size_t)ch*16*CO + f*4];
        }
    };
    auto storeTiles = [&](int buf, int ch) {
        #pragma unroll
        for (int j = 0; j < AJ; j++) {
            int c4 = j * (256 / ROWS) + abase;
            float4 av = pA[j];
            if (LAYER > 0) {
                int k0 = ch*16 + c4*4;
                av.x = fmaxf(fmaf(av.x, sS[k0+0], sT[k0+0]), 0.f);
                av.y = fmaxf(fmaf(av.y, sS[k0+1], sT[k0+1]), 0.f);
                av.z = fmaxf(fmaf(av.z, sS[k0+2], sT[k0+2]), 0.f);
                av.w = fmaxf(fmaf(av.w, sS[k0+3], sT[k0+3]), 0.f);
            }
            As[buf][(c4*4+0)*ROWS + arow] = av.x;
            As[buf][(c4*4+1)*ROWS + arow] = av.y;
            As[buf][(c4*4+2)*ROWS + arow] = av.z;
            As[buf][(c4*4+3)*ROWS + arow] = av.w;
        }
        #pragma unroll
        for (int j = 0; j < WJ; j++) {
            int f = tid + j*256;
            *(float4*)&Ws[buf][f*4] = pW[j];
        }
    };
    auto mma_step = [&](const float* AsK, const float* WsK) {
        float4 a0 = *(const float4*)(AsK + rg*8);
        float4 a1 = *(const float4*)(AsK + rg*8 + 4);
        float4 w0 = *(const float4*)(WsK + cg*8);
        float4 w1 = *(const float4*)(WsK + cg*8 + 4);
        unsigned long long wp0, wp1, wp2, wp3;
        PACK2(wp0, w0.x, w0.y); PACK2(wp1, w0.z, w0.w);
        PACK2(wp2, w1.x, w1.y); PACK2(wp3, w1.z, w1.w);
        float a[8] = {a0.x,a0.y,a0.z,a0.w,a1.x,a1.y,a1.z,a1.w};
        #pragma unroll
        for (int i = 0; i < 8; i++) {
            unsigned long long ap;
            PACK2(ap, a[i], a[i]);
            FMA2(acc[i][0], ap, wp0);
            FMA2(acc[i][1], ap, wp1);
            FMA2(acc[i][2], ap, wp2);
            FMA2(acc[i][3], ap, wp3);
        }
    };

    loadA(0); loadW(0);
    #pragma unroll
    for (int ch = 0; ch < CHUNKS; ch++) {
        int buf = ch & 1;
        storeTiles(buf, ch);
        __syncthreads();
        if (ch + 1 < CHUNKS) { loadA(ch + 1); loadW(ch + 1); }
        #pragma unroll
        for (int k = 0; k < 16; k++)
            mma_step(&As[buf][k*ROWS], &Ws[buf][k*CO]);
    }

    if (LAYER == 0) {   // K tail: cols 64..67 = [local_xyz | 0]
        int p  = s_sel[tid];
        int bm = (int)((rowBase + tid) >> 5);
        const float* cp = centers + (size_t)bm*3;
        const float* xp = xyz + (((size_t)bBat << 13) + p)*3;
        As[0][0*ROWS + tid] = xp[0] - cp[0];
        As[0][1*ROWS + tid] = xp[1] - cp[1];
        As[0][2*ROWS + tid] = xp[2] - cp[2];
        As[0][3*ROWS + tid] = 0.f;
        Ws[0][tid] = Wt[64*64 + tid];      // rows 64..67 of W1t (4*64 floats)
        __syncthreads();
        #pragma unroll
        for (int k = 0; k < 4; k++)
            mma_step(&As[0][k*ROWS], &Ws[0][k*CO]);
    }

    // epilogue
    float bj[8];
    #pragma unroll
    for (int j = 0; j < 8; j++) bj[j] = bias[cg*8 + j];
    float colsum[8], colsq[8], colmax[8];
    #pragma unroll
    for (int j = 0; j < 8; j++) { colsum[j] = 0.f; colsq[j] = 0.f; colmax[j] = -3.4e38f; }

    #pragma unroll
    for (int i = 0; i < 8; i++) {
        float v[8];
        #pragma unroll
        for (int j = 0; j < 4; j++) {
            float lo, hi;
            UNPACK2(lo, hi, acc[i][j]);
            v[j*2]   = lo + bj[j*2];
            v[j*2+1] = hi + bj[j*2+1];
        }
        #pragma unroll
        for (int j = 0; j < 8; j++) {
            colsum[j] += v[j];
            colsq[j]  = fmaf(v[j], v[j], colsq[j]);
            if (LAYER == 2) colmax[j] = fmaxf(colmax[j], v[j]);
        }
        if (LAYER < 2) {
            size_t n = rowBase + (size_t)rg*8 + i;
            *(float4*)&Y[n*CO + cg*8]     = make_float4(v[0], v[1], v[2], v[3]);
            *(float4*)&Y[n*CO + cg*8 + 4] = make_float4(v[4], v[5], v[6], v[7]);
        }
    }
    #pragma unroll
    for (int j = 0; j < 8; j++) {
        atomicAdd(&ssum[cg*8 + j], colsum[j]);
        atomicAdd(&ssq [cg*8 + j], colsq[j]);
    }
    if (LAYER == 2) {
        int q = rg >> 2;      // ROWS=128: rows rg*8..rg*8+7 all in 32-row group q
        #pragma unroll
        for (int j = 0; j < 8; j++) {
            int ik = __float_as_int(colmax[j]);
            ik ^= ((ik >> 31) & 0x7fffffff);
            atomicMax(&smax[q*128 + cg*8 + j], ik);
        }
    }
    __syncthreads();
    if (tid < CO) {
        atomicAdd(&g_sum[LAYER][tid], (double)ssum[tid]);
        atomicAdd(&g_sq [LAYER][tid], (double)ssq [tid]);
    }
    if (LAYER == 2) {
        for (int t = tid; t < 512; t += 256) {
            int qq = t >> 7, c = t & 127;
            int bmv = (int)(rowBase >> 5) + qq;
            int bb = bmv >> 11, mm = bmv & 2047;
            g_max[((size_t)bb*128 + c)*2048 + mm] = smax[t];
        }
    }
}

// ---------------- BN stats -> scale/shift --------------------------------
__global__ void finalize_kernel(int L, const float* __restrict__ g,
                                const float* __restrict__ beta, int Co)
{
    int c = threadIdx.x;
    if (c >= Co) return;
    double inv = 1.0 / (double)NROWS;
    double mu  = g_sum[L][c] * inv;
    double var = g_sq[L][c] * inv - mu*mu;
    if (var < 0.0) var = 0.0;
    float s = g[c] / sqrtf((float)var + BN_EPS);
    g_s[L][c] = s;
    g_t[L][c] = fmaf(-(float)mu, s, beta[c]);
}

// ---------------- BN+ReLU on pre-pooled max, transposed layout -----------
__global__ void maxpool_kernel(float* __restrict__ out)
{
    int i = blockIdx.x * blockDim.x + threadIdx.x;   // over B*128*M = 2M
    int c = (i >> 11) & 127;
    float s = g_s[2][c], t = g_t[2][c];
    int key = g_max[i];
    key ^= ((key >> 31) & 0x7fffffff);
    float y = __int_as_float(key);
    out[(size_t)Bb*Mm*3 + i] = fmaxf(fmaf(y, s, t), 0.f);
}

// ---------------- launch ---------------------------------------------------
extern "C" void kernel_launch(void* const* d_in, const int* in_sizes, int n_in,
                              void* d_out, int out_size)
{
    (void)in_sizes; (void)n_in; (void)out_size;
    const float* xyz  = (const float*)d_in[0];
    const float* feats= (const float*)d_in[1];
    const float* W1   = (const float*)d_in[2];
    const float* b1   = (const float*)d_in[3];
    const float* g1   = (const float*)d_in[4];
    const float* be1  = (const float*)d_in[5];
    const float* W2   = (const float*)d_in[6];
    const float* b2   = (const float*)d_in[7];
    const float* g2   = (const float*)d_in[8];
    const float* be2  = (const float*)d_in[9];
    const float* W3   = (const float*)d_in[10];
    const float* b3   = (const float*)d_in[11];
    const float* g3   = (const float*)d_in[12];
    const float* be3  = (const float*)d_in[13];
    float* out = (float*)d_out;
    const float* centers = out;     // knn writes centers at d_out[0 : B*M*3)

    prep_kernel<<<32, 256>>>(W1, W2, W3);
    transpose_kernel<<<dim3(Pp/32, CIN/32, Bb), dim3(32, 8)>>>(feats);
    knn_kernel<<<Bb*Mm, 256>>>(xyz, out);

    gemm_kernel<0><<<NROWS/256, 256>>>(b1, xyz, centers);
    finalize_kernel<<<1, 64>>>(0, g1, be1, 64);
    gemm_kernel<1><<<NROWS/256, 256>>>(b2, xyz, centers);
    finalize_kernel<<<1, 64>>>(1, g2, be2, 64);
    gemm_kernel<2><<<NROWS/128, 256>>>(b3, xyz, centers);
    finalize_kernel<<<1, 128>>>(2, g3, be3, 128);

    maxpool_kernel<<<(Bb*Mm*128)/256, 256>>>(out);
}

// round 6
// speedup vs baseline: 1.5586x; 1.0244x over previous
#include <cuda_runtime.h>
#include <cuda_bf16.h>
#include <cstdint>

#define Bb   8
#define Pp   8192
#define CIN  64
#define KK   32
#define Mm   2048
#define NROWS (Bb*Mm*KK)     // 524288
#define BN_EPS 1e-5f

// ---------------- scratch (device globals; no allocation) ----------------
__device__ __align__(128) float  g_featsT[(size_t)Bb*Pp*CIN];   // 16 MB
__device__ __align__(128) float4 g_xyz4[(size_t)Bb*Pp];         // 1 MB
__device__ __align__(128) int    g_sel[(size_t)NROWS];          // 2 MB
__device__ __align__(128) float  g_y1[(size_t)NROWS*64];        // 134 MB
__device__ __align__(128) float  g_y2[(size_t)NROWS*64];        // 134 MB
__device__ __align__(128) float  g_maxf[(size_t)Bb*128*Mm];     // 8 MB
// weight hi/lo bf16 images (unswizzled, K-major rows)
__device__ __align__(128) __nv_bfloat16 g_Wh0[64*80],  g_Wl0[64*80];
__device__ __align__(128) __nv_bfloat16 g_Wh1[64*64],  g_Wl1[64*64];
__device__ __align__(128) __nv_bfloat16 g_Wh2[128*64], g_Wl2[128*64];
__device__ double g_sum[3][128];
__device__ double g_sq[3][128];
__device__ float  g_s[3][128];
__device__ float  g_t[3][128];

// ---------------- small helpers ------------------------------------------
__device__ __forceinline__ uint32_t smem_u32(const void* p) {
    uint32_t a;
    asm("{ .reg .u64 t; cvta.to.shared.u64 t, %1; cvt.u32.u64 %0, t; }" : "=r"(a) : "l"(p));
    return a;
}
__device__ __forceinline__ unsigned pkb(__nv_bfloat16 a, __nv_bfloat16 b) {
    __nv_bfloat162 t; t.x = a; t.y = b;
    return *(unsigned*)&t;
}
__device__ __forceinline__ void wsplit(float w, __nv_bfloat16& h, __nv_bfloat16& l) {
    h = __float2bfloat16(w);
    l = __float2bfloat16(w - __bfloat162float(h));
}
__device__ __forceinline__ void ldsm4(unsigned* r, uint32_t addr) {
    asm volatile("ldmatrix.sync.aligned.m8n8.x4.shared.b16 {%0,%1,%2,%3}, [%4];"
        : "=r"(r[0]), "=r"(r[1]), "=r"(r[2]), "=r"(r[3]) : "r"(addr));
}
__device__ __forceinline__ void mma16816(float* c, const unsigned* a,
                                         unsigned b0, unsigned b1) {
    asm volatile("mma.sync.aligned.m16n8k16.row.col.f32.bf16.bf16.f32 "
        "{%0,%1,%2,%3}, {%4,%5,%6,%7}, {%8,%9}, {%0,%1,%2,%3};"
        : "+f"(c[0]), "+f"(c[1]), "+f"(c[2]), "+f"(c[3])
        : "r"(a[0]), "r"(a[1]), "r"(a[2]), "r"(a[3]), "r"(b0), "r"(b1));
}

// ---------------- prep: zero stats + bf16 hi/lo weight images -------------
__global__ void prep_kernel(const float* __restrict__ W1,
                            const float* __restrict__ W2,
                            const float* __restrict__ W3)
{
    int tid = blockIdx.x * blockDim.x + threadIdx.x;
    if (tid < 384) { ((double*)g_sum)[tid] = 0.0; ((double*)g_sq)[tid] = 0.0; }
    if (tid >= 5120 + 4096 + 8192) return;
    float w;
    __nv_bfloat16 *ph, *pl;
    int idx;
    if (tid < 5120) {                   // W0: [64][80] = feats(64)+xyz(3)+pad
        int n = tid / 80, k = tid % 80;
        if (k < 64)      w = W1[n*67 + k + 3];
        else if (k < 67) w = W1[n*67 + (k - 64)];
        else             w = 0.f;
        ph = g_Wh0; pl = g_Wl0; idx = tid;
    } else if (tid < 9216) {            // W1: [64][64]
        int t = tid - 5120;
        w = W2[t];
        ph = g_Wh1; pl = g_Wl1; idx = t;
    } else {                            // W2: [128][64]
        int t = tid - 9216;
        w = W3[t];
        ph = g_Wh2; pl = g_Wl2; idx = t;
    }
    __nv_bfloat16 h, l; wsplit(w, h, l);
    ph[idx] = h; pl[idx] = l;
}

// ---------------- xyz -> padded float4 ------------------------------------
__global__ void pad_kernel(const float* __restrict__ xyz)
{
    int i = blockIdx.x * blockDim.x + threadIdx.x;
    const float* s = xyz + (size_t)i*3;
    g_xyz4[i] = make_float4(s[0], s[1], s[2], 0.f);
}

// ---------------- feats (B,C,P) -> featsT (B,P,C) ------------------------
__global__ void transpose_kernel(const float* __restrict__ f)
{
    __shared__ float tile[32][33];
    int b  = blockIdx.z;
    int c0 = blockIdx.y * 32;
    int p0 = blockIdx.x * 32;
    int tx = threadIdx.x, ty = threadIdx.y;
    #pragma unroll
    for (int i = ty; i < 32; i += 8)
        tile[i][tx] = f[((size_t)b*CIN + c0 + i)*Pp + p0 + tx];
    __syncthreads();
    #pragma unroll
    for (int i = ty; i < 32; i += 8)
        g_featsT[((size_t)b*Pp + p0 + i)*CIN + c0 + tx] = tile[tx][i];
}

// ---------------- KNN: 4-pass radix-select on 32-bit distance ------------
__global__ void __launch_bounds__(256) knn_kernel(float* __restrict__ centers_out)
{
    int bm = blockIdx.x;
    int b  = bm >> 11;
    int m  = bm & 2047;
    __shared__ float ctr[3];
    __shared__ unsigned int hist[256];
    __shared__ unsigned int s_prefix;
    __shared__ int s_remaining;
    __shared__ int s_cnt;
    __shared__ int s_min;
    __shared__ int s_last;
    int tid  = threadIdx.x;
    int lane = tid & 31;

    if (tid == 0) {
        int ci = (m == 2047) ? 8191
               : (int)(__fmul_rn(8191.0f, __fdiv_rn((float)m, 2047.0f)));
        float4 cp = g_xyz4[(size_t)(b << 13) + ci];
        ctr[0] = cp.x; ctr[1] = cp.y; ctr[2] = cp.z;
        float* co = centers_out + (size_t)bm*3;
        co[0] = cp.x; co[1] = cp.y; co[2] = cp.z;
        s_prefix = 0u; s_remaining = KK; s_cnt = 0; s_last = -1;
    }
    __syncthreads();
    float cx = ctr[0], cy = ctr[1], cz = ctr[2];
    float cn = __fadd_rn(__fadd_rn(__fmul_rn(cx,cx), __fmul_rn(cy,cy)), __fmul_rn(cz,cz));

    unsigned int dm[32];
    #pragma unroll
    for (int j = 0; j < 32; j++) {
        int p = tid + j*256;
        float4 xv = g_xyz4[(size_t)(b << 13) + p];
        float x = xv.x, y = xv.y, z = xv.z;
        float xn = __fadd_rn(__fadd_rn(__fmul_rn(x,x), __fmul_rn(y,y)), __fmul_rn(z,z));
        float dt = __fadd_rn(__fadd_rn(__fmul_rn(cx,x), __fmul_rn(cy,y)), __fmul_rn(cz,z));
        float d  = __fsub_rn(__fadd_rn(cn, xn), __fmul_rn(2.0f, dt));
        unsigned u = __float_as_uint(d);
        dm[j] = (u & 0x80000000u) ? ~u : (u | 0x80000000u);
    }

    for (int pass = 0; pass < 4; pass++) {
        hist[tid] = 0;
        __syncthreads();
        unsigned pref = s_prefix;
        int sh = 24 - 8*pass;
        #pragma unroll
        for (int j = 0; j < 32; j++) {
            bool ok = (pass == 0) || ((dm[j] >> (sh + 8)) == pref);
            unsigned bkt = (dm[j] >> sh) & 255u;
            unsigned mask = __ballot_sync(0xffffffffu, ok);
            if (ok) {
                unsigned peers = __match_any_sync(mask, bkt);
                if ((peers & ((1u << lane) - 1u)) == 0u)
                    atomicAdd(&hist[bkt], __popc(peers));
            }
        }
        __syncthreads();
        if (tid < 32) {
            unsigned cum[8];
            unsigned run = 0;
            #pragma unroll
            for (int i = 0; i < 8; i++) { run += hist[tid*8 + i]; cum[i] = run; }
            unsigned tot = run;
            unsigned off = tot;
            #pragma unroll
            for (int dd = 1; dd < 32; dd <<= 1) {
                unsigned v = __shfl_up_sync(0xffffffffu, off, dd);
                if (lane >= dd) off += v;
            }
            off -= tot;
            unsigned rem = (unsigned)s_remaining;
            #pragma unroll
            for (int i = 0; i < 8; i++) {
                unsigned prev = off + (i ? cum[i-1] : 0u);
                unsigned cu   = off + cum[i];
                if (prev < rem && cu >= rem) {
                    s_prefix = (s_prefix << 8) | (unsigned)(tid*8 + i);
                    s_remaining = (int)(rem - prev);
                }
            }
        }
        __syncthreads();
    }
    unsigned thr = s_prefix;
    int rem = s_remaining;

    int* selg = g_sel + (size_t)bm * KK;
    #pragma unroll
    for (int j = 0; j < 32; j++) {
        if (dm[j] < thr) {
            int s = atomicAdd(&s_cnt, 1);
            selg[s] = tid + j*256;
        }
    }
    __syncthreads();
    int base = s_cnt;
    for (int r = 0; r < rem; r++) {
        if (tid == 0) s_min = 0x7fffffff;
        __syncthreads();
        int last = s_last;
        #pragma unroll
        for (int j = 0; j < 32; j++) {
            int p = tid + j*256;
            if (dm[j] == thr && p > last) atomicMin(&s_min, p);
        }
        __syncthreads();
        if (tid == 0) { selg[base + r] = s_min; s_last = s_min; }
        __syncthreads();
    }
}

// ---------------- bf16x3 GEMM via mma.sync (HMMA tensor pipe) -------------
// A smem: 128 rows x [ah(K)|al(K)] bf16, XOR-(row&7) chunk swizzle.
// B smem: CO rows x [bh(K)|bl(K)] bf16, same swizzle.
// 3 segments: (ah,bh), (al,bh), (ah,bl).
template<int LAYER>
__global__ void __launch_bounds__(256) mma_kernel(const float* __restrict__ bias,
                                                  const float* __restrict__ centers)
{
    constexpr int CO    = (LAYER == 2) ? 128 : 64;
    constexpr int K     = (LAYER == 0) ? 80 : 64;
    constexpr int KC    = K / 8;              // 8-col chunks per segment
    constexpr int NKCH  = K / 16;             // 16-col mma chunks per segment
    constexpr int ST    = (LAYER == 0) ? 24 : 16;   // row stride, 16B units
    constexpr int ASZ   = 128 * ST * 16;
    constexpr int WCOLS = CO / 2;
    constexpr int NT    = WCOLS / 8;          // 8-col tiles per warp
    constexpr int HC    = KC / 2;             // chunks per row-half

    extern __shared__ __align__(16) char dyn[];
    char* Asm = dyn;
    char* Bsm = dyn + ASZ;
    __shared__ float sb[CO], ssum[CO], ssq[CO];
    __shared__ float sS[64], sT[64];

    const int tid = threadIdx.x;
    const size_t rowBase = (size_t)blockIdx.x * 128;
    const int bBat = (int)(rowBase >> 16);

    if (tid < CO) { sb[tid] = bias[tid]; ssum[tid] = 0.f; ssq[tid] = 0.f; }
    if (LAYER > 0 && tid < 64) { sS[tid] = g_s[LAYER-1][tid]; sT[tid] = g_t[LAYER-1][tid]; }
    __syncthreads();

    // ---- A build: 2 threads per row ----
    {
        int row = tid >> 1, half = tid & 1;
        const float* srcf;
        float dx = 0.f, dy = 0.f, dz = 0.f;
        if (LAYER == 0) {
            int p = g_sel[rowBase + row];
            srcf = g_featsT + (((size_t)bBat << 13) + (unsigned)p) * 64;
            float4 X = g_xyz4[((size_t)bBat << 13) + (unsigned)p];
            int bm = (int)((rowBase + row) >> 5);
            dx = X.x - centers[bm*3 + 0];
            dy = X.y - centers[bm*3 + 1];
            dz = X.z - centers[bm*3 + 2];
        } else {
            srcf = ((LAYER == 1) ? g_y1 : g_y2) + (rowBase + row) * 64;
        }
        int rx = row & 7;
        unsigned rowOff = (unsigned)row * (ST*16);
        #pragma unroll
        for (int j = 0; j < HC; j++) {
            int c  = half*HC + j;
            int k0 = c*8;
            float f[8];
            if (LAYER > 0) {
                float4 v0 = *(const float4*)(srcf + k0);
                float4 v1 = *(const float4*)(srcf + k0 + 4);
                f[0]=v0.x; f[1]=v0.y; f[2]=v0.z; f[3]=v0.w;
                f[4]=v1.x; f[5]=v1.y; f[6]=v1.z; f[7]=v1.w;
                #pragma unroll
                for (int i = 0; i < 8; i++)
                    f[i] = fmaxf(fmaf(f[i], sS[k0+i], sT[k0+i]), 0.f);
            } else {
                if (k0 + 8 <= 64) {
                    float4 v0 = *(const float4*)(srcf + k0);
                    float4 v1 = *(const float4*)(srcf + k0 + 4);
                    f[0]=v0.x; f[1]=v0.y; f[2]=v0.z; f[3]=v0.w;
                    f[4]=v1.x; f[5]=v1.y; f[6]=v1.z; f[7]=v1.w;
                } else if (k0 == 64) {
                    f[0]=dx; f[1]=dy; f[2]=dz;
                    f[3]=0.f; f[4]=0.f; f[5]=0.f; f[6]=0.f; f[7]=0.f;
                } else {
                    #pragma unroll
                    for (int i = 0; i < 8; i++) f[i] = 0.f;
                }
            }
            unsigned hv[4], lv[4];
            #pragma unroll
            for (int q = 0; q < 4; q++) {
                __nv_bfloat16 ha, la, hb, lb;
                wsplit(f[2*q],   ha, la);
                wsplit(f[2*q+1], hb, lb);
                hv[q] = pkb(ha, hb); lv[q] = pkb(la, lb);
            }
            unsigned ch = (unsigned)(c ^ rx);
            unsigned cl = (unsigned)((KC + c) ^ rx);
            *(uint4*)(Asm + rowOff + ch*16) = make_uint4(hv[0],hv[1],hv[2],hv[3]);
            *(uint4*)(Asm + rowOff + cl*16) = make_uint4(lv[0],lv[1],lv[2],lv[3]);
        }
    }
    // ---- B copy: hi/lo images -> swizzled smem ----
    {
        const __nv_bfloat16* Wh = (LAYER==0) ? g_Wh0 : (LAYER==1) ? g_Wh1 : g_Wh2;
        const __nv_bfloat16* Wl = (LAYER==0) ? g_Wl0 : (LAYER==1) ? g_Wl1 : g_Wl2;
        for (int i = tid; i < CO * 2 * KC; i += 256) {
            int n = i / (2*KC), c = i % (2*KC);
            const __nv_bfloat16* src = (c < KC) ? (Wh + n*K + c*8)
                                                : (Wl + n*K + (c - KC)*8);
            uint4 v = *(const uint4*)src;
            unsigned cs = (unsigned)(c ^ (n & 7));
            *(uint4*)(Bsm + (unsigned)n*(ST*16) + cs*16) = v;
        }
    }
    __syncthreads();

    // ---- MMA main loop ----
    const uint32_t Abase = smem_u32(Asm);
    const uint32_t Bbase = smem_u32(Bsm);
    const int warp = tid >> 5, lane = tid & 31;
    const int wm = warp >> 1, wn = warp & 1;
    const int Rw = wm*32, Cw = wn*WCOLS;

    const int arow = lane & 15;
    const uint32_t aAddr0 = Abase + (unsigned)(Rw + arow)      * (ST*16);
    const uint32_t aAddr1 = Abase + (unsigned)(Rw + 16 + arow) * (ST*16);
    const unsigned axr = (unsigned)(arow & 7);
    const unsigned aHi = (unsigned)(lane >> 4);
    const int nro  = (lane & 7) + ((lane & 16) >> 1);
    const unsigned bxr = (unsigned)(nro & 7);
    const unsigned bHi = (unsigned)((lane >> 3) & 1);

    float cc[2][NT][4];
    #pragma unroll
    for (int mi = 0; mi < 2; mi++)
        #pragma unroll
        for (int ni = 0; ni < NT; ni++)
            #pragma unroll
            for (int q = 0; q < 4; q++) cc[mi][ni][q] = 0.f;

    #pragma unroll
    for (int s = 0; s < 3; s++) {
        const unsigned sa = (s == 1) ? KC : 0;
        const unsigned sbc = (s == 2) ? KC : 0;
        #pragma unroll
        for (int kc = 0; kc < NKCH; kc++) {
            unsigned ca = sa + kc*2 + aHi;
            unsigned a0r[4], a1r[4];
            ldsm4(a0r, aAddr0 + ((ca ^ axr) << 4));
            ldsm4(a1r, aAddr1 + ((ca ^ axr) << 4));
            unsigned cb = sbc + kc*2 + bHi;
            #pragma unroll
            for (int ntp = 0; ntp < NT/2; ntp++) {
                int brow = Cw + ntp*16 + nro;
                unsigned br[4];
                ldsm4(br, Bbase + (unsigned)brow*(ST*16) + ((cb ^ bxr) << 4));
                mma16816(cc[0][ntp*2],   a0r, br[0], br[1]);
                mma16816(cc[0][ntp*2+1], a0r, br[2], br[3]);
                mma16816(cc[1][ntp*2],   a1r, br[0], br[1]);
                mma16816(cc[1][ntp*2+1], a1r, br[2], br[3]);
            }
        }
    }

    // ---- epilogue: bias, Y store, stats, L2 max ----
    float* Y = (LAYER == 0) ? g_y1 : g_y2;
    const int tq = lane >> 2, tr = lane & 3;
    #pragma unroll
    for (int ni = 0; ni < NT; ni++) {
        int cn = Cw + ni*8 + tr*2;
        float b0 = sb[cn], b1 = sb[cn+1];
        float s0=0.f, s1=0.f, q0=0.f, q1=0.f, m0=-3.4e38f, m1=-3.4e38f;
        #pragma unroll
        for (int mi = 0; mi < 2; mi++) {
            float d0 = cc[mi][ni][0] + b0;
            float d1 = cc[mi][ni][1] + b1;
            float d2 = cc[mi][ni][2] + b0;
            float d3 = cc[mi][ni][3] + b1;
            if (LAYER < 2) {
                size_t r = rowBase + Rw + mi*16 + tq;
                *(float2*)&Y[r*64 + cn]     = make_float2(d0, d1);
                *(float2*)&Y[(r+8)*64 + cn] = make_float2(d2, d3);
            }
            s0 += d0 + d2;  s1 += d1 + d3;
            q0 += d0*d0 + d2*d2;  q1 += d1*d1 + d3*d3;
            m0 = fmaxf(m0, fmaxf(d0, d2));  m1 = fmaxf(m1, fmaxf(d1, d3));
        }
        #pragma unroll
        for (int o = 4; o <= 16; o <<= 1) {
            s0 += __shfl_xor_sync(0xffffffffu, s0, o);
            s1 += __shfl_xor_sync(0xffffffffu, s1, o);
            q0 += __shfl_xor_sync(0xffffffffu, q0, o);
            q1 += __shfl_xor_sync(0xffffffffu, q1, o);
            if (LAYER == 2) {
                m0 = fmaxf(m0, __shfl_xor_sync(0xffffffffu, m0, o));
                m1 = fmaxf(m1, __shfl_xor_sync(0xffffffffu, m1, o));
            }
        }
        if (lane < 4) {
            atomicAdd(&ssum[cn],   s0);
            atomicAdd(&ssum[cn+1], s1);
            atomicAdd(&ssq[cn],    q0);
            atomicAdd(&ssq[cn+1],  q1);
            if (LAYER == 2) {
                int bm = (int)(rowBase >> 5) + wm;
                size_t o0 = ((size_t)(bm >> 11)*128 + (unsigned)cn)*2048 + (unsigned)(bm & 2047);
                g_maxf[o0]        = m0;
                g_maxf[o0 + 2048] = m1;
            }
        }
    }
    __syncthreads();
    if (tid < CO) {
        atomicAdd(&g_sum[LAYER][tid], (double)ssum[tid]);
        atomicAdd(&g_sq [LAYER][tid], (double)ssq [tid]);
    }
}

// ---------------- BN stats -> scale/shift --------------------------------
__global__ void finalize_kernel(int L, const float* __restrict__ g,
                                const float* __restrict__ beta, int Co)
{
    int c = threadIdx.x;
    if (c >= Co) return;
    double inv = 1.0 / (double)NROWS;
    double mu  = g_sum[L][c] * inv;
    double var = g_sq[L][c] * inv - mu*mu;
    if (var < 0.0) var = 0.0;
    float s = g[c] / sqrtf((float)var + BN_EPS);
    g_s[L][c] = s;
    g_t[L][c] = fmaf(-(float)mu, s, beta[c]);
}

// ---------------- BN+ReLU on pre-pooled max, transposed layout -----------
__global__ void maxpool_kernel(float* __restrict__ out)
{
    int i = blockIdx.x * blockDim.x + threadIdx.x;   // over B*128*M = 2M
    int c = (i >> 11) & 127;
    float s = g_s[2][c], t = g_t[2][c];
    out[(size_t)Bb*Mm*3 + i] = fmaxf(fmaf(g_maxf[i], s, t), 0.f);
}

// ---------------- launch ---------------------------------------------------
extern "C" void kernel_launch(void* const* d_in, const int* in_sizes, int n_in,
                              void* d_out, int out_size)
{
    (void)in_sizes; (void)n_in; (void)out_size;
    const float* xyz  = (const float*)d_in[0];
    const float* feats= (const float*)d_in[1];
    const float* W1   = (const float*)d_in[2];
    const float* b1   = (const float*)d_in[3];
    const float* g1   = (const float*)d_in[4];
    const float* be1  = (const float*)d_in[5];
    const float* W2   = (const float*)d_in[6];
    const float* b2   = (const float*)d_in[7];
    const float* g2   = (const float*)d_in[8];
    const float* be2  = (const float*)d_in[9];
    const float* W3   = (const float*)d_in[10];
    const float* b3   = (const float*)d_in[11];
    const float* g3   = (const float*)d_in[12];
    const float* be3  = (const float*)d_in[13];
    float* out = (float*)d_out;
    const float* centers = out;   // knn writes centers into d_out[0 : B*M*3)

    const int SM0 = 128*24*16 + 64*24*16;     // 73728
    const int SM1 = 128*16*16 + 64*16*16;     // 49152
    const int SM2 = 128*16*16 + 128*16*16;    // 65536
    cudaFuncSetAttribute(mma_kernel<0>, cudaFuncAttributeMaxDynamicSharedMemorySize, SM0);
    cudaFuncSetAttribute(mma_kernel<1>, cudaFuncAttributeMaxDynamicSharedMemorySize, SM1);
    cudaFuncSetAttribute(mma_kernel<2>, cudaFuncAttributeMaxDynamicSharedMemorySize, SM2);

    prep_kernel<<<68, 256>>>(W1, W2, W3);
    pad_kernel<<<(Bb*Pp)/256, 256>>>(xyz);
    transpose_kernel<<<dim3(Pp/32, CIN/32, Bb), dim3(32, 8)>>>(feats);
    knn_kernel<<<Bb*Mm, 256>>>(out);

    mma_kernel<0><<<NROWS/128, 256, SM0>>>(b1, centers);
    finalize_kernel<<<1, 64>>>(0, g1, be1, 64);
    mma_kernel<1><<<NROWS/128, 256, SM1>>>(b2, centers);
    finalize_kernel<<<1, 64>>>(1, g2, be2, 64);
    mma_kernel<2><<<NROWS/128, 256, SM2>>>(b3, centers);
    finalize_kernel<<<1, 128>>>(2, g3, be3, 128);

    maxpool_kernel<<<(Bb*Mm*128)/256, 256>>>(out);
}

// round 7
// speedup vs baseline: 1.6396x; 1.0520x over previous
#include <cuda_runtime.h>
#include <cuda_bf16.h>
#include <cstdint>

#define Bb   8
#define Pp   8192
#define CIN  64
#define KK   32
#define Mm   2048
#define NROWS (Bb*Mm*KK)     // 524288
#define BN_EPS 1e-5f

// ---------------- scratch (device globals; no allocation) ----------------
__device__ __align__(128) float  g_featsT[(size_t)Bb*Pp*CIN];   // 16 MB
__device__ __align__(128) float4 g_xyz4[(size_t)Bb*Pp];         // 1 MB
__device__ __align__(128) int    g_sel[(size_t)NROWS];          // 2 MB
__device__ __align__(128) float  g_y1[(size_t)NROWS*64];        // 134 MB
__device__ __align__(128) float  g_y2[(size_t)NROWS*64];        // 134 MB
__device__ __align__(128) float  g_maxf[(size_t)Bb*128*Mm];     // 8 MB
// weight hi/lo bf16 images (unswizzled, K-major rows)
__device__ __align__(128) __nv_bfloat16 g_Wh0[64*80],  g_Wl0[64*80];
__device__ __align__(128) __nv_bfloat16 g_Wh1[64*64],  g_Wl1[64*64];
__device__ __align__(128) __nv_bfloat16 g_Wh2[128*64], g_Wl2[128*64];
__device__ double g_sum[3][128];
__device__ double g_sq[3][128];
__device__ float  g_s[3][128];
__device__ float  g_t[3][128];

// ---------------- small helpers ------------------------------------------
__device__ __forceinline__ uint32_t smem_u32(const void* p) {
    uint32_t a;
    asm("{ .reg .u64 t; cvta.to.shared.u64 t, %1; cvt.u32.u64 %0, t; }" : "=r"(a) : "l"(p));
    return a;
}
__device__ __forceinline__ unsigned pkb(__nv_bfloat16 a, __nv_bfloat16 b) {
    __nv_bfloat162 t; t.x = a; t.y = b;
    return *(unsigned*)&t;
}
__device__ __forceinline__ void wsplit(float w, __nv_bfloat16& h, __nv_bfloat16& l) {
    h = __float2bfloat16(w);
    l = __float2bfloat16(w - __bfloat162float(h));
}
__device__ __forceinline__ void ldsm4(unsigned* r, uint32_t addr) {
    asm volatile("ldmatrix.sync.aligned.m8n8.x4.shared.b16 {%0,%1,%2,%3}, [%4];"
        : "=r"(r[0]), "=r"(r[1]), "=r"(r[2]), "=r"(r[3]) : "r"(addr));
}
__device__ __forceinline__ void mma16816(float* c, const unsigned* a,
                                         unsigned b0, unsigned b1) {
    asm volatile("mma.sync.aligned.m16n8k16.row.col.f32.bf16.bf16.f32 "
        "{%0,%1,%2,%3}, {%4,%5,%6,%7}, {%8,%9}, {%0,%1,%2,%3};"
        : "+f"(c[0]), "+f"(c[1]), "+f"(c[2]), "+f"(c[3])
        : "r"(a[0]), "r"(a[1]), "r"(a[2]), "r"(a[3]), "r"(b0), "r"(b1));
}

// ---------------- prep: zero stats + bf16 hi/lo weight images -------------
__global__ void prep_kernel(const float* __restrict__ W1,
                            const float* __restrict__ W2,
                            const float* __restrict__ W3)
{
    int tid = blockIdx.x * blockDim.x + threadIdx.x;
    if (tid < 384) { ((double*)g_sum)[tid] = 0.0; ((double*)g_sq)[tid] = 0.0; }
    if (tid >= 5120 + 4096 + 8192) return;
    float w;
    __nv_bfloat16 *ph, *pl;
    int idx;
    if (tid < 5120) {                   // W0: [64][80] = feats(64)+xyz(3)+pad
        int n = tid / 80, k = tid % 80;
        if (k < 64)      w = W1[n*67 + k + 3];
        else if (k < 67) w = W1[n*67 + (k - 64)];
        else             w = 0.f;
        ph = g_Wh0; pl = g_Wl0; idx = tid;
    } else if (tid < 9216) {            // W1: [64][64]
        int t = tid - 5120;
        w = W2[t];
        ph = g_Wh1; pl = g_Wl1; idx = t;
    } else {                            // W2: [128][64]
        int t = tid - 9216;
        w = W3[t];
        ph = g_Wh2; pl = g_Wl2; idx = t;
    }
    __nv_bfloat16 h, l; wsplit(w, h, l);
    ph[idx] = h; pl[idx] = l;
}

// ---------------- xyz -> padded float4 ------------------------------------
__global__ void pad_kernel(const float* __restrict__ xyz)
{
    int i = blockIdx.x * blockDim.x + threadIdx.x;
    const float* s = xyz + (size_t)i*3;
    g_xyz4[i] = make_float4(s[0], s[1], s[2], 0.f);
}

// ---------------- feats (B,C,P) -> featsT (B,P,C) ------------------------
__global__ void transpose_kernel(const float* __restrict__ f)
{
    __shared__ float tile[32][33];
    int b  = blockIdx.z;
    int c0 = blockIdx.y * 32;
    int p0 = blockIdx.x * 32;
    int tx = threadIdx.x, ty = threadIdx.y;
    #pragma unroll
    for (int i = ty; i < 32; i += 8)
        tile[i][tx] = f[((size_t)b*CIN + c0 + i)*Pp + p0 + tx];
    __syncthreads();
    #pragma unroll
    for (int i = ty; i < 32; i += 8)
        g_featsT[((size_t)b*Pp + p0 + i)*CIN + c0 + tx] = tile[tx][i];
}

// ---------------- KNN: radix-select, per-warp hists + compaction ----------
#define CAP 4096
__global__ void __launch_bounds__(256) knn_kernel(float* __restrict__ centers_out)
{
    int bm = blockIdx.x;
    int b  = bm >> 11;
    int m  = bm & 2047;
    __shared__ float ctr[3];
    __shared__ unsigned int whist[8][256];     // per-warp privatized histograms
    __shared__ unsigned int s_prefix;
    __shared__ int s_remaining;
    __shared__ int s_cnt;
    __shared__ int s_ncand;
    __shared__ int s_min;
    __shared__ int s_last;
    __shared__ unsigned int cand_dm[CAP];
    __shared__ int          cand_id[CAP];
    int tid  = threadIdx.x;
    int wid  = tid >> 5;
    int lane = tid & 31;

    if (tid == 0) {
        int ci = (m == 2047) ? 8191
               : (int)(__fmul_rn(8191.0f, __fdiv_rn((float)m, 2047.0f)));
        float4 cp = g_xyz4[(size_t)(b << 13) + ci];
        ctr[0] = cp.x; ctr[1] = cp.y; ctr[2] = cp.z;
        float* co = centers_out + (size_t)bm*3;
        co[0] = cp.x; co[1] = cp.y; co[2] = cp.z;
        s_prefix = 0u; s_remaining = KK; s_cnt = 0; s_ncand = 0; s_last = -1;
    }
    __syncthreads();
    float cx = ctr[0], cy = ctr[1], cz = ctr[2];
    float cn = __fadd_rn(__fadd_rn(__fmul_rn(cx,cx), __fmul_rn(cy,cy)), __fmul_rn(cz,cz));

    // order-preserving mapped distance bits; point p = tid + j*256
    unsigned int dm[32];
    #pragma unroll
    for (int j = 0; j < 32; j++) {
        int p = tid + j*256;
        float4 xv = g_xyz4[(size_t)(b << 13) + p];
        float x = xv.x, y = xv.y, z = xv.z;
        float xn = __fadd_rn(__fadd_rn(__fmul_rn(x,x), __fmul_rn(y,y)), __fmul_rn(z,z));
        float dt = __fadd_rn(__fadd_rn(__fmul_rn(cx,x), __fmul_rn(cy,y)), __fmul_rn(cz,z));
        float d  = __fsub_rn(__fadd_rn(cn, xn), __fmul_rn(2.0f, dt));
        unsigned u = __float_as_uint(d);
        dm[j] = (u & 0x80000000u) ? ~u : (u | 0x80000000u);
    }

    // scan helper: executed after histogram fill; NC = copies to sum
    auto scan = [&](int NC) {
        if (tid < 32) {
            unsigned cum[8];
            unsigned run = 0;
            #pragma unroll
            for (int i = 0; i < 8; i++) {
                int bin = tid*8 + i;
                unsigned h = 0;
                for (int c = 0; c < NC; c++) h += whist[c][bin];
                run += h; cum[i] = run;
            }
            unsigned tot = run;
            unsigned off = tot;
            #pragma unroll
            for (int dd = 1; dd < 32; dd <<= 1) {
                unsigned v = __shfl_up_sync(0xffffffffu, off, dd);
                if (lane >= dd) off += v;
            }
            off -= tot;
            unsigned rem = (unsigned)s_remaining;
            #pragma unroll
            for (int i = 0; i < 8; i++) {
                unsigned prev = off + (i ? cum[i-1] : 0u);
                unsigned cu   = off + cum[i];
                if (prev < rem && cu >= rem) {
                    s_prefix = (s_prefix << 8) | (unsigned)(tid*8 + i);
                    s_remaining = (int)(rem - prev);
                }
            }
        }
    };

    // ---- pass 0 (full, no filter), per-warp hist ----
    {
        #pragma unroll
        for (int t = tid; t < 2048; t += 256) ((unsigned*)whist)[t] = 0;
        __syncthreads();
        #pragma unroll
        for (int j = 0; j < 32; j++) {
            unsigned bkt = dm[j] >> 24;
            unsigned peers = __match_any_sync(0xffffffffu, bkt);
            if ((peers & ((1u << lane) - 1u)) == 0u)
                atomicAdd(&whist[wid][bkt], __popc(peers));
        }
        __syncthreads();
        scan(8);
        __syncthreads();
    }
    // ---- pass 1 (full, 8-bit prefix filter), per-warp hist ----
    {
        #pragma unroll
        for (int t = tid; t < 2048; t += 256) ((unsigned*)whist)[t] = 0;
        __syncthreads();
        unsigned pref = s_prefix;
        #pragma unroll
        for (int j = 0; j < 32; j++) {
            bool ok = (dm[j] >> 24) == pref;
            unsigned bkt = (dm[j] >> 16) & 255u;
            unsigned mask = __ballot_sync(0xffffffffu, ok);
            if (ok) {
                unsigned peers = __match_any_sync(mask, bkt);
                if ((peers & ((1u << lane) - 1u)) == 0u)
                    atomicAdd(&whist[wid][bkt], __popc(peers));
            }
        }
        __syncthreads();
        scan(8);
        __syncthreads();
    }
    // ---- compact 16-bit-prefix survivors ----
    {
        unsigned pref16 = s_prefix;
        #pragma unroll
        for (int j = 0; j < 32; j++) {
            if ((dm[j] >> 16) == pref16) {
                int pos = atomicAdd(&s_ncand, 1);
                if (pos < CAP) { cand_dm[pos] = dm[j]; cand_id[pos] = tid + j*256; }
            }
        }
        __syncthreads();
    }
    int ncand = s_ncand;
    if (ncand <= CAP) {
        // ---- passes 2,3 over the candidate list (single hist copy) ----
        int nIter = (ncand + 255) >> 8;
        #pragma unroll
        for (int pass = 2; pass < 4; pass++) {
            for (int t = tid; t < 256; t += 256) whist[0][t] = 0;
            __syncthreads();
            unsigned pref = s_prefix;
            int sh = 24 - 8*pass;
            for (int it = 0; it < nIter; it++) {
                int t = it*256 + tid;
                unsigned dv = (t < ncand) ? cand_dm[t] : 0u;
                bool ok = (t < ncand) && ((dv >> (sh + 8)) == pref);
                unsigned bkt = (dv >> sh) & 255u;
                unsigned mask = __ballot_sync(0xffffffffu, ok);
                if (ok) {
                    unsigned peers = __match_any_sync(mask, bkt);
                    if ((peers & ((1u << lane) - 1u)) == 0u)
                        atomicAdd(&whist[0][bkt], __popc(peers));
                }
            }
            __syncthreads();
            scan(1);
            __syncthreads();
        }
    } else {
        // exact fallback: full passes 2,3 with per-warp hists
        for (int pass = 2; pass < 4; pass++) {
            #pragma unroll
            for (int t = tid; t < 2048; t += 256) ((unsigned*)whist)[t] = 0;
            __syncthreads();
            unsigned pref = s_prefix;
            int sh = 24 - 8*pass;
            #pragma unroll
            for (int j = 0; j < 32; j++) {
                bool ok = (dm[j] >> (sh + 8)) == pref;
                unsigned bkt = (dm[j] >> sh) & 255u;
                unsigned mask = __ballot_sync(0xffffffffu, ok);
                if (ok) {
                    unsigned peers = __match_any_sync(mask, bkt);
                    if ((peers & ((1u << lane) - 1u)) == 0u)
                        atomicAdd(&whist[wid][bkt], __popc(peers));
                }
            }
            __syncthreads();
            scan(8);
            __syncthreads();
        }
    }
    unsigned thr = s_prefix;      // exact K-th smallest distance bits
    int rem = s_remaining;        // how many to take among dm == thr (>=1)

    int* selg = g_sel + (size_t)bm * KK;
    #pragma unroll
    for (int j = 0; j < 32; j++) {
        if (dm[j] < thr) {
            int s = atomicAdd(&s_cnt, 1);
            selg[s] = tid + j*256;
        }
    }
    __syncthreads();
    int base = s_cnt;             // == KK - rem
    for (int r = 0; r < rem; r++) {
        if (tid == 0) s_min = 0x7fffffff;
        __syncthreads();
        int last = s_last;
        #pragma unroll
        for (int j = 0; j < 32; j++) {
            int p = tid + j*256;
            if (dm[j] == thr && p > last) atomicMin(&s_min, p);
        }
        __syncthreads();
        if (tid == 0) { selg[base + r] = s_min; s_last = s_min; }
        __syncthreads();
    }
}

// ---------------- bf16x3 GEMM via mma.sync (HMMA tensor pipe) -------------
template<int LAYER>
__global__ void __launch_bounds__(256) mma_kernel(const float* __restrict__ bias,
                                                  const float* __restrict__ centers)
{
    constexpr int CO    = (LAYER == 2) ? 128 : 64;
    constexpr int K     = (LAYER == 0) ? 80 : 64;
    constexpr int KC    = K / 8;
    constexpr int NKCH  = K / 16;
    constexpr int ST    = (LAYER == 0) ? 24 : 16;
    constexpr int ASZ   = 128 * ST * 16;
    constexpr int WCOLS = CO / 2;
    constexpr int NT    = WCOLS / 8;
    constexpr int HC    = KC / 2;

    extern __shared__ __align__(16) char dyn[];
    char* Asm = dyn;
    char* Bsm = dyn + ASZ;
    __shared__ float sb[CO], ssum[CO], ssq[CO];
    __shared__ float sS[64], sT[64];

    const int tid = threadIdx.x;
    const size_t rowBase = (size_t)blockIdx.x * 128;
    const int bBat = (int)(rowBase >> 16);

    if (tid < CO) { sb[tid] = bias[tid]; ssum[tid] = 0.f; ssq[tid] = 0.f; }
    if (LAYER > 0 && tid < 64) { sS[tid] = g_s[LAYER-1][tid]; sT[tid] = g_t[LAYER-1][tid]; }
    __syncthreads();

    // ---- A build: 2 threads per row ----
    {
        int row = tid >> 1, half = tid & 1;
        const float* srcf;
        float dx = 0.f, dy = 0.f, dz = 0.f;
        if (LAYER == 0) {
            int p = g_sel[rowBase + row];
            srcf = g_featsT + (((size_t)bBat << 13) + (unsigned)p) * 64;
            float4 X = g_xyz4[((size_t)bBat << 13) + (unsigned)p];
            int bm = (int)((rowBase + row) >> 5);
            dx = X.x - centers[bm*3 + 0];
            dy = X.y - centers[bm*3 + 1];
            dz = X.z - centers[bm*3 + 2];
        } else {
            srcf = ((LAYER == 1) ? g_y1 : g_y2) + (rowBase + row) * 64;
        }
        int rx = row & 7;
        unsigned rowOff = (unsigned)row * (ST*16);
        #pragma unroll
        for (int j = 0; j < HC; j++) {
            int c  = half*HC + j;
            int k0 = c*8;
            float f[8];
            if (LAYER > 0) {
                float4 v0 = *(const float4*)(srcf + k0);
                float4 v1 = *(const float4*)(srcf + k0 + 4);
                f[0]=v0.x; f[1]=v0.y; f[2]=v0.z; f[3]=v0.w;
                f[4]=v1.x; f[5]=v1.y; f[6]=v1.z; f[7]=v1.w;
                #pragma unroll
                for (int i = 0; i < 8; i++)
                    f[i] = fmaxf(fmaf(f[i], sS[k0+i], sT[k0+i]), 0.f);
            } else {
                if (k0 + 8 <= 64) {
                    float4 v0 = *(const float4*)(srcf + k0);
                    float4 v1 = *(const float4*)(srcf + k0 + 4);
                    f[0]=v0.x; f[1]=v0.y; f[2]=v0.z; f[3]=v0.w;
                    f[4]=v1.x; f[5]=v1.y; f[6]=v1.z; f[7]=v1.w;
                } else if (k0 == 64) {
                    f[0]=dx; f[1]=dy; f[2]=dz;
                    f[3]=0.f; f[4]=0.f; f[5]=0.f; f[6]=0.f; f[7]=0.f;
                } else {
                    #pragma unroll
                    for (int i = 0; i < 8; i++) f[i] = 0.f;
                }
            }
            unsigned hv[4], lv[4];
            #pragma unroll
            for (int q = 0; q < 4; q++) {
                __nv_bfloat16 ha, la, hb, lb;
                wsplit(f[2*q],   ha, la);
                wsplit(f[2*q+1], hb, lb);
                hv[q] = pkb(ha, hb); lv[q] = pkb(la, lb);
            }
            unsigned ch = (unsigned)(c ^ rx);
            unsigned cl = (unsigned)((KC + c) ^ rx);
            *(uint4*)(Asm + rowOff + ch*16) = make_uint4(hv[0],hv[1],hv[2],hv[3]);
            *(uint4*)(Asm + rowOff + cl*16) = make_uint4(lv[0],lv[1],lv[2],lv[3]);
        }
    }
    // ---- B copy: hi/lo images -> swizzled smem ----
    {
        const __nv_bfloat16* Wh = (LAYER==0) ? g_Wh0 : (LAYER==1) ? g_Wh1 : g_Wh2;
        const __nv_bfloat16* Wl = (LAYER==0) ? g_Wl0 : (LAYER==1) ? g_Wl1 : g_Wl2;
        for (int i = tid; i < CO * 2 * KC; i += 256) {
            int n = i / (2*KC), c = i % (2*KC);
            const __nv_bfloat16* src = (c < KC) ? (Wh + n*K + c*8)
                                                : (Wl + n*K + (c - KC)*8);
            uint4 v = *(const uint4*)src;
            unsigned cs = (unsigned)(c ^ (n & 7));
            *(uint4*)(Bsm + (unsigned)n*(ST*16) + cs*16) = v;
        }
    }
    __syncthreads();

    // ---- MMA main loop ----
    const uint32_t Abase = smem_u32(Asm);
    const uint32_t Bbase = smem_u32(Bsm);
    const int warp = tid >> 5, lane = tid & 31;
    const int wm = warp >> 1, wn = warp & 1;
    const int Rw = wm*32, Cw = wn*WCOLS;

    const int arow = lane & 15;
    const uint32_t aAddr0 = Abase + (unsigned)(Rw + arow)      * (ST*16);
    const uint32_t aAddr1 = Abase + (unsigned)(Rw + 16 + arow) * (ST*16);
    const unsigned axr = (unsigned)(arow & 7);
    const unsigned aHi = (unsigned)(lane >> 4);
    const int nro  = (lane & 7) + ((lane & 16) >> 1);
    const unsigned bxr = (unsigned)(nro & 7);
    const unsigned bHi = (unsigned)((lane >> 3) & 1);

    float cc[2][NT][4];
    #pragma unroll
    for (int mi = 0; mi < 2; mi++)
        #pragma unroll
        for (int ni = 0; ni < NT; ni++)
            #pragma unroll
            for (int q = 0; q < 4; q++) cc[mi][ni][q] = 0.f;

    #pragma unroll
    for (int s = 0; s < 3; s++) {
        const unsigned sa = (s == 1) ? KC : 0;
        const unsigned sbc = (s == 2) ? KC : 0;
        #pragma unroll
        for (int kc = 0; kc < NKCH; kc++) {
            unsigned ca = sa + kc*2 + aHi;
            unsigned a0r[4], a1r[4];
            ldsm4(a0r, aAddr0 + ((ca ^ axr) << 4));
            ldsm4(a1r, aAddr1 + ((ca ^ axr) << 4));
            unsigned cb = sbc + kc*2 + bHi;
            #pragma unroll
            for (int ntp = 0; ntp < NT/2; ntp++) {
                int brow = Cw + ntp*16 + nro;
                unsigned br[4];
                ldsm4(br, Bbase + (unsigned)brow*(ST*16) + ((cb ^ bxr) << 4));
                mma16816(cc[0][ntp*2],   a0r, br[0], br[1]);
                mma16816(cc[0][ntp*2+1], a0r, br[2], br[3]);
                mma16816(cc[1][ntp*2],   a1r, br[0], br[1]);
                mma16816(cc[1][ntp*2+1], a1r, br[2], br[3]);
            }
        }
    }

    // ---- epilogue: bias, Y store, stats, L2 max ----
    float* Y = (LAYER == 0) ? g_y1 : g_y2;
    const int tq = lane >> 2, tr = lane & 3;
    #pragma unroll
    for (int ni = 0; ni < NT; ni++) {
        int cn = Cw + ni*8 + tr*2;
        float b0 = sb[cn], b1 = sb[cn+1];
        float s0=0.f, s1=0.f, q0=0.f, q1=0.f, m0=-3.4e38f, m1=-3.4e38f;
        #pragma unroll
        for (int mi = 0; mi < 2; mi++) {
            float d0 = cc[mi][ni][0] + b0;
            float d1 = cc[mi][ni][1] + b1;
            float d2 = cc[mi][ni][2] + b0;
            float d3 = cc[mi][ni][3] + b1;
            if (LAYER < 2) {
                size_t r = rowBase + Rw + mi*16 + tq;
                *(float2*)&Y[r*64 + cn]     = make_float2(d0, d1);
                *(float2*)&Y[(r+8)*64 + cn] = make_float2(d2, d3);
            }
            s0 += d0 + d2;  s1 += d1 + d3;
            q0 += d0*d0 + d2*d2;  q1 += d1*d1 + d3*d3;
            m0 = fmaxf(m0, fmaxf(d0, d2));  m1 = fmaxf(m1, fmaxf(d1, d3));
        }
        #pragma unroll
        for (int o = 4; o <= 16; o <<= 1) {
            s0 += __shfl_xor_sync(0xffffffffu, s0, o);
            s1 += __shfl_xor_sync(0xffffffffu, s1, o);
            q0 += __shfl_xor_sync(0xffffffffu, q0, o);
            q1 += __shfl_xor_sync(0xffffffffu, q1, o);
            if (LAYER == 2) {
                m0 = fmaxf(m0, __shfl_xor_sync(0xffffffffu, m0, o));
                m1 = fmaxf(m1, __shfl_xor_sync(0xffffffffu, m1, o));
            }
        }
        if (lane < 4) {
            atomicAdd(&ssum[cn],   s0);
            atomicAdd(&ssum[cn+1], s1);
            atomicAdd(&ssq[cn],    q0);
            atomicAdd(&ssq[cn+1],  q1);
            if (LAYER == 2) {
                int bm = (int)(rowBase >> 5) + wm;
                size_t o0 = ((size_t)(bm >> 11)*128 + (unsigned)cn)*2048 + (unsigned)(bm & 2047);
                g_maxf[o0]        = m0;
                g_maxf[o0 + 2048] = m1;
            }
        }
    }
    __syncthreads();
    if (tid < CO) {
        atomicAdd(&g_sum[LAYER][tid], (double)ssum[tid]);
        atomicAdd(&g_sq [LAYER][tid], (double)ssq [tid]);
    }
}

// ---------------- BN stats -> scale/shift --------------------------------
__global__ void finalize_kernel(int L, const float* __restrict__ g,
                                const float* __restrict__ beta, int Co)
{
    int c = threadIdx.x;
    if (c >= Co) return;
    double inv = 1.0 / (double)NROWS;
    double mu  = g_sum[L][c] * inv;
    double var = g_sq[L][c] * inv - mu*mu;
    if (var < 0.0) var = 0.0;
    float s = g[c] / sqrtf((float)var + BN_EPS);
    g_s[L][c] = s;
    g_t[L][c] = fmaf(-(float)mu, s, beta[c]);
}

// ---------------- BN+ReLU on pre-pooled max, transposed layout -----------
__global__ void maxpool_kernel(float* __restrict__ out)
{
    int i = blockIdx.x * blockDim.x + threadIdx.x;   // over B*128*M = 2M
    int c = (i >> 11) & 127;
    float s = g_s[2][c], t = g_t[2][c];
    out[(size_t)Bb*Mm*3 + i] = fmaxf(fmaf(g_maxf[i], s, t), 0.f);
}

// ---------------- launch ---------------------------------------------------
extern "C" void kernel_launch(void* const* d_in, const int* in_sizes, int n_in,
                              void* d_out, int out_size)
{
    (void)in_sizes; (void)n_in; (void)out_size;
    const float* xyz  = (const float*)d_in[0];
    const float* feats= (const float*)d_in[1];
    const float* W1   = (const float*)d_in[2];
    const float* b1   = (const float*)d_in[3];
    const float* g1   = (const float*)d_in[4];
    const float* be1  = (const float*)d_in[5];
    const float* W2   = (const float*)d_in[6];
    const float* b2   = (const float*)d_in[7];
    const float* g2   = (const float*)d_in[8];
    const float* be2  = (const float*)d_in[9];
    const float* W3   = (const float*)d_in[10];
    const float* b3   = (const float*)d_in[11];
    const float* g3   = (const float*)d_in[12];
    const float* be3  = (const float*)d_in[13];
    float* out = (float*)d_out;
    const float* centers = out;   // knn writes centers into d_out[0 : B*M*3)

    const int SM0 = 128*24*16 + 64*24*16;     // 73728
    const int SM1 = 128*16*16 + 64*16*16;     // 49152
    const int SM2 = 128*16*16 + 128*16*16;    // 65536
    cudaFuncSetAttribute(mma_kernel<0>, cudaFuncAttributeMaxDynamicSharedMemorySize, SM0);
    cudaFuncSetAttribute(mma_kernel<1>, cudaFuncAttributeMaxDynamicSharedMemorySize, SM1);
    cudaFuncSetAttribute(mma_kernel<2>, cudaFuncAttributeMaxDynamicSharedMemorySize, SM2);

    prep_kernel<<<68, 256>>>(W1, W2, W3);
    pad_kernel<<<(Bb*Pp)/256, 256>>>(xyz);
    transpose_kernel<<<dim3(Pp/32, CIN/32, Bb), dim3(32, 8)>>>(feats);
    knn_kernel<<<Bb*Mm, 256>>>(out);

    mma_kernel<0><<<NROWS/128, 256, SM0>>>(b1, centers);
    finalize_kernel<<<1, 64>>>(0, g1, be1, 64);
    mma_kernel<1><<<NROWS/128, 256, SM1>>>(b2, centers);
    finalize_kernel<<<1, 64>>>(1, g2, be2, 64);
    mma_kernel<2><<<NROWS/128, 256, SM2>>>(b3, centers);
    finalize_kernel<<<1, 128>>>(2, g3, be3, 128);

    maxpool_kernel<<<(Bb*Mm*128)/256, 256>>>(out);
}

// round 8
// speedup vs baseline: 1.6762x; 1.0223x over previous
#include <cuda_runtime.h>
#include <cuda_bf16.h>
#include <cstdint>

#define Bb   8
#define Pp   8192
#define CIN  64
#define KK   32
#define Mm   2048
#define NROWS (Bb*Mm*KK)     // 524288
#define BN_EPS 1e-5f

// ---------------- scratch (device globals; no allocation) ----------------
__device__ __align__(128) float  g_featsT[(size_t)Bb*Pp*CIN];   // 16 MB
__device__ __align__(128) float4 g_xyz4[(size_t)Bb*Pp];         // 1 MB
__device__ __align__(128) float4 g_pka[(size_t)Bb*4096];        // (x0,x1,y0,y1)
__device__ __align__(128) float4 g_pkb[(size_t)Bb*4096];        // (z0,z1,n0,n1)
__device__ __align__(128) int    g_sel[(size_t)NROWS];          // 2 MB
__device__ __align__(128) float  g_y1[(size_t)NROWS*64];        // 134 MB
__device__ __align__(128) float  g_y2[(size_t)NROWS*64];        // 134 MB
__device__ __align__(128) float  g_maxf[(size_t)Bb*128*Mm];     // 8 MB
// weight hi/lo bf16 images (unswizzled, K-major rows)
__device__ __align__(128) __nv_bfloat16 g_Wh0[64*80],  g_Wl0[64*80];
__device__ __align__(128) __nv_bfloat16 g_Wh1[64*64],  g_Wl1[64*64];
__device__ __align__(128) __nv_bfloat16 g_Wh2[128*64], g_Wl2[128*64];
__device__ double g_sum[3][128];
__device__ double g_sq[3][128];
__device__ float  g_s[3][128];
__device__ float  g_t[3][128];

// ---------------- small helpers ------------------------------------------
__device__ __forceinline__ uint32_t smem_u32(const void* p) {
    uint32_t a;
    asm("{ .reg .u64 t; cvta.to.shared.u64 t, %1; cvt.u32.u64 %0, t; }" : "=r"(a) : "l"(p));
    return a;
}
__device__ __forceinline__ unsigned pkb(__nv_bfloat16 a, __nv_bfloat16 b) {
    __nv_bfloat162 t; t.x = a; t.y = b;
    return *(unsigned*)&t;
}
__device__ __forceinline__ void wsplit(float w, __nv_bfloat16& h, __nv_bfloat16& l) {
    h = __float2bfloat16(w);
    l = __float2bfloat16(w - __bfloat162float(h));
}
__device__ __forceinline__ void ldsm4(unsigned* r, uint32_t addr) {
    asm volatile("ldmatrix.sync.aligned.m8n8.x4.shared.b16 {%0,%1,%2,%3}, [%4];"
        : "=r"(r[0]), "=r"(r[1]), "=r"(r[2]), "=r"(r[3]) : "r"(addr));
}
__device__ __forceinline__ void mma16816(float* c, const unsigned* a,
                                         unsigned b0, unsigned b1) {
    asm volatile("mma.sync.aligned.m16n8k16.row.col.f32.bf16.bf16.f32 "
        "{%0,%1,%2,%3}, {%4,%5,%6,%7}, {%8,%9}, {%0,%1,%2,%3};"
        : "+f"(c[0]), "+f"(c[1]), "+f"(c[2]), "+f"(c[3])
        : "r"(a[0]), "r"(a[1]), "r"(a[2]), "r"(a[3]), "r"(b0), "r"(b1));
}
// packed f32x2 (exact per-lane fp32 rn)
#define PACK2(d, lo, hi)  asm("mov.b64 %0, {%1,%2};" : "=l"(d) : "f"(lo), "f"(hi))
#define UNPACK2U(lo, hi, v) asm("mov.b64 {%0,%1}, %2;" : "=r"(lo), "=r"(hi) : "l"(v))
#define MUL2(d, a, b)     asm("mul.rn.f32x2 %0, %1, %2;" : "=l"(d) : "l"(a), "l"(b))
#define ADD2(d, a, b)     asm("add.rn.f32x2 %0, %1, %2;" : "=l"(d) : "l"(a), "l"(b))

// ---------------- prep: zero stats + bf16 hi/lo weight images -------------
__global__ void prep_kernel(const float* __restrict__ W1,
                            const float* __restrict__ W2,
                            const float* __restrict__ W3)
{
    int tid = blockIdx.x * blockDim.x + threadIdx.x;
    if (tid < 384) { ((double*)g_sum)[tid] = 0.0; ((double*)g_sq)[tid] = 0.0; }
    if (tid >= 5120 + 4096 + 8192) return;
    float w;
    __nv_bfloat16 *ph, *pl;
    int idx;
    if (tid < 5120) {                   // W0: [64][80] = feats(64)+xyz(3)+pad
        int n = tid / 80, k = tid % 80;
        if (k < 64)      w = W1[n*67 + k + 3];
        else if (k < 67) w = W1[n*67 + (k - 64)];
        else             w = 0.f;
        ph = g_Wh0; pl = g_Wl0; idx = tid;
    } else if (tid < 9216) {            // W1: [64][64]
        int t = tid - 5120;
        w = W2[t];
        ph = g_Wh1; pl = g_Wl1; idx = t;
    } else {                            // W2: [128][64]
        int t = tid - 9216;
        w = W3[t];
        ph = g_Wh2; pl = g_Wl2; idx = t;
    }
    __nv_bfloat16 h, l; wsplit(w, h, l);
    ph[idx] = h; pl[idx] = l;
}

// ---------------- xyz -> padded float4 + packed pair arrays (w/ |x|^2) ----
__global__ void pad_kernel(const float* __restrict__ xyz)
{
    int i = blockIdx.x * blockDim.x + threadIdx.x;   // Bb*4096
    int b = i >> 12, q = i & 4095;
    const float* s = xyz + (((size_t)(b << 13)) + (size_t)q*2)*3;
    float x0 = s[0], y0 = s[1], z0 = s[2];
    float x1 = s[3], y1 = s[4], z1 = s[5];
    float n0 = __fadd_rn(__fadd_rn(__fmul_rn(x0,x0), __fmul_rn(y0,y0)), __fmul_rn(z0,z0));
    float n1 = __fadd_rn(__fadd_rn(__fmul_rn(x1,x1), __fmul_rn(y1,y1)), __fmul_rn(z1,z1));
    g_pka[i] = make_float4(x0, x1, y0, y1);
    g_pkb[i] = make_float4(z0, z1, n0, n1);
    g_xyz4[(size_t)(b << 13) + q*2]     = make_float4(x0, y0, z0, 0.f);
    g_xyz4[(size_t)(b << 13) + q*2 + 1] = make_float4(x1, y1, z1, 0.f);
}

// ---------------- feats (B,C,P) -> featsT (B,P,C) ------------------------
__global__ void transpose_kernel(const float* __restrict__ f)
{
    __shared__ float tile[32][33];
    int b  = blockIdx.z;
    int c0 = blockIdx.y * 32;
    int p0 = blockIdx.x * 32;
    int tx = threadIdx.x, ty = threadIdx.y;
    #pragma unroll
    for (int i = ty; i < 32; i += 8)
        tile[i][tx] = f[((size_t)b*CIN + c0 + i)*Pp + p0 + tx];
    __syncthreads();
    #pragma unroll
    for (int i = ty; i < 32; i += 8)
        g_featsT[((size_t)b*Pp + p0 + i)*CIN + c0 + tx] = tile[tx][i];
}

// ---------------- KNN: f32x2 distances + pass0 + compacted radix ---------
#define CAP 4096
__global__ void __launch_bounds__(256) knn_kernel(float* __restrict__ centers_out)
{
    int bm = blockIdx.x;
    int b  = bm >> 11;
    int m  = bm & 2047;
    __shared__ float ctr[3];
    __shared__ unsigned int whist[8][256];
    __shared__ unsigned int s_prefix;
    __shared__ int s_remaining;
    __shared__ int s_cnt;
    __shared__ int s_ncand;
    __shared__ int s_min;
    __shared__ int s_last;
    __shared__ unsigned int cand_dm[CAP];
    __shared__ int          cand_id[CAP];
    int tid  = threadIdx.x;
    int wid  = tid >> 5;
    int lane = tid & 31;

    if (tid == 0) {
        int ci = (m == 2047) ? 8191
               : (int)(__fmul_rn(8191.0f, __fdiv_rn((float)m, 2047.0f)));
        float4 cp = g_xyz4[(size_t)(b << 13) + ci];
        ctr[0] = cp.x; ctr[1] = cp.y; ctr[2] = cp.z;
        float* co = centers_out + (size_t)bm*3;
        co[0] = cp.x; co[1] = cp.y; co[2] = cp.z;
        s_prefix = 0u; s_remaining = KK; s_cnt = 0; s_ncand = 0; s_last = -1;
    }
    // zero per-warp hists while waiting
    #pragma unroll
    for (int t = tid; t < 2048; t += 256) ((unsigned*)whist)[t] = 0;
    __syncthreads();
    float cx = ctr[0], cy = ctr[1], cz = ctr[2];
    float cn = __fadd_rn(__fadd_rn(__fmul_rn(cx,cx), __fmul_rn(cy,cy)), __fmul_rn(cz,cz));

    unsigned long long cxp, cyp, czp, cnp;
    PACK2(cxp, cx, cx); PACK2(cyp, cy, cy); PACK2(czp, cz, cz); PACK2(cnp, cn, cn);

    // distances: thread handles point-pairs q = tid + jj*256 (points 2q, 2q+1)
    unsigned int dm[32];
    #pragma unroll
    for (int jj = 0; jj < 16; jj++) {
        int q = tid + jj*256;
        float4 A = g_pka[(size_t)(b << 12) + q];
        float4 B = g_pkb[(size_t)(b << 12) + q];
        unsigned long long xp, yp, zp, np;
        PACK2(xp, A.x, A.y); PACK2(yp, A.z, A.w);
        PACK2(zp, B.x, B.y); PACK2(np, B.z, B.w);
        unsigned long long t1, t2, t3, s12, dt, sum, dd, d2;
        MUL2(t1, cxp, xp); MUL2(t2, cyp, yp); MUL2(t3, czp, zp);
        ADD2(s12, t1, t2); ADD2(dt, s12, t3);
        ADD2(sum, cnp, np);
        ADD2(dd, dt, dt);                       // == 2*dt exactly
        dd ^= 0x8000000080000000ULL;            // negate both lanes
        ADD2(d2, sum, dd);                      // == fsub_rn(sum, 2*dt)
        unsigned u0, u1;
        UNPACK2U(u0, u1, d2);
        dm[2*jj]   = u0 ^ ((unsigned)(((int)u0) >> 31) | 0x80000000u);
        dm[2*jj+1] = u1 ^ ((unsigned)(((int)u1) >> 31) | 0x80000000u);
    }

    // scan helper
    auto scan = [&](int NC) {
        if (tid < 32) {
            unsigned cum[8];
            unsigned run = 0;
            #pragma unroll
            for (int i = 0; i < 8; i++) {
                int bin = tid*8 + i;
                unsigned h = 0;
                for (int c = 0; c < NC; c++) h += whist[c][bin];
                run += h; cum[i] = run;
            }
            unsigned tot = run;
            unsigned off = tot;
            #pragma unroll
            for (int dd2 = 1; dd2 < 32; dd2 <<= 1) {
                unsigned v = __shfl_up_sync(0xffffffffu, off, dd2);
                if (lane >= dd2) off += v;
            }
            off -= tot;
            unsigned rem = (unsigned)s_remaining;
            #pragma unroll
            for (int i = 0; i < 8; i++) {
                unsigned prev = off + (i ? cum[i-1] : 0u);
                unsigned cu   = off + cum[i];
                if (prev < rem && cu >= rem) {
                    s_prefix = (s_prefix << 8) | (unsigned)(tid*8 + i);
                    s_remaining = (int)(rem - prev);
                }
            }
        }
    };

    // ---- pass 0 (full), per-warp hists ----
    #pragma unroll
    for (int j = 0; j < 32; j++) {
        unsigned bkt = dm[j] >> 24;
        unsigned peers = __match_any_sync(0xffffffffu, bkt);
        if ((peers & ((1u << lane) - 1u)) == 0u)
            atomicAdd(&whist[wid][bkt], __popc(peers));
    }
    __syncthreads();
    scan(8);
    __syncthreads();

    int* selg = g_sel + (size_t)bm * KK;
    // ---- compact: bucket < pref8 -> direct select; == pref8 -> candidate ----
    {
        unsigned pref8 = s_prefix;
        #pragma unroll
        for (int j = 0; j < 32; j++) {
            unsigned bkt = dm[j] >> 24;
            int pid = ((tid + (j >> 1)*256) << 1) | (j & 1);
            if (bkt < pref8) {
                int s = atomicAdd(&s_cnt, 1);
                selg[s] = pid;
            }
            bool isc = (bkt == pref8);
            unsigned mk = __ballot_sync(0xffffffffu, isc);
            if (isc) {
                int ldr = __ffs(mk) - 1;
                int basep = 0;
                if (lane == ldr) basep = atomicAdd(&s_ncand, __popc(mk));
                basep = __shfl_sync(mk, basep, ldr);
                int pos = basep + __popc(mk & ((1u << lane) - 1u));
                if (pos < CAP) { cand_dm[pos] = dm[j]; cand_id[pos] = pid; }
            }
        }
        __syncthreads();
    }
    int ncand = s_ncand;

    if (ncand <= CAP) {
        // ---- passes 1..3 over candidates ----
        int nIter = (ncand + 255) >> 8;
        for (int pass = 1; pass < 4; pass++) {
            if (tid < 256) whist[0][tid] = 0;
            __syncthreads();
            unsigned pref = s_prefix;
            int sh = 24 - 8*pass;
            for (int it = 0; it < nIter; it++) {
                int t = it*256 + tid;
                unsigned dv = (t < ncand) ? cand_dm[t] : 0u;
                bool ok = (t < ncand) && ((dv >> (sh + 8)) == pref);
                unsigned bkt = (dv >> sh) & 255u;
                unsigned mask = __ballot_sync(0xffffffffu, ok);
                if (ok) {
                    unsigned peers = __match_any_sync(mask, bkt);
                    if ((peers & ((1u << lane) - 1u)) == 0u)
                        atomicAdd(&whist[0][bkt], __popc(peers));
                }
            }
            __syncthreads();
            scan(1);
            __syncthreads();
        }
        unsigned thr = s_prefix;
        int rem = s_remaining;
        // ---- selection from candidates ----
        for (int it = 0; it < nIter; it++) {
            int t = it*256 + tid;
            if (t < ncand && cand_dm[t] < thr) {
                int s = atomicAdd(&s_cnt, 1);
                selg[s] = cand_id[t];
            }
        }
        __syncthreads();
        int base = s_cnt;
        for (int r = 0; r < rem; r++) {
            if (tid == 0) s_min = 0x7fffffff;
            __syncthreads();
            int last = s_last;
            for (int it = 0; it < nIter; it++) {
                int t = it*256 + tid;
                if (t < ncand && cand_dm[t] == thr && cand_id[t] > last)
                    atomicMin(&s_min, cand_id[t]);
            }
            __syncthreads();
            if (tid == 0) { selg[base + r] = s_min; s_last = s_min; }
            __syncthreads();
        }
    } else {
        // ---- exact fallback: full passes 1..3 + full selection ----
        if (tid == 0) s_cnt = 0;   // discard direct selections; redo fully
        for (int pass = 1; pass < 4; pass++) {
            #pragma unroll
            for (int t = tid; t < 2048; t += 256) ((unsigned*)whist)[t] = 0;
            __syncthreads();
            unsigned pref = s_prefix;
            int sh = 24 - 8*pass;
            #pragma unroll
            for (int j = 0; j < 32; j++) {
                bool ok = (dm[j] >> (sh + 8)) == pref;
                unsigned bkt = (dm[j] >> sh) & 255u;
                unsigned mask = __ballot_sync(0xffffffffu, ok);
                if (ok) {
                    unsigned peers = __match_any_sync(mask, bkt);
                    if ((peers & ((1u << lane) - 1u)) == 0u)
                        atomicAdd(&whist[wid][bkt], __popc(peers));
                }
            }
            __syncthreads();
            scan(8);
            __syncthreads();
        }
        unsigned thr = s_prefix;
        int rem = s_remaining;
        #pragma unroll
        for (int j = 0; j < 32; j++) {
            int pid = ((tid + (j >> 1)*256) << 1) | (j & 1);
            if (dm[j] < thr) {
                int s = atomicAdd(&s_cnt, 1);
                selg[s] = pid;
            }
        }
        __syncthreads();
        int base = s_cnt;
        for (int r = 0; r < rem; r++) {
            if (tid == 0) s_min = 0x7fffffff;
            __syncthreads();
            int last = s_last;
            #pragma unroll
            for (int j = 0; j < 32; j++) {
                int pid = ((tid + (j >> 1)*256) << 1) | (j & 1);
                if (dm[j] == thr && pid > last) atomicMin(&s_min, pid);
            }
            __syncthreads();
            if (tid == 0) { selg[base + r] = s_min; s_last = s_min; }
            __syncthreads();
        }
    }
}

// ---------------- bf16x3 GEMM via mma.sync (HMMA tensor pipe) -------------
template<int LAYER>
__global__ void __launch_bounds__(256) mma_kernel(const float* __restrict__ bias,
                                                  const float* __restrict__ centers)
{
    constexpr int CO    = (LAYER == 2) ? 128 : 64;
    constexpr int K     = (LAYER == 0) ? 80 : 64;
    constexpr int KC    = K / 8;
    constexpr int NKCH  = K / 16;
    constexpr int ST    = (LAYER == 0) ? 24 : 16;
    constexpr int ASZ   = 128 * ST * 16;
    constexpr int WCOLS = CO / 2;
    constexpr int NT    = WCOLS / 8;
    constexpr int HC    = KC / 2;

    extern __shared__ __align__(16) char dyn[];
    char* Asm = dyn;
    char* Bsm = dyn + ASZ;
    __shared__ float sb[CO], ssum[CO], ssq[CO];
    __shared__ float sS[64], sT[64];

    const int tid = threadIdx.x;
    const size_t rowBase = (size_t)blockIdx.x * 128;
    const int bBat = (int)(rowBase >> 16);

    if (tid < CO) { sb[tid] = bias[tid]; ssum[tid] = 0.f; ssq[tid] = 0.f; }
    if (LAYER > 0 && tid < 64) { sS[tid] = g_s[LAYER-1][tid]; sT[tid] = g_t[LAYER-1][tid]; }
    __syncthreads();

    // ---- A build: 2 threads per row ----
    {
        int row = tid >> 1, half = tid & 1;
        const float* srcf;
        float dx = 0.f, dy = 0.f, dz = 0.f;
        if (LAYER == 0) {
            int p = g_sel[rowBase + row];
            srcf = g_featsT + (((size_t)bBat << 13) + (unsigned)p) * 64;
            float4 X = g_xyz4[((size_t)bBat << 13) + (unsigned)p];
            int bm = (int)((rowBase + row) >> 5);
            dx = X.x - centers[bm*3 + 0];
            dy = X.y - centers[bm*3 + 1];
            dz = X.z - centers[bm*3 + 2];
        } else {
            srcf = ((LAYER == 1) ? g_y1 : g_y2) + (rowBase + row) * 64;
        }
        int rx = row & 7;
        unsigned rowOff = (unsigned)row * (ST*16);
        #pragma unroll
        for (int j = 0; j < HC; j++) {
            int c  = half*HC + j;
            int k0 = c*8;
            float f[8];
            if (LAYER > 0) {
                float4 v0 = *(const float4*)(srcf + k0);
                float4 v1 = *(const float4*)(srcf + k0 + 4);
                f[0]=v0.x; f[1]=v0.y; f[2]=v0.z; f[3]=v0.w;
                f[4]=v1.x; f[5]=v1.y; f[6]=v1.z; f[7]=v1.w;
                #pragma unroll
                for (int i = 0; i < 8; i++)
                    f[i] = fmaxf(fmaf(f[i], sS[k0+i], sT[k0+i]), 0.f);
            } else {
                if (k0 + 8 <= 64) {
                    float4 v0 = *(const float4*)(srcf + k0);
                    float4 v1 = *(const float4*)(srcf + k0 + 4);
                    f[0]=v0.x; f[1]=v0.y; f[2]=v0.z; f[3]=v0.w;
                    f[4]=v1.x; f[5]=v1.y; f[6]=v1.z; f[7]=v1.w;
                } else if (k0 == 64) {
                    f[0]=dx; f[1]=dy; f[2]=dz;
                    f[3]=0.f; f[4]=0.f; f[5]=0.f; f[6]=0.f; f[7]=0.f;
                } else {
                    #pragma unroll
                    for (int i = 0; i < 8; i++) f[i] = 0.f;
                }
            }
            unsigned hv[4], lv[4];
            #pragma unroll
            for (int q = 0; q < 4; q++) {
                __nv_bfloat16 ha, la, hb, lb;
                wsplit(f[2*q],   ha, la);
                wsplit(f[2*q+1], hb, lb);
                hv[q] = pkb(ha, hb); lv[q] = pkb(la, lb);
            }
            unsigned ch = (unsigned)(c ^ rx);
            unsigned cl = (unsigned)((KC + c) ^ rx);
            *(uint4*)(Asm + rowOff + ch*16) = make_uint4(hv[0],hv[1],hv[2],hv[3]);
            *(uint4*)(Asm + rowOff + cl*16) = make_uint4(lv[0],lv[1],lv[2],lv[3]);
        }
    }
    // ---- B copy: hi/lo images -> swizzled smem ----
    {
        const __nv_bfloat16* Wh = (LAYER==0) ? g_Wh0 : (LAYER==1) ? g_Wh1 : g_Wh2;
        const __nv_bfloat16* Wl = (LAYER==0) ? g_Wl0 : (LAYER==1) ? g_Wl1 : g_Wl2;
        for (int i = tid; i < CO * 2 * KC; i += 256) {
            int n = i / (2*KC), c = i % (2*KC);
            const __nv_bfloat16* src = (c < KC) ? (Wh + n*K + c*8)
                                                : (Wl + n*K + (c - KC)*8);
            uint4 v = *(const uint4*)src;
            unsigned cs = (unsigned)(c ^ (n & 7));
            *(uint4*)(Bsm + (unsigned)n*(ST*16) + cs*16) = v;
        }
    }
    __syncthreads();

    // ---- MMA main loop ----
    const uint32_t Abase = smem_u32(Asm);
    const uint32_t Bbase = smem_u32(Bsm);
    const int warp = tid >> 5, lane = tid & 31;
    const int wm = warp >> 1, wn = warp & 1;
    const int Rw = wm*32, Cw = wn*WCOLS;

    const int arow = lane & 15;
    const uint32_t aAddr0 = Abase + (unsigned)(Rw + arow)      * (ST*16);
    const uint32_t aAddr1 = Abase + (unsigned)(Rw + 16 + arow) * (ST*16);
    const unsigned axr = (unsigned)(arow & 7);
    const unsigned aHi = (unsigned)(lane >> 4);
    const int nro  = (lane & 7) + ((lane & 16) >> 1);
    const unsigned bxr = (unsigned)(nro & 7);
    const unsigned bHi = (unsigned)((lane >> 3) & 1);

    float cc[2][NT][4];
    #pragma unroll
    for (int mi = 0; mi < 2; mi++)
        #pragma unroll
        for (int ni = 0; ni < NT; ni++)
            #pragma unroll
            for (int q = 0; q < 4; q++) cc[mi][ni][q] = 0.f;

    #pragma unroll
    for (int s = 0; s < 3; s++) {
        const unsigned sa = (s == 1) ? KC : 0;
        const unsigned sbc = (s == 2) ? KC : 0;
        #pragma unroll
        for (int kc = 0; kc < NKCH; kc++) {
            unsigned ca = sa + kc*2 + aHi;
            unsigned a0r[4], a1r[4];
            ldsm4(a0r, aAddr0 + ((ca ^ axr) << 4));
            ldsm4(a1r, aAddr1 + ((ca ^ axr) << 4));
            unsigned cb = sbc + kc*2 + bHi;
            #pragma unroll
            for (int ntp = 0; ntp < NT/2; ntp++) {
                int brow = Cw + ntp*16 + nro;
                unsigned br[4];
                ldsm4(br, Bbase + (unsigned)brow*(ST*16) + ((cb ^ bxr) << 4));
                mma16816(cc[0][ntp*2],   a0r, br[0], br[1]);
                mma16816(cc[0][ntp*2+1], a0r, br[2], br[3]);
                mma16816(cc[1][ntp*2],   a1r, br[0], br[1]);
                mma16816(cc[1][ntp*2+1], a1r, br[2], br[3]);
            }
        }
    }

    // ---- epilogue: bias, Y store, stats, L2 max ----
    float* Y = (LAYER == 0) ? g_y1 : g_y2;
    const int tq = lane >> 2, tr = lane & 3;
    #pragma unroll
    for (int ni = 0; ni < NT; ni++) {
        int cn = Cw + ni*8 + tr*2;
        float b0 = sb[cn], b1 = sb[cn+1];
        float s0=0.f, s1=0.f, q0=0.f, q1=0.f, m0=-3.4e38f, m1=-3.4e38f;
        #pragma unroll
        for (int mi = 0; mi < 2; mi++) {
            float d0 = cc[mi][ni][0] + b0;
            float d1 = cc[mi][ni][1] + b1;
            float d2 = cc[mi][ni][2] + b0;
            float d3 = cc[mi][ni][3] + b1;
            if (LAYER < 2) {
                size_t r = rowBase + Rw + mi*16 + tq;
                *(float2*)&Y[r*64 + cn]     = make_float2(d0, d1);
                *(float2*)&Y[(r+8)*64 + cn] = make_float2(d2, d3);
            }
            s0 += d0 + d2;  s1 += d1 + d3;
            q0 += d0*d0 + d2*d2;  q1 += d1*d1 + d3*d3;
            m0 = fmaxf(m0, fmaxf(d0, d2));  m1 = fmaxf(m1, fmaxf(d1, d3));
        }
        #pragma unroll
        for (int o = 4; o <= 16; o <<= 1) {
            s0 += __shfl_xor_sync(0xffffffffu, s0, o);
            s1 += __shfl_xor_sync(0xffffffffu, s1, o);
            q0 += __shfl_xor_sync(0xffffffffu, q0, o);
            q1 += __shfl_xor_sync(0xffffffffu, q1, o);
            if (LAYER == 2) {
                m0 = fmaxf(m0, __shfl_xor_sync(0xffffffffu, m0, o));
                m1 = fmaxf(m1, __shfl_xor_sync(0xffffffffu, m1, o));
            }
        }
        if (lane < 4) {
            atomicAdd(&ssum[cn],   s0);
            atomicAdd(&ssum[cn+1], s1);
            atomicAdd(&ssq[cn],    q0);
            atomicAdd(&ssq[cn+1],  q1);
            if (LAYER == 2) {
                int bm = (int)(rowBase >> 5) + wm;
                size_t o0 = ((size_t)(bm >> 11)*128 + (unsigned)cn)*2048 + (unsigned)(bm & 2047);
                g_maxf[o0]        = m0;
                g_maxf[o0 + 2048] = m1;
            }
        }
    }
    __syncthreads();
    if (tid < CO) {
        atomicAdd(&g_sum[LAYER][tid], (double)ssum[tid]);
        atomicAdd(&g_sq [LAYER][tid], (double)ssq [tid]);
    }
}

// ---------------- BN stats -> scale/shift --------------------------------
__global__ void finalize_kernel(int L, const float* __restrict__ g,
                                const float* __restrict__ beta, int Co)
{
    int c = threadIdx.x;
    if (c >= Co) return;
    double inv = 1.0 / (double)NROWS;
    double mu  = g_sum[L][c] * inv;
    double var = g_sq[L][c] * inv - mu*mu;
    if (var < 0.0) var = 0.0;
    float s = g[c] / sqrtf((float)var + BN_EPS);
    g_s[L][c] = s;
    g_t[L][c] = fmaf(-(float)mu, s, beta[c]);
}

// ---------------- BN+ReLU on pre-pooled max, transposed layout -----------
__global__ void maxpool_kernel(float* __restrict__ out)
{
    int i = blockIdx.x * blockDim.x + threadIdx.x;   // over B*128*M = 2M
    int c = (i >> 11) & 127;
    float s = g_s[2][c], t = g_t[2][c];
    out[(size_t)Bb*Mm*3 + i] = fmaxf(fmaf(g_maxf[i], s, t), 0.f);
}

// ---------------- launch ---------------------------------------------------
extern "C" void kernel_launch(void* const* d_in, const int* in_sizes, int n_in,
                              void* d_out, int out_size)
{
    (void)in_sizes; (void)n_in; (void)out_size;
    const float* xyz  = (const float*)d_in[0];
    const float* feats= (const float*)d_in[1];
    const float* W1   = (const float*)d_in[2];
    const float* b1   = (const float*)d_in[3];
    const float* g1   = (const float*)d_in[4];
    const float* be1  = (const float*)d_in[5];
    const float* W2   = (const float*)d_in[6];
    const float* b2   = (const float*)d_in[7];
    const float* g2   = (const float*)d_in[8];
    const float* be2  = (const float*)d_in[9];
    const float* W3   = (const float*)d_in[10];
    const float* b3   = (const float*)d_in[11];
    const float* g3   = (const float*)d_in[12];
    const float* be3  = (const float*)d_in[13];
    float* out = (float*)d_out;
    const float* centers = out;   // knn writes centers into d_out[0 : B*M*3)

    const int SM0 = 128*24*16 + 64*24*16;     // 73728
    const int SM1 = 128*16*16 + 64*16*16;     // 49152
    const int SM2 = 128*16*16 + 128*16*16;    // 65536
    cudaFuncSetAttribute(mma_kernel<0>, cudaFuncAttributeMaxDynamicSharedMemorySize, SM0);
    cudaFuncSetAttribute(mma_kernel<1>, cudaFuncAttributeMaxDynamicSharedMemorySize, SM1);
    cudaFuncSetAttribute(mma_kernel<2>, cudaFuncAttributeMaxDynamicSharedMemorySize, SM2);

    prep_kernel<<<68, 256>>>(W1, W2, W3);
    pad_kernel<<<(Bb*4096)/256, 256>>>(xyz);
    transpose_kernel<<<dim3(Pp/32, CIN/32, Bb), dim3(32, 8)>>>(feats);
    knn_kernel<<<Bb*Mm, 256>>>(out);

    mma_kernel<0><<<NROWS/128, 256, SM0>>>(b1, centers);
    finalize_kernel<<<1, 64>>>(0, g1, be1, 64);
    mma_kernel<1><<<NROWS/128, 256, SM1>>>(b2, centers);
    finalize_kernel<<<1, 64>>>(1, g2, be2, 64);
    mma_kernel<2><<<NROWS/128, 256, SM2>>>(b3, centers);
    finalize_kernel<<<1, 128>>>(2, g3, be3, 128);

    maxpool_kernel<<<(Bb*Mm*128)/256, 256>>>(out);
}

// round 9
// speedup vs baseline: 1.8988x; 1.1328x over previous
#include <cuda_runtime.h>
#include <cuda_bf16.h>
#include <cstdint>

#define Bb   8
#define Pp   8192
#define CIN  64
#define KK   32
#define Mm   2048
#define NROWS (Bb*Mm*KK)     // 524288
#define BN_EPS 1e-5f

// ---------------- scratch (device globals; no allocation) ----------------
__device__ __align__(128) float  g_featsT[(size_t)Bb*Pp*CIN];   // 16 MB
__device__ __align__(128) float4 g_xyz4[(size_t)Bb*Pp];         // 1 MB
__device__ __align__(128) float4 g_pka[(size_t)Bb*4096];        // (x0,x1,y0,y1)
__device__ __align__(128) float4 g_pkb[(size_t)Bb*4096];        // (z0,z1,n0,n1)
__device__ __align__(128) int    g_sel[(size_t)NROWS];          // 2 MB
__device__ __align__(128) float  g_y1[(size_t)NROWS*64];        // 134 MB
__device__ __align__(128) float  g_y2[(size_t)NROWS*64];        // 134 MB
__device__ __align__(128) float  g_maxf[(size_t)Bb*128*Mm];     // 8 MB
// weight hi/lo bf16 images (unswizzled, K-major rows)
__device__ __align__(128) __nv_bfloat16 g_Wh0[64*80],  g_Wl0[64*80];
__device__ __align__(128) __nv_bfloat16 g_Wh1[64*64],  g_Wl1[64*64];
__device__ __align__(128) __nv_bfloat16 g_Wh2[128*64], g_Wl2[128*64];
__device__ double g_sum[3][128];
__device__ double g_sq[3][128];
__device__ float  g_s[3][128];
__device__ float  g_t[3][128];

// ---------------- small helpers ------------------------------------------
__device__ __forceinline__ uint32_t smem_u32(const void* p) {
    uint32_t a;
    asm("{ .reg .u64 t; cvta.to.shared.u64 t, %1; cvt.u32.u64 %0, t; }" : "=r"(a) : "l"(p));
    return a;
}
__device__ __forceinline__ unsigned pkb(__nv_bfloat16 a, __nv_bfloat16 b) {
    __nv_bfloat162 t; t.x = a; t.y = b;
    return *(unsigned*)&t;
}
__device__ __forceinline__ void wsplit(float w, __nv_bfloat16& h, __nv_bfloat16& l) {
    h = __float2bfloat16(w);
    l = __float2bfloat16(w - __bfloat162float(h));
}
__device__ __forceinline__ void ldsm4(unsigned* r, uint32_t addr) {
    asm volatile("ldmatrix.sync.aligned.m8n8.x4.shared.b16 {%0,%1,%2,%3}, [%4];"
        : "=r"(r[0]), "=r"(r[1]), "=r"(r[2]), "=r"(r[3]) : "r"(addr));
}
__device__ __forceinline__ void mma16816(float* c, const unsigned* a,
                                         unsigned b0, unsigned b1) {
    asm volatile("mma.sync.aligned.m16n8k16.row.col.f32.bf16.bf16.f32 "
        "{%0,%1,%2,%3}, {%4,%5,%6,%7}, {%8,%9}, {%0,%1,%2,%3};"
        : "+f"(c[0]), "+f"(c[1]), "+f"(c[2]), "+f"(c[3])
        : "r"(a[0]), "r"(a[1]), "r"(a[2]), "r"(a[3]), "r"(b0), "r"(b1));
}
// packed f32x2 (exact per-lane fp32 rn)
#define PACK2(d, lo, hi)  asm("mov.b64 %0, {%1,%2};" : "=l"(d) : "f"(lo), "f"(hi))
#define UNPACK2U(lo, hi, v) asm("mov.b64 {%0,%1}, %2;" : "=r"(lo), "=r"(hi) : "l"(v))
#define MUL2(d, a, b)     asm("mul.rn.f32x2 %0, %1, %2;" : "=l"(d) : "l"(a), "l"(b))
#define ADD2(d, a, b)     asm("add.rn.f32x2 %0, %1, %2;" : "=l"(d) : "l"(a), "l"(b))

// ---------------- prep: zero stats + bf16 hi/lo weight images -------------
__global__ void prep_kernel(const float* __restrict__ W1,
                            const float* __restrict__ W2,
                            const float* __restrict__ W3)
{
    int tid = blockIdx.x * blockDim.x + threadIdx.x;
    if (tid < 384) { ((double*)g_sum)[tid] = 0.0; ((double*)g_sq)[tid] = 0.0; }
    if (tid >= 5120 + 4096 + 8192) return;
    float w;
    __nv_bfloat16 *ph, *pl;
    int idx;
    if (tid < 5120) {                   // W0: [64][80] = feats(64)+xyz(3)+pad
        int n = tid / 80, k = tid % 80;
        if (k < 64)      w = W1[n*67 + k + 3];
        else if (k < 67) w = W1[n*67 + (k - 64)];
        else             w = 0.f;
        ph = g_Wh0; pl = g_Wl0; idx = tid;
    } else if (tid < 9216) {            // W1: [64][64]
        int t = tid - 5120;
        w = W2[t];
        ph = g_Wh1; pl = g_Wl1; idx = t;
    } else {                            // W2: [128][64]
        int t = tid - 9216;
        w = W3[t];
        ph = g_Wh2; pl = g_Wl2; idx = t;
    }
    __nv_bfloat16 h, l; wsplit(w, h, l);
    ph[idx] = h; pl[idx] = l;
}

// ---------------- xyz -> padded float4 + packed pair arrays (w/ |x|^2) ----
__global__ void pad_kernel(const float* __restrict__ xyz)
{
    int i = blockIdx.x * blockDim.x + threadIdx.x;   // Bb*4096
    int b = i >> 12, q = i & 4095;
    const float* s = xyz + (((size_t)(b << 13)) + (size_t)q*2)*3;
    float x0 = s[0], y0 = s[1], z0 = s[2];
    float x1 = s[3], y1 = s[4], z1 = s[5];
    float n0 = __fadd_rn(__fadd_rn(__fmul_rn(x0,x0), __fmul_rn(y0,y0)), __fmul_rn(z0,z0));
    float n1 = __fadd_rn(__fadd_rn(__fmul_rn(x1,x1), __fmul_rn(y1,y1)), __fmul_rn(z1,z1));
    g_pka[i] = make_float4(x0, x1, y0, y1);
    g_pkb[i] = make_float4(z0, z1, n0, n1);
    g_xyz4[(size_t)(b << 13) + q*2]     = make_float4(x0, y0, z0, 0.f);
    g_xyz4[(size_t)(b << 13) + q*2 + 1] = make_float4(x1, y1, z1, 0.f);
}

// ---------------- feats (B,C,P) -> featsT (B,P,C) ------------------------
__global__ void transpose_kernel(const float* __restrict__ f)
{
    __shared__ float tile[32][33];
    int b  = blockIdx.z;
    int c0 = blockIdx.y * 32;
    int p0 = blockIdx.x * 32;
    int tx = threadIdx.x, ty = threadIdx.y;
    #pragma unroll
    for (int i = ty; i < 32; i += 8)
        tile[i][tx] = f[((size_t)b*CIN + c0 + i)*Pp + p0 + tx];
    __syncthreads();
    #pragma unroll
    for (int i = ty; i < 32; i += 8)
        g_featsT[((size_t)b*Pp + p0 + i)*CIN + c0 + tx] = tile[tx][i];
}

// ---------------- KNN: sample-pivot + compare-compact + exact radix ------
#define CAP 3072
__global__ void __launch_bounds__(256, 4) knn_kernel(float* __restrict__ centers_out)
{
    int bm = blockIdx.x;
    int b  = bm >> 11;
    int m  = bm & 2047;
    __shared__ float ctr[3];
    __shared__ unsigned int hist[256];
    __shared__ unsigned int s_prefix;
    __shared__ int s_remaining;
    __shared__ int s_cnt;
    __shared__ int s_ncand;
    __shared__ int s_min;
    __shared__ int s_last;
    __shared__ unsigned int cand_dm[CAP];
    __shared__ int          cand_id[CAP];
    int tid  = threadIdx.x;
    int lane = tid & 31;

    if (tid == 0) {
        int ci = (m == 2047) ? 8191
               : (int)(__fmul_rn(8191.0f, __fdiv_rn((float)m, 2047.0f)));
        float4 cp = g_xyz4[(size_t)(b << 13) + ci];
        ctr[0] = cp.x; ctr[1] = cp.y; ctr[2] = cp.z;
        float* co = centers_out + (size_t)bm*3;
        co[0] = cp.x; co[1] = cp.y; co[2] = cp.z;
        s_prefix = 0u; s_remaining = KK; s_cnt = 0; s_ncand = 0; s_last = -1;
    }
    __syncthreads();
    float cx = ctr[0], cy = ctr[1], cz = ctr[2];
    float cn = __fadd_rn(__fadd_rn(__fmul_rn(cx,cx), __fmul_rn(cy,cy)), __fmul_rn(cz,cz));

    unsigned long long cxp, cyp, czp, cnp;
    PACK2(cxp, cx, cx); PACK2(cyp, cy, cy); PACK2(czp, cz, cz); PACK2(cnp, cn, cn);

    const float4* PA = g_pka + ((size_t)b << 12);
    const float4* PB = g_pkb + ((size_t)b << 12);

    // packed exact fp32 distance of pair q -> mapped uints (m0: point 2q, m1: 2q+1)
    auto dist2 = [&](int q, unsigned& m0, unsigned& m1) {
        float4 A = __ldg(PA + q);
        float4 B = __ldg(PB + q);
        unsigned long long xp, yp, zp, np;
        PACK2(xp, A.x, A.y); PACK2(yp, A.z, A.w);
        PACK2(zp, B.x, B.y); PACK2(np, B.z, B.w);
        unsigned long long t1, t2, t3, s12, dt, sum, dd, d2;
        MUL2(t1, cxp, xp); MUL2(t2, cyp, yp); MUL2(t3, czp, zp);
        ADD2(s12, t1, t2); ADD2(dt, s12, t3);
        ADD2(sum, cnp, np);
        ADD2(dd, dt, dt);
        dd ^= 0x8000000080000000ULL;
        ADD2(d2, sum, dd);
        unsigned u0, u1;
        UNPACK2U(u0, u1, d2);
        m0 = u0 ^ ((unsigned)(((int)u0) >> 31) | 0x80000000u);
        m1 = u1 ^ ((unsigned)(((int)u1) >> 31) | 0x80000000u);
    };

    // 256-bin scan: find byte of 32nd-smallest; update s_prefix/s_remaining
    auto scan = [&]() {
        if (tid < 32) {
            unsigned cum[8];
            unsigned run = 0;
            #pragma unroll
            for (int i = 0; i < 8; i++) { run += hist[tid*8 + i]; cum[i] = run; }
            unsigned tot = run;
            unsigned off = tot;
            #pragma unroll
            for (int dd2 = 1; dd2 < 32; dd2 <<= 1) {
                unsigned v = __shfl_up_sync(0xffffffffu, off, dd2);
                if (lane >= dd2) off += v;
            }
            off -= tot;
            unsigned rem = (unsigned)s_remaining;
            #pragma unroll
            for (int i = 0; i < 8; i++) {
                unsigned prev = off + (i ? cum[i-1] : 0u);
                unsigned cu   = off + cum[i];
                if (prev < rem && cu >= rem) {
                    s_prefix = (s_prefix << 8) | (unsigned)(tid*8 + i);
                    s_remaining = (int)(rem - prev);
                }
            }
        }
    };
    // warp-aggregated histogram add
    auto hadd = [&](bool ok, unsigned bkt) {
        unsigned mask = __ballot_sync(0xffffffffu, ok);
        if (ok) {
            unsigned peers = __match_any_sync(mask, bkt);
            if ((peers & ((1u << lane) - 1u)) == 0u)
                atomicAdd(&hist[bkt], __popc(peers));
        }
    };

    // ---- sample phase: 512 points {16t, 16t+1}, exact 32nd smallest ----
    unsigned sd0, sd1;
    dist2(tid * 8, sd0, sd1);
    for (int pass = 0; pass < 4; pass++) {
        hist[tid] = 0;
        __syncthreads();
        unsigned pref = s_prefix;
        int sh = 24 - 8*pass;
        bool ok0 = (pass == 0) || ((sd0 >> (sh + 8)) == pref);
        bool ok1 = (pass == 0) || ((sd1 >> (sh + 8)) == pref);
        hadd(ok0, (sd0 >> sh) & 255u);
        hadd(ok1, (sd1 >> sh) & 255u);
        __syncthreads();
        scan();
        __syncthreads();
    }
    unsigned Tm = s_prefix;    // sample 32nd-smallest >= true 32nd-smallest
    __syncthreads();
    if (tid == 0) { s_prefix = 0u; s_remaining = KK; }

    // ---- main sweep: compare + warp-aggregated compact (d <= Tm) ----
    auto append = [&](unsigned u, int pid) {
        bool isc = (u <= Tm);
        unsigned mk = __ballot_sync(0xffffffffu, isc);
        if (isc) {
            int ldr = __ffs(mk) - 1;
            int basep = 0;
            if (lane == ldr) basep = atomicAdd(&s_ncand, __popc(mk));
            basep = __shfl_sync(mk, basep, ldr);
            int pos = basep + __popc(mk & ((1u << lane) - 1u));
            if (pos < CAP) { cand_dm[pos] = u; cand_id[pos] = pid; }
        }
    };
    #pragma unroll
    for (int jj = 0; jj < 16; jj++) {
        int q = tid + jj*256;
        unsigned u0, u1;
        dist2(q, u0, u1);
        append(u0, 2*q);
        append(u1, 2*q + 1);
    }
    __syncthreads();
    int ncand = s_ncand;
    int* selg = g_sel + (size_t)bm * KK;

    if (ncand <= CAP) {
        // ---- exact 4-pass radix over candidates ----
        int nIter = (ncand + 255) >> 8;
        for (int pass = 0; pass < 4; pass++) {
            hist[tid] = 0;
            __syncthreads();
            unsigned pref = s_prefix;
            int sh = 24 - 8*pass;
            for (int it = 0; it < nIter; it++) {
                int t = it*256 + tid;
                unsigned dv = (t < ncand) ? cand_dm[t] : 0u;
                bool ok = (t < ncand) && ((pass == 0) || ((dv >> (sh + 8)) == pref));
                hadd(ok, (dv >> sh) & 255u);
            }
            __syncthreads();
            scan();
            __syncthreads();
        }
        unsigned thr = s_prefix;
        int rem = s_remaining;
        // ---- selection ----
        for (int it = 0; it < nIter; it++) {
            int t = it*256 + tid;
            if (t < ncand && cand_dm[t] < thr) {
                int s = atomicAdd(&s_cnt, 1);
                selg[s] = cand_id[t];
            }
        }
        __syncthreads();
        int base = s_cnt;
        for (int r = 0; r < rem; r++) {
            if (tid == 0) s_min = 0x7fffffff;
            __syncthreads();
            int last = s_last;
            for (int it = 0; it < nIter; it++) {
                int t = it*256 + tid;
                if (t < ncand && cand_dm[t] == thr && cand_id[t] > last)
                    atomicMin(&s_min, cand_id[t]);
            }
            __syncthreads();
            if (tid == 0) { selg[base + r] = s_min; s_last = s_min; }
            __syncthreads();
        }
    } else {
        // ---- exact fallback: recompute-based full 4-pass radix ----
        __syncthreads();
        if (tid == 0) { s_prefix = 0u; s_remaining = KK; s_cnt = 0; }
        __syncthreads();
        for (int pass = 0; pass < 4; pass++) {
            hist[tid] = 0;
            __syncthreads();
            unsigned pref = s_prefix;
            int sh = 24 - 8*pass;
            for (int jj = 0; jj < 16; jj++) {
                unsigned u0, u1;
                dist2(tid + jj*256, u0, u1);
                bool ok0 = (pass == 0) || ((u0 >> (sh + 8)) == pref);
                bool ok1 = (pass == 0) || ((u1 >> (sh + 8)) == pref);
                hadd(ok0, (u0 >> sh) & 255u);
                hadd(ok1, (u1 >> sh) & 255u);
            }
            __syncthreads();
            scan();
            __syncthreads();
        }
        unsigned thr = s_prefix;
        int rem = s_remaining;
        for (int jj = 0; jj < 16; jj++) {
            int q = tid + jj*256;
            unsigned u0, u1;
            dist2(q, u0, u1);
            if (u0 < thr) { int s = atomicAdd(&s_cnt, 1); selg[s] = 2*q; }
            if (u1 < thr) { int s = atomicAdd(&s_cnt, 1); selg[s] = 2*q + 1; }
        }
        __syncthreads();
        int base = s_cnt;
        for (int r = 0; r < rem; r++) {
            if (tid == 0) s_min = 0x7fffffff;
            __syncthreads();
            int last = s_last;
            for (int jj = 0; jj < 16; jj++) {
                int q = tid + jj*256;
                unsigned u0, u1;
                dist2(q, u0, u1);
                if (u0 == thr && 2*q     > last) atomicMin(&s_min, 2*q);
                if (u1 == thr && 2*q + 1 > last) atomicMin(&s_min, 2*q + 1);
            }
            __syncthreads();
            if (tid == 0) { selg[base + r] = s_min; s_last = s_min; }
            __syncthreads();
        }
    }
}

// ---------------- bf16x3 GEMM via mma.sync (HMMA tensor pipe) -------------
template<int LAYER>
__global__ void __launch_bounds__(256) mma_kernel(const float* __restrict__ bias,
                                                  const float* __restrict__ centers)
{
    constexpr int CO    = (LAYER == 2) ? 128 : 64;
    constexpr int K     = (LAYER == 0) ? 80 : 64;
    constexpr int KC    = K / 8;
    constexpr int NKCH  = K / 16;
    constexpr int ST    = (LAYER == 0) ? 24 : 16;
    constexpr int ASZ   = 128 * ST * 16;
    constexpr int WCOLS = CO / 2;
    constexpr int NT    = WCOLS / 8;
    constexpr int HC    = KC / 2;

    extern __shared__ __align__(16) char dyn[];
    char* Asm = dyn;
    char* Bsm = dyn + ASZ;
    __shared__ float sb[CO], ssum[CO], ssq[CO];
    __shared__ float sS[64], sT[64];

    const int tid = threadIdx.x;
    const size_t rowBase = (size_t)blockIdx.x * 128;
    const int bBat = (int)(rowBase >> 16);

    if (tid < CO) { sb[tid] = bias[tid]; ssum[tid] = 0.f; ssq[tid] = 0.f; }
    if (LAYER > 0 && tid < 64) { sS[tid] = g_s[LAYER-1][tid]; sT[tid] = g_t[LAYER-1][tid]; }
    __syncthreads();

    // ---- A build: 2 threads per row ----
    {
        int row = tid >> 1, half = tid & 1;
        const float* srcf;
        float dx = 0.f, dy = 0.f, dz = 0.f;
        if (LAYER == 0) {
            int p = g_sel[rowBase + row];
            srcf = g_featsT + (((size_t)bBat << 13) + (unsigned)p) * 64;
            float4 X = g_xyz4[((size_t)bBat << 13) + (unsigned)p];
            int bm = (int)((rowBase + row) >> 5);
            dx = X.x - centers[bm*3 + 0];
            dy = X.y - centers[bm*3 + 1];
            dz = X.z - centers[bm*3 + 2];
        } else {
            srcf = ((LAYER == 1) ? g_y1 : g_y2) + (rowBase + row) * 64;
        }
        int rx = row & 7;
        unsigned rowOff = (unsigned)row * (ST*16);
        #pragma unroll
        for (int j = 0; j < HC; j++) {
            int c  = half*HC + j;
            int k0 = c*8;
            float f[8];
            if (LAYER > 0) {
                float4 v0 = *(const float4*)(srcf + k0);
                float4 v1 = *(const float4*)(srcf + k0 + 4);
                f[0]=v0.x; f[1]=v0.y; f[2]=v0.z; f[3]=v0.w;
                f[4]=v1.x; f[5]=v1.y; f[6]=v1.z; f[7]=v1.w;
                #pragma unroll
                for (int i = 0; i < 8; i++)
                    f[i] = fmaxf(fmaf(f[i], sS[k0+i], sT[k0+i]), 0.f);
            } else {
                if (k0 + 8 <= 64) {
                    float4 v0 = *(const float4*)(srcf + k0);
                    float4 v1 = *(const float4*)(srcf + k0 + 4);
                    f[0]=v0.x; f[1]=v0.y; f[2]=v0.z; f[3]=v0.w;
                    f[4]=v1.x; f[5]=v1.y; f[6]=v1.z; f[7]=v1.w;
                } else if (k0 == 64) {
                    f[0]=dx; f[1]=dy; f[2]=dz;
                    f[3]=0.f; f[4]=0.f; f[5]=0.f; f[6]=0.f; f[7]=0.f;
                } else {
                    #pragma unroll
                    for (int i = 0; i < 8; i++) f[i] = 0.f;
                }
            }
            unsigned hv[4], lv[4];
            #pragma unroll
            for (int q = 0; q < 4; q++) {
                __nv_bfloat16 ha, la, hb, lb;
                wsplit(f[2*q],   ha, la);
                wsplit(f[2*q+1], hb, lb);
                hv[q] = pkb(ha, hb); lv[q] = pkb(la, lb);
            }
            unsigned ch = (unsigned)(c ^ rx);
            unsigned cl = (unsigned)((KC + c) ^ rx);
            *(uint4*)(Asm + rowOff + ch*16) = make_uint4(hv[0],hv[1],hv[2],hv[3]);
            *(uint4*)(Asm + rowOff + cl*16) = make_uint4(lv[0],lv[1],lv[2],lv[3]);
        }
    }
    // ---- B copy: hi/lo images -> swizzled smem ----
    {
        const __nv_bfloat16* Wh = (LAYER==0) ? g_Wh0 : (LAYER==1) ? g_Wh1 : g_Wh2;
        const __nv_bfloat16* Wl = (LAYER==0) ? g_Wl0 : (LAYER==1) ? g_Wl1 : g_Wl2;
        for (int i = tid; i < CO * 2 * KC; i += 256) {
            int n = i / (2*KC), c = i % (2*KC);
            const __nv_bfloat16* src = (c < KC) ? (Wh + n*K + c*8)
                                                : (Wl + n*K + (c - KC)*8);
            uint4 v = *(const uint4*)src;
            unsigned cs = (unsigned)(c ^ (n & 7));
            *(uint4*)(Bsm + (unsigned)n*(ST*16) + cs*16) = v;
        }
    }
    __syncthreads();

    // ---- MMA main loop ----
    const uint32_t Abase = smem_u32(Asm);
    const uint32_t Bbase = smem_u32(Bsm);
    const int warp = tid >> 5, lane = tid & 31;
    const int wm = warp >> 1, wn = warp & 1;
    const int Rw = wm*32, Cw = wn*WCOLS;

    const int arow = lane & 15;
    const uint32_t aAddr0 = Abase + (unsigned)(Rw + arow)      * (ST*16);
    const uint32_t aAddr1 = Abase + (unsigned)(Rw + 16 + arow) * (ST*16);
    const unsigned axr = (unsigned)(arow & 7);
    const unsigned aHi = (unsigned)(lane >> 4);
    const int nro  = (lane & 7) + ((lane & 16) >> 1);
    const unsigned bxr = (unsigned)(nro & 7);
    const unsigned bHi = (unsigned)((lane >> 3) & 1);

    float cc[2][NT][4];
    #pragma unroll
    for (int mi = 0; mi < 2; mi++)
        #pragma unroll
        for (int ni = 0; ni < NT; ni++)
            #pragma unroll
            for (int q = 0; q < 4; q++) cc[mi][ni][q] = 0.f;

    #pragma unroll
    for (int s = 0; s < 3; s++) {
        const unsigned sa = (s == 1) ? KC : 0;
        const unsigned sbc = (s == 2) ? KC : 0;
        #pragma unroll
        for (int kc = 0; kc < NKCH; kc++) {
            unsigned ca = sa + kc*2 + aHi;
            unsigned a0r[4], a1r[4];
            ldsm4(a0r, aAddr0 + ((ca ^ axr) << 4));
            ldsm4(a1r, aAddr1 + ((ca ^ axr) << 4));
            unsigned cb = sbc + kc*2 + bHi;
            #pragma unroll
            for (int ntp = 0; ntp < NT/2; ntp++) {
                int brow = Cw + ntp*16 + nro;
                unsigned br[4];
                ldsm4(br, Bbase + (unsigned)brow*(ST*16) + ((cb ^ bxr) << 4));
                mma16816(cc[0][ntp*2],   a0r, br[0], br[1]);
                mma16816(cc[0][ntp*2+1], a0r, br[2], br[3]);
                mma16816(cc[1][ntp*2],   a1r, br[0], br[1]);
                mma16816(cc[1][ntp*2+1], a1r, br[2], br[3]);
            }
        }
    }

    // ---- epilogue: bias, Y store, stats, L2 max ----
    float* Y = (LAYER == 0) ? g_y1 : g_y2;
    const int tq = lane >> 2, tr = lane & 3;
    #pragma unroll
    for (int ni = 0; ni < NT; ni++) {
        int cn = Cw + ni*8 + tr*2;
        float b0 = sb[cn], b1 = sb[cn+1];
        float s0=0.f, s1=0.f, q0=0.f, q1=0.f, m0=-3.4e38f, m1=-3.4e38f;
        #pragma unroll
        for (int mi = 0; mi < 2; mi++) {
            float d0 = cc[mi][ni][0] + b0;
            float d1 = cc[mi][ni][1] + b1;
            float d2 = cc[mi][ni][2] + b0;
            float d3 = cc[mi][ni][3] + b1;
            if (LAYER < 2) {
                size_t r = rowBase + Rw + mi*16 + tq;
                *(float2*)&Y[r*64 + cn]     = make_float2(d0, d1);
                *(float2*)&Y[(r+8)*64 + cn] = make_float2(d2, d3);
            }
            s0 += d0 + d2;  s1 += d1 + d3;
            q0 += d0*d0 + d2*d2;  q1 += d1*d1 + d3*d3;
            m0 = fmaxf(m0, fmaxf(d0, d2));  m1 = fmaxf(m1, fmaxf(d1, d3));
        }
        #pragma unroll
        for (int o = 4; o <= 16; o <<= 1) {
            s0 += __shfl_xor_sync(0xffffffffu, s0, o);
            s1 += __shfl_xor_sync(0xffffffffu, s1, o);
            q0 += __shfl_xor_sync(0xffffffffu, q0, o);
            q1 += __shfl_xor_sync(0xffffffffu, q1, o);
            if (LAYER == 2) {
                m0 = fmaxf(m0, __shfl_xor_sync(0xffffffffu, m0, o));
                m1 = fmaxf(m1, __shfl_xor_sync(0xffffffffu, m1, o));
            }
        }
        if (lane < 4) {
            atomicAdd(&ssum[cn],   s0);
            atomicAdd(&ssum[cn+1], s1);
            atomicAdd(&ssq[cn],    q0);
            atomicAdd(&ssq[cn+1],  q1);
            if (LAYER == 2) {
                int bm = (int)(rowBase >> 5) + wm;
                size_t o0 = ((size_t)(bm >> 11)*128 + (unsigned)cn)*2048 + (unsigned)(bm & 2047);
                g_maxf[o0]        = m0;
                g_maxf[o0 + 2048] = m1;
            }
        }
    }
    __syncthreads();
    if (tid < CO) {
        atomicAdd(&g_sum[LAYER][tid], (double)ssum[tid]);
        atomicAdd(&g_sq [LAYER][tid], (double)ssq [tid]);
    }
}

// ---------------- BN stats -> scale/shift --------------------------------
__global__ void finalize_kernel(int L, const float* __restrict__ g,
                                const float* __restrict__ beta, int Co)
{
    int c = threadIdx.x;
    if (c >= Co) return;
    double inv = 1.0 / (double)NROWS;
    double mu  = g_sum[L][c] * inv;
    double var = g_sq[L][c] * inv - mu*mu;
    if (var < 0.0) var = 0.0;
    float s = g[c] / sqrtf((float)var + BN_EPS);
    g_s[L][c] = s;
    g_t[L][c] = fmaf(-(float)mu, s, beta[c]);
}

// ---------------- BN+ReLU on pre-pooled max, transposed layout -----------
__global__ void maxpool_kernel(float* __restrict__ out)
{
    int i = blockIdx.x * blockDim.x + threadIdx.x;   // over B*128*M = 2M
    int c = (i >> 11) & 127;
    float s = g_s[2][c], t = g_t[2][c];
    out[(size_t)Bb*Mm*3 + i] = fmaxf(fmaf(g_maxf[i], s, t), 0.f);
}

// ---------------- launch ---------------------------------------------------
extern "C" void kernel_launch(void* const* d_in, const int* in_sizes, int n_in,
                              void* d_out, int out_size)
{
    (void)in_sizes; (void)n_in; (void)out_size;
    const float* xyz  = (const float*)d_in[0];
    const float* feats= (const float*)d_in[1];
    const float* W1   = (const float*)d_in[2];
    const float* b1   = (const float*)d_in[3];
    const float* g1   = (const float*)d_in[4];
    const float* be1  = (const float*)d_in[5];
    const float* W2   = (const float*)d_in[6];
    const float* b2   = (const float*)d_in[7];
    const float* g2   = (const float*)d_in[8];
    const float* be2  = (const float*)d_in[9];
    const float* W3   = (const float*)d_in[10];
    const float* b3   = (const float*)d_in[11];
    const float* g3   = (const float*)d_in[12];
    const float* be3  = (const float*)d_in[13];
    float* out = (float*)d_out;
    const float* centers = out;   // knn writes centers into d_out[0 : B*M*3)

    const int SM0 = 128*24*16 + 64*24*16;     // 73728
    const int SM1 = 128*16*16 + 64*16*16;     // 49152
    const int SM2 = 128*16*16 + 128*16*16;    // 65536
    cudaFuncSetAttribute(mma_kernel<0>, cudaFuncAttributeMaxDynamicSharedMemorySize, SM0);
    cudaFuncSetAttribute(mma_kernel<1>, cudaFuncAttributeMaxDynamicSharedMemorySize, SM1);
    cudaFuncSetAttribute(mma_kernel<2>, cudaFuncAttributeMaxDynamicSharedMemorySize, SM2);

    prep_kernel<<<68, 256>>>(W1, W2, W3);
    pad_kernel<<<(Bb*4096)/256, 256>>>(xyz);
    transpose_kernel<<<dim3(Pp/32, CIN/32, Bb), dim3(32, 8)>>>(feats);
    knn_kernel<<<Bb*Mm, 256>>>(out);

    mma_kernel<0><<<NROWS/128, 256, SM0>>>(b1, centers);
    finalize_kernel<<<1, 64>>>(0, g1, be1, 64);
    mma_kernel<1><<<NROWS/128, 256, SM1>>>(b2, centers);
    finalize_kernel<<<1, 64>>>(1, g2, be2, 64);
    mma_kernel<2><<<NROWS/128, 256, SM2>>>(b3, centers);
    finalize_kernel<<<1, 128>>>(2, g3, be3, 128);

    maxpool_kernel<<<(Bb*Mm*128)/256, 256>>>(out);
}

// round 10
// speedup vs baseline: 2.2784x; 1.1999x over previous
#include <cuda_runtime.h>
#include <cuda_bf16.h>
#include <cstdint>

#define Bb   8
#define Pp   8192
#define CIN  64
#define KK   32
#define Mm   2048
#define NROWS (Bb*Mm*KK)     // 524288
#define BN_EPS 1e-5f

// ---------------- scratch (device globals; no allocation) ----------------
__device__ __align__(128) float  g_featsT[(size_t)Bb*Pp*CIN];   // 16 MB
__device__ __align__(128) float4 g_xyz4[(size_t)Bb*Pp];         // (x,y,z,|x|^2)
__device__ __align__(128) int    g_sel[(size_t)NROWS];          // 2 MB
__device__ __align__(128) float  g_y1[(size_t)NROWS*64];        // 134 MB
__device__ __align__(128) float  g_y2[(size_t)NROWS*64];        // 134 MB
__device__ __align__(128) float  g_maxf[(size_t)Bb*128*Mm];     // 8 MB
// weight hi/lo bf16 images (unswizzled, K-major rows)
__device__ __align__(128) __nv_bfloat16 g_Wh0[64*80],  g_Wl0[64*80];
__device__ __align__(128) __nv_bfloat16 g_Wh1[64*64],  g_Wl1[64*64];
__device__ __align__(128) __nv_bfloat16 g_Wh2[128*64], g_Wl2[128*64];
__device__ double g_sum[3][128];
__device__ double g_sq[3][128];
__device__ float  g_s[3][128];
__device__ float  g_t[3][128];

// ---------------- small helpers ------------------------------------------
__device__ __forceinline__ uint32_t smem_u32(const void* p) {
    uint32_t a;
    asm("{ .reg .u64 t; cvta.to.shared.u64 t, %1; cvt.u32.u64 %0, t; }" : "=r"(a) : "l"(p));
    return a;
}
__device__ __forceinline__ unsigned pkb(__nv_bfloat16 a, __nv_bfloat16 b) {
    __nv_bfloat162 t; t.x = a; t.y = b;
    return *(unsigned*)&t;
}
__device__ __forceinline__ void wsplit(float w, __nv_bfloat16& h, __nv_bfloat16& l) {
    h = __float2bfloat16(w);
    l = __float2bfloat16(w - __bfloat162float(h));
}
__device__ __forceinline__ void ldsm4(unsigned* r, uint32_t addr) {
    asm volatile("ldmatrix.sync.aligned.m8n8.x4.shared.b16 {%0,%1,%2,%3}, [%4];"
        : "=r"(r[0]), "=r"(r[1]), "=r"(r[2]), "=r"(r[3]) : "r"(addr));
}
__device__ __forceinline__ void mma16816(float* c, const unsigned* a,
                                         unsigned b0, unsigned b1) {
    asm volatile("mma.sync.aligned.m16n8k16.row.col.f32.bf16.bf16.f32 "
        "{%0,%1,%2,%3}, {%4,%5,%6,%7}, {%8,%9}, {%0,%1,%2,%3};"
        : "+f"(c[0]), "+f"(c[1]), "+f"(c[2]), "+f"(c[3])
        : "r"(a[0]), "r"(a[1]), "r"(a[2]), "r"(a[3]), "r"(b0), "r"(b1));
}
__device__ __forceinline__ unsigned mapu(float d) {
    unsigned u = __float_as_uint(d);
    return u ^ ((unsigned)(((int)u) >> 31) | 0x80000000u);
}

// ---------------- prep: zero stats + bf16 hi/lo weight images -------------
__global__ void prep_kernel(const float* __restrict__ W1,
                            const float* __restrict__ W2,
                            const float* __restrict__ W3)
{
    int tid = blockIdx.x * blockDim.x + threadIdx.x;
    if (tid < 384) { ((double*)g_sum)[tid] = 0.0; ((double*)g_sq)[tid] = 0.0; }
    if (tid >= 5120 + 4096 + 8192) return;
    float w;
    __nv_bfloat16 *ph, *pl;
    int idx;
    if (tid < 5120) {                   // W0: [64][80] = feats(64)+xyz(3)+pad
        int n = tid / 80, k = tid % 80;
        if (k < 64)      w = W1[n*67 + k + 3];
        else if (k < 67) w = W1[n*67 + (k - 64)];
        else             w = 0.f;
        ph = g_Wh0; pl = g_Wl0; idx = tid;
    } else if (tid < 9216) {            // W1: [64][64]
        int t = tid - 5120;
        w = W2[t];
        ph = g_Wh1; pl = g_Wl1; idx = t;
    } else {                            // W2: [128][64]
        int t = tid - 9216;
        w = W3[t];
        ph = g_Wh2; pl = g_Wl2; idx = t;
    }
    __nv_bfloat16 h, l; wsplit(w, h, l);
    ph[idx] = h; pl[idx] = l;
}

// ---------------- xyz -> float4 (x,y,z,|x|^2) -----------------------------
__global__ void pad_kernel(const float* __restrict__ xyz)
{
    int i = blockIdx.x * blockDim.x + threadIdx.x;   // Bb*Pp
    const float* s = xyz + (size_t)i*3;
    float x = s[0], y = s[1], z = s[2];
    float n = __fadd_rn(__fadd_rn(__fmul_rn(x,x), __fmul_rn(y,y)), __fmul_rn(z,z));
    g_xyz4[i] = make_float4(x, y, z, n);
}

// ---------------- feats (B,C,P) -> featsT (B,P,C) ------------------------
__global__ void transpose_kernel(const float* __restrict__ f)
{
    __shared__ float tile[32][33];
    int b  = blockIdx.z;
    int c0 = blockIdx.y * 32;
    int p0 = blockIdx.x * 32;
    int tx = threadIdx.x, ty = threadIdx.y;
    #pragma unroll
    for (int i = ty; i < 32; i += 8)
        tile[i][tx] = f[((size_t)b*CIN + c0 + i)*Pp + p0 + tx];
    __syncthreads();
    #pragma unroll
    for (int i = ty; i < 32; i += 8)
        g_featsT[((size_t)b*Pp + p0 + i)*CIN + c0 + tx] = tile[tx][i];
}

// ---------------- KNN: 4 queries/block, sample pivot, float-compare sweep -
#define CAPQ 1280
__global__ void __launch_bounds__(256, 4) knn_kernel(float* __restrict__ centers_out)
{
    int blk = blockIdx.x;          // 0..4095
    int b   = blk >> 9;
    int mbase = (blk & 511) * 4;

    extern __shared__ char sm[];
    unsigned* hist    = (unsigned*)sm;                 // 1024 bins (4 x 256)
    unsigned* cand_dm = hist + 1024;                   // 4*CAPQ
    int*      cand_id = (int*)(cand_dm + 4*CAPQ);      // 4*CAPQ
    __shared__ float    ctr[4][4];
    __shared__ float    sTf[4];
    __shared__ unsigned s_prefix[4];
    __shared__ int s_remaining[4], s_ncand[4], s_cnt[4];
    __shared__ int s_min, s_last;

    int tid  = threadIdx.x;
    int wid  = tid >> 5;
    int lane = tid & 31;
    const float4* X4 = g_xyz4 + ((size_t)b << 13);

    if (tid < 4) {
        int m = mbase + tid;
        int ci = (m == 2047) ? 8191
               : (int)(__fmul_rn(8191.0f, __fdiv_rn((float)m, 2047.0f)));
        float4 cp = X4[ci];
        ctr[tid][0] = cp.x; ctr[tid][1] = cp.y; ctr[tid][2] = cp.z; ctr[tid][3] = cp.w;
        float* co = centers_out + (size_t)(b*2048 + m)*3;
        co[0] = cp.x; co[1] = cp.y; co[2] = cp.z;
        s_prefix[tid] = 0u; s_remaining[tid] = KK;
        s_ncand[tid] = 0; s_cnt[tid] = 0;
    }
    __syncthreads();
    float cxq[4], cyq[4], czq[4], cnq[4];
    #pragma unroll
    for (int q = 0; q < 4; q++) {
        cxq[q] = ctr[q][0]; cyq[q] = ctr[q][1]; czq[q] = ctr[q][2]; cnq[q] = ctr[q][3];
    }
    // exact same arithmetic chain as before (mul,mul,mul,add,add / add, mul2, sub)
    auto distq = [&](int q, float4 X) -> float {
        float dt = __fadd_rn(__fadd_rn(__fmul_rn(cxq[q],X.x), __fmul_rn(cyq[q],X.y)),
                             __fmul_rn(czq[q],X.z));
        return __fsub_rn(__fadd_rn(cnq[q], X.w), __fmul_rn(2.0f, dt));
    };
    // warp-aggregated hist add (bkt may include q*256 offset)
    auto hadd = [&](bool ok, unsigned bkt) {
        unsigned mask = __ballot_sync(0xffffffffu, ok);
        if (ok) {
            unsigned peers = __match_any_sync(mask, bkt);
            if ((peers & ((1u << lane) - 1u)) == 0u)
                atomicAdd(&hist[bkt], __popc(peers));
        }
    };
    // scan of 256 bins at hist+base by the executing warp; updates query q state
    auto scanq = [&](int q, int base) {
        unsigned cum[8];
        unsigned run = 0;
        #pragma unroll
        for (int i = 0; i < 8; i++) { run += hist[base + lane*8 + i]; cum[i] = run; }
        unsigned tot = run;
        unsigned off = tot;
        #pragma unroll
        for (int dd = 1; dd < 32; dd <<= 1) {
            unsigned v = __shfl_up_sync(0xffffffffu, off, dd);
            if (lane >= dd) off += v;
        }
        off -= tot;
        unsigned rem = (unsigned)s_remaining[q];
        #pragma unroll
        for (int i = 0; i < 8; i++) {
            unsigned prev = off + (i ? cum[i-1] : 0u);
            unsigned cu   = off + cum[i];
            if (prev < rem && cu >= rem) {
                s_prefix[q] = (s_prefix[q] << 8) | (unsigned)(lane*8 + i);
                s_remaining[q] = (int)(rem - prev);
            }
        }
    };

    // ---- sample phase: 512 points {16t,16t+1}; 4 queries in parallel ----
    unsigned sd[4][2];
    {
        float4 A = __ldg(X4 + 16*tid);
        float4 Bp = __ldg(X4 + 16*tid + 1);
        #pragma unroll
        for (int q = 0; q < 4; q++) {
            sd[q][0] = mapu(distq(q, A));
            sd[q][1] = mapu(distq(q, Bp));
        }
    }
    for (int pass = 0; pass < 4; pass++) {
        #pragma unroll
        for (int t = tid; t < 1024; t += 256) hist[t] = 0;
        __syncthreads();
        unsigned prefq[4];
        #pragma unroll
        for (int q = 0; q < 4; q++) prefq[q] = s_prefix[q];
        int sh = 24 - 8*pass;
        #pragma unroll
        for (int q = 0; q < 4; q++) {
            #pragma unroll
            for (int k = 0; k < 2; k++) {
                bool ok = (pass == 0) || ((sd[q][k] >> (sh + 8)) == prefq[q]);
                hadd(ok, (unsigned)(q*256) + ((sd[q][k] >> sh) & 255u));
            }
        }
        __syncthreads();
        if (wid < 4) scanq(wid, wid*256);
        __syncthreads();
    }
    if (tid < 4) {
        unsigned mv = s_prefix[tid];
        unsigned u  = (mv & 0x80000000u) ? (mv ^ 0x80000000u) : ~mv;
        sTf[tid] = __uint_as_float(u);
        s_prefix[tid] = 0u; s_remaining[tid] = KK;
    }
    __syncthreads();
    float Tf[4] = {sTf[0], sTf[1], sTf[2], sTf[3]};

    // ---- main sweep: 1 LDG.128/point, 4 queries, compare + rare append ----
    #pragma unroll 4
    for (int jj = 0; jj < 32; jj++) {
        int p = tid + jj*256;
        float4 X = __ldg(X4 + p);
        #pragma unroll
        for (int q = 0; q < 4; q++) {
            float d = distq(q, X);
            if (d <= Tf[q]) {
                int pos = atomicAdd(&s_ncand[q], 1);
                if (pos < CAPQ) {
                    cand_dm[q*CAPQ + pos] = mapu(d);
                    cand_id[q*CAPQ + pos] = p;
                }
            }
        }
    }
    __syncthreads();

    // ---- per query: exact radix over candidates + selection (serial) ----
    for (int q = 0; q < 4; q++) {
        int nc = s_ncand[q];
        int* selg = g_sel + (size_t)(b*2048 + mbase + q) * KK;
        if (nc <= CAPQ) {
            int nIter = (nc + 255) >> 8;
            for (int pass = 0; pass < 4; pass++) {
                hist[tid] = 0;
                __syncthreads();
                unsigned pref = s_prefix[q];
                int sh = 24 - 8*pass;
                for (int it = 0; it < nIter; it++) {
                    int t = it*256 + tid;
                    unsigned dv = (t < nc) ? cand_dm[q*CAPQ + t] : 0u;
                    bool ok = (t < nc) && ((pass == 0) || ((dv >> (sh + 8)) == pref));
                    hadd(ok, (dv >> sh) & 255u);
                }
                __syncthreads();
                if (wid == 0) scanq(q, 0);
                __syncthreads();
            }
            unsigned thr = s_prefix[q];
            int rem = s_remaining[q];
            for (int it = 0; it < nIter; it++) {
                int t = it*256 + tid;
                if (t < nc && cand_dm[q*CAPQ + t] < thr) {
                    int s = atomicAdd(&s_cnt[q], 1);
                    selg[s] = cand_id[q*CAPQ + t];
                }
            }
            if (tid == 0) s_last = -1;
            __syncthreads();
            int base = s_cnt[q];
            for (int r = 0; r < rem; r++) {
                if (tid == 0) s_min = 0x7fffffff;
                __syncthreads();
                int last = s_last;
                for (int it = 0; it < nIter; it++) {
                    int t = it*256 + tid;
                    if (t < nc && cand_dm[q*CAPQ + t] == thr && cand_id[q*CAPQ + t] > last)
                        atomicMin(&s_min, cand_id[q*CAPQ + t]);
                }
                __syncthreads();
                if (tid == 0) { selg[base + r] = s_min; s_last = s_min; }
                __syncthreads();
            }
        } else {
            // ---- exact fallback: full recompute radix for this query ----
            __syncthreads();
            if (tid == 0) { s_prefix[q] = 0u; s_remaining[q] = KK; s_cnt[q] = 0; s_last = -1; }
            __syncthreads();
            for (int pass = 0; pass < 4; pass++) {
                hist[tid] = 0;
                __syncthreads();
                unsigned pref = s_prefix[q];
                int sh = 24 - 8*pass;
                for (int jj = 0; jj < 32; jj++) {
                    float4 X = __ldg(X4 + tid + jj*256);
                    unsigned u = mapu(distq(q, X));
                    bool ok = (pass == 0) || ((u >> (sh + 8)) == pref);
                    hadd(ok, (u >> sh) & 255u);
                }
                __syncthreads();
                if (wid == 0) scanq(q, 0);
                __syncthreads();
            }
            unsigned thr = s_prefix[q];
            int rem = s_remaining[q];
            for (int jj = 0; jj < 32; jj++) {
                int p = tid + jj*256;
                float4 X = __ldg(X4 + p);
                if (mapu(distq(q, X)) < thr) {
                    int s = atomicAdd(&s_cnt[q], 1);
                    selg[s] = p;
                }
            }
            __syncthreads();
            int base = s_cnt[q];
            for (int r = 0; r < rem; r++) {
                if (tid == 0) s_min = 0x7fffffff;
                __syncthreads();
                int last = s_last;
                for (int jj = 0; jj < 32; jj++) {
                    int p = tid + jj*256;
                    float4 X = __ldg(X4 + p);
                    if (mapu(distq(q, X)) == thr && p > last) atomicMin(&s_min, p);
                }
                __syncthreads();
                if (tid == 0) { selg[base + r] = s_min; s_last = s_min; }
                __syncthreads();
            }
        }
    }
}

// ---------------- bf16x3 GEMM via mma.sync (HMMA tensor pipe) -------------
template<int LAYER>
__global__ void __launch_bounds__(256) mma_kernel(const float* __restrict__ bias,
                                                  const float* __restrict__ centers)
{
    constexpr int CO    = (LAYER == 2) ? 128 : 64;
    constexpr int K     = (LAYER == 0) ? 80 : 64;
    constexpr int KC    = K / 8;
    constexpr int NKCH  = K / 16;
    constexpr int ST    = (LAYER == 0) ? 24 : 16;
    constexpr int ASZ   = 128 * ST * 16;
    constexpr int WCOLS = CO / 2;
    constexpr int NT    = WCOLS / 8;
    constexpr int HC    = KC / 2;

    extern __shared__ __align__(16) char dyn[];
    char* Asm = dyn;
    char* Bsm = dyn + ASZ;
    __shared__ float sb[CO], ssum[CO], ssq[CO];
    __shared__ float sS[64], sT[64];

    const int tid = threadIdx.x;
    const size_t rowBase = (size_t)blockIdx.x * 128;
    const int bBat = (int)(rowBase >> 16);

    if (tid < CO) { sb[tid] = bias[tid]; ssum[tid] = 0.f; ssq[tid] = 0.f; }
    if (LAYER > 0 && tid < 64) { sS[tid] = g_s[LAYER-1][tid]; sT[tid] = g_t[LAYER-1][tid]; }
    __syncthreads();

    // ---- A build: 2 threads per row ----
    {
        int row = tid >> 1, half = tid & 1;
        const float* srcf;
        float dx = 0.f, dy = 0.f, dz = 0.f;
        if (LAYER == 0) {
            int p = g_sel[rowBase + row];
            srcf = g_featsT + (((size_t)bBat << 13) + (unsigned)p) * 64;
            float4 X = g_xyz4[((size_t)bBat << 13) + (unsigned)p];
            int bm = (int)((rowBase + row) >> 5);
            dx = X.x - centers[bm*3 + 0];
            dy = X.y - centers[bm*3 + 1];
            dz = X.z - centers[bm*3 + 2];
        } else {
            srcf = ((LAYER == 1) ? g_y1 : g_y2) + (rowBase + row) * 64;
        }
        int rx = row & 7;
        unsigned rowOff = (unsigned)row * (ST*16);
        #pragma unroll
        for (int j = 0; j < HC; j++) {
            int c  = half*HC + j;
            int k0 = c*8;
            float f[8];
            if (LAYER > 0) {
                float4 v0 = *(const float4*)(srcf + k0);
                float4 v1 = *(const float4*)(srcf + k0 + 4);
                f[0]=v0.x; f[1]=v0.y; f[2]=v0.z; f[3]=v0.w;
                f[4]=v1.x; f[5]=v1.y; f[6]=v1.z; f[7]=v1.w;
                #pragma unroll
                for (int i = 0; i < 8; i++)
                    f[i] = fmaxf(fmaf(f[i], sS[k0+i], sT[k0+i]), 0.f);
            } else {
                if (k0 + 8 <= 64) {
                    float4 v0 = *(const float4*)(srcf + k0);
                    float4 v1 = *(const float4*)(srcf + k0 + 4);
                    f[0]=v0.x; f[1]=v0.y; f[2]=v0.z; f[3]=v0.w;
                    f[4]=v1.x; f[5]=v1.y; f[6]=v1.z; f[7]=v1.w;
                } else if (k0 == 64) {
                    f[0]=dx; f[1]=dy; f[2]=dz;
                    f[3]=0.f; f[4]=0.f; f[5]=0.f; f[6]=0.f; f[7]=0.f;
                } else {
                    #pragma unroll
                    for (int i = 0; i < 8; i++) f[i] = 0.f;
                }
            }
            unsigned hv[4], lv[4];
            #pragma unroll
            for (int q = 0; q < 4; q++) {
                __nv_bfloat16 ha, la, hb, lb;
                wsplit(f[2*q],   ha, la);
                wsplit(f[2*q+1], hb, lb);
                hv[q] = pkb(ha, hb); lv[q] = pkb(la, lb);
            }
            unsigned ch = (unsigned)(c ^ rx);
            unsigned cl = (unsigned)((KC + c) ^ rx);
            *(uint4*)(Asm + rowOff + ch*16) = make_uint4(hv[0],hv[1],hv[2],hv[3]);
            *(uint4*)(Asm + rowOff + cl*16) = make_uint4(lv[0],lv[1],lv[2],lv[3]);
        }
    }
    // ---- B copy: hi/lo images -> swizzled smem ----
    {
        const __nv_bfloat16* Wh = (LAYER==0) ? g_Wh0 : (LAYER==1) ? g_Wh1 : g_Wh2;
        const __nv_bfloat16* Wl = (LAYER==0) ? g_Wl0 : (LAYER==1) ? g_Wl1 : g_Wl2;
        for (int i = tid; i < CO * 2 * KC; i += 256) {
            int n = i / (2*KC), c = i % (2*KC);
            const __nv_bfloat16* src = (c < KC) ? (Wh + n*K + c*8)
                                                : (Wl + n*K + (c - KC)*8);
            uint4 v = *(const uint4*)src;
            unsigned cs = (unsigned)(c ^ (n & 7));
            *(uint4*)(Bsm + (unsigned)n*(ST*16) + cs*16) = v;
        }
    }
    __syncthreads();

    // ---- MMA main loop ----
    const uint32_t Abase = smem_u32(Asm);
    const uint32_t Bbase = smem_u32(Bsm);
    const int warp = tid >> 5, lane = tid & 31;
    const int wm = warp >> 1, wn = warp & 1;
    const int Rw = wm*32, Cw = wn*WCOLS;

    const int arow = lane & 15;
    const uint32_t aAddr0 = Abase + (unsigned)(Rw + arow)      * (ST*16);
    const uint32_t aAddr1 = Abase + (unsigned)(Rw + 16 + arow) * (ST*16);
    const unsigned axr = (unsigned)(arow & 7);
    const unsigned aHi = (unsigned)(lane >> 4);
    const int nro  = (lane & 7) + ((lane & 16) >> 1);
    const unsigned bxr = (unsigned)(nro & 7);
    const unsigned bHi = (unsigned)((lane >> 3) & 1);

    float cc[2][NT][4];
    #pragma unroll
    for (int mi = 0; mi < 2; mi++)
        #pragma unroll
        for (int ni = 0; ni < NT; ni++)
            #pragma unroll
            for (int q = 0; q < 4; q++) cc[mi][ni][q] = 0.f;

    #pragma unroll
    for (int s = 0; s < 3; s++) {
        const unsigned sa = (s == 1) ? KC : 0;
        const unsigned sbc = (s == 2) ? KC : 0;
        #pragma unroll
        for (int kc = 0; kc < NKCH; kc++) {
            unsigned ca = sa + kc*2 + aHi;
            unsigned a0r[4], a1r[4];
            ldsm4(a0r, aAddr0 + ((ca ^ axr) << 4));
            ldsm4(a1r, aAddr1 + ((ca ^ axr) << 4));
            unsigned cb = sbc + kc*2 + bHi;
            #pragma unroll
            for (int ntp = 0; ntp < NT/2; ntp++) {
                int brow = Cw + ntp*16 + nro;
                unsigned br[4];
                ldsm4(br, Bbase + (unsigned)brow*(ST*16) + ((cb ^ bxr) << 4));
                mma16816(cc[0][ntp*2],   a0r, br[0], br[1]);
                mma16816(cc[0][ntp*2+1], a0r, br[2], br[3]);
                mma16816(cc[1][ntp*2],   a1r, br[0], br[1]);
                mma16816(cc[1][ntp*2+1], a1r, br[2], br[3]);
            }
        }
    }

    // ---- epilogue: bias, Y store, stats, L2 max ----
    float* Y = (LAYER == 0) ? g_y1 : g_y2;
    const int tq = lane >> 2, tr = lane & 3;
    #pragma unroll
    for (int ni = 0; ni < NT; ni++) {
        int cn = Cw + ni*8 + tr*2;
        float b0 = sb[cn], b1 = sb[cn+1];
        float s0=0.f, s1=0.f, q0=0.f, q1=0.f, m0=-3.4e38f, m1=-3.4e38f;
        #pragma unroll
        for (int mi = 0; mi < 2; mi++) {
            float d0 = cc[mi][ni][0] + b0;
            float d1 = cc[mi][ni][1] + b1;
            float d2 = cc[mi][ni][2] + b0;
            float d3 = cc[mi][ni][3] + b1;
            if (LAYER < 2) {
                size_t r = rowBase + Rw + mi*16 + tq;
                *(float2*)&Y[r*64 + cn]     = make_float2(d0, d1);
                *(float2*)&Y[(r+8)*64 + cn] = make_float2(d2, d3);
            }
            s0 += d0 + d2;  s1 += d1 + d3;
            q0 += d0*d0 + d2*d2;  q1 += d1*d1 + d3*d3;
            m0 = fmaxf(m0, fmaxf(d0, d2));  m1 = fmaxf(m1, fmaxf(d1, d3));
        }
        #pragma unroll
        for (int o = 4; o <= 16; o <<= 1) {
            s0 += __shfl_xor_sync(0xffffffffu, s0, o);
            s1 += __shfl_xor_sync(0xffffffffu, s1, o);
            q0 += __shfl_xor_sync(0xffffffffu, q0, o);
            q1 += __shfl_xor_sync(0xffffffffu, q1, o);
            if (LAYER == 2) {
                m0 = fmaxf(m0, __shfl_xor_sync(0xffffffffu, m0, o));
                m1 = fmaxf(m1, __shfl_xor_sync(0xffffffffu, m1, o));
            }
        }
        if (lane < 4) {
            atomicAdd(&ssum[cn],   s0);
            atomicAdd(&ssum[cn+1], s1);
            atomicAdd(&ssq[cn],    q0);
            atomicAdd(&ssq[cn+1],  q1);
            if (LAYER == 2) {
                int bm = (int)(rowBase >> 5) + wm;
                size_t o0 = ((size_t)(bm >> 11)*128 + (unsigned)cn)*2048 + (unsigned)(bm & 2047);
                g_maxf[o0]        = m0;
                g_maxf[o0 + 2048] = m1;
            }
        }
    }
    __syncthreads();
    if (tid < CO) {
        atomicAdd(&g_sum[LAYER][tid], (double)ssum[tid]);
        atomicAdd(&g_sq [LAYER][tid], (double)ssq [tid]);
    }
}

// ---------------- BN stats -> scale/shift --------------------------------
__global__ void finalize_kernel(int L, const float* __restrict__ g,
                                const float* __restrict__ beta, int Co)
{
    int c = threadIdx.x;
    if (c >= Co) return;
    double inv = 1.0 / (double)NROWS;
    double mu  = g_sum[L][c] * inv;
    double var = g_sq[L][c] * inv - mu*mu;
    if (var < 0.0) var = 0.0;
    float s = g[c] / sqrtf((float)var + BN_EPS);
    g_s[L][c] = s;
    g_t[L][c] = fmaf(-(float)mu, s, beta[c]);
}

// ---------------- BN+ReLU on pre-pooled max, transposed layout -----------
__global__ void maxpool_kernel(float* __restrict__ out)
{
    int i = blockIdx.x * blockDim.x + threadIdx.x;   // over B*128*M = 2M
    int c = (i >> 11) & 127;
    float s = g_s[2][c], t = g_t[2][c];
    out[(size_t)Bb*Mm*3 + i] = fmaxf(fmaf(g_maxf[i], s, t), 0.f);
}

// ---------------- launch ---------------------------------------------------
extern "C" void kernel_launch(void* const* d_in, const int* in_sizes, int n_in,
                              void* d_out, int out_size)
{
    (void)in_sizes; (void)n_in; (void)out_size;
    const float* xyz  = (const float*)d_in[0];
    const float* feats= (const float*)d_in[1];
    const float* W1   = (const float*)d_in[2];
    const float* b1   = (const float*)d_in[3];
    const float* g1   = (const float*)d_in[4];
    const float* be1  = (const float*)d_in[5];
    const float* W2   = (const float*)d_in[6];
    const float* b2   = (const float*)d_in[7];
    const float* g2   = (const float*)d_in[8];
    const float* be2  = (const float*)d_in[9];
    const float* W3   = (const float*)d_in[10];
    const float* b3   = (const float*)d_in[11];
    const float* g3   = (const float*)d_in[12];
    const float* be3  = (const float*)d_in[13];
    float* out = (float*)d_out;
    const float* centers = out;   // knn writes centers into d_out[0 : B*M*3)

    const int SM0 = 128*24*16 + 64*24*16;     // 73728
    const int SM1 = 128*16*16 + 64*16*16;     // 49152
    const int SM2 = 128*16*16 + 128*16*16;    // 65536
    cudaFuncSetAttribute(mma_kernel<0>, cudaFuncAttributeMaxDynamicSharedMemorySize, SM0);
    cudaFuncSetAttribute(mma_kernel<1>, cudaFuncAttributeMaxDynamicSharedMemorySize, SM1);
    cudaFuncSetAttribute(mma_kernel<2>, cudaFuncAttributeMaxDynamicSharedMemorySize, SM2);

    const int KNN_SMEM = 1024*4 + 4*CAPQ*4*2;   // hist + cand arrays = 45056 B

    prep_kernel<<<68, 256>>>(W1, W2, W3);
    pad_kernel<<<(Bb*Pp)/256, 256>>>(xyz);
    transpose_kernel<<<dim3(Pp/32, CIN/32, Bb), dim3(32, 8)>>>(feats);
    knn_kernel<<<Bb*512, 256, KNN_SMEM>>>(out);

    mma_kernel<0><<<NROWS/128, 256, SM0>>>(b1, centers);
    finalize_kernel<<<1, 64>>>(0, g1, be1, 64);
    mma_kernel<1><<<NROWS/128, 256, SM1>>>(b2, centers);
    finalize_kernel<<<1, 64>>>(1, g2, be2, 64);
    mma_kernel<2><<<NROWS/128, 256, SM2>>>(b3, centers);
    finalize_kernel<<<1, 128>>>(2, g3, be3, 128);

    maxpool_kernel<<<(Bb*Mm*128)/256, 256>>>(out);
}

// round 11
// speedup vs baseline: 2.3005x; 1.0097x over previous
#include <cuda_runtime.h>
#include <cuda_bf16.h>
#include <cstdint>

#define Bb   8
#define Pp   8192
#define CIN  64
#define KK   32
#define Mm   2048
#define NROWS (Bb*Mm*KK)     // 524288
#define BN_EPS 1e-5f

// ---------------- scratch (device globals; no allocation) ----------------
__device__ __align__(128) __nv_bfloat16 g_fh[(size_t)Bb*Pp*CIN]; // feats hi (8 MB)
__device__ __align__(128) __nv_bfloat16 g_fl[(size_t)Bb*Pp*CIN]; // feats lo (8 MB)
__device__ __align__(128) float4 g_xyz4[(size_t)Bb*Pp];          // (x,y,z,|x|^2)
__device__ __align__(128) int    g_sel[(size_t)NROWS];           // 2 MB
__device__ __align__(128) float  g_y1[(size_t)NROWS*64];         // 134 MB
__device__ __align__(128) float  g_y2[(size_t)NROWS*64];         // 134 MB
__device__ __align__(128) float  g_maxf[(size_t)Bb*128*Mm];      // 8 MB
// weight hi/lo bf16 images (unswizzled, K-major rows)
__device__ __align__(128) __nv_bfloat16 g_Wh0[64*80],  g_Wl0[64*80];
__device__ __align__(128) __nv_bfloat16 g_Wh1[64*64],  g_Wl1[64*64];
__device__ __align__(128) __nv_bfloat16 g_Wh2[128*64], g_Wl2[128*64];
__device__ double g_sum[3][128];
__device__ double g_sq[3][128];
__device__ float  g_s[3][128];
__device__ float  g_t[3][128];

// ---------------- small helpers ------------------------------------------
__device__ __forceinline__ uint32_t smem_u32(const void* p) {
    uint32_t a;
    asm("{ .reg .u64 t; cvta.to.shared.u64 t, %1; cvt.u32.u64 %0, t; }" : "=r"(a) : "l"(p));
    return a;
}
__device__ __forceinline__ unsigned pkb(__nv_bfloat16 a, __nv_bfloat16 b) {
    __nv_bfloat162 t; t.x = a; t.y = b;
    return *(unsigned*)&t;
}
__device__ __forceinline__ void wsplit(float w, __nv_bfloat16& h, __nv_bfloat16& l) {
    h = __float2bfloat16(w);
    l = __float2bfloat16(w - __bfloat162float(h));
}
// cvt two fp32 -> bf16x2 {lo, hi} with rn (hi operand goes to upper half)
__device__ __forceinline__ unsigned cvt2bf(float hi, float lo) {
    unsigned r;
    asm("cvt.rn.bf16x2.f32 %0, %1, %2;" : "=r"(r) : "f"(hi), "f"(lo));
    return r;
}
__device__ __forceinline__ void ldsm4(unsigned* r, uint32_t addr) {
    asm volatile("ldmatrix.sync.aligned.m8n8.x4.shared.b16 {%0,%1,%2,%3}, [%4];"
        : "=r"(r[0]), "=r"(r[1]), "=r"(r[2]), "=r"(r[3]) : "r"(addr));
}
__device__ __forceinline__ void mma16816(float* c, const unsigned* a,
                                         unsigned b0, unsigned b1) {
    asm volatile("mma.sync.aligned.m16n8k16.row.col.f32.bf16.bf16.f32 "
        "{%0,%1,%2,%3}, {%4,%5,%6,%7}, {%8,%9}, {%0,%1,%2,%3};"
        : "+f"(c[0]), "+f"(c[1]), "+f"(c[2]), "+f"(c[3])
        : "r"(a[0]), "r"(a[1]), "r"(a[2]), "r"(a[3]), "r"(b0), "r"(b1));
}
__device__ __forceinline__ unsigned mapu(float d) {
    unsigned u = __float_as_uint(d);
    return u ^ ((unsigned)(((int)u) >> 31) | 0x80000000u);
}
// packed f32x2 (exact per-lane fp32 rn)
#define PACK2(d, lo, hi)    asm("mov.b64 %0, {%1,%2};" : "=l"(d) : "f"(lo), "f"(hi))
#define UNPACK2F(lo, hi, v) asm("mov.b64 {%0,%1}, %2;" : "=f"(lo), "=f"(hi) : "l"(v))
#define MUL2(d, a, b)       asm("mul.rn.f32x2 %0, %1, %2;" : "=l"(d) : "l"(a), "l"(b))
#define ADD2(d, a, b)       asm("add.rn.f32x2 %0, %1, %2;" : "=l"(d) : "l"(a), "l"(b))

// ---------------- prep: zero stats + bf16 hi/lo weight images -------------
__global__ void prep_kernel(const float* __restrict__ W1,
                            const float* __restrict__ W2,
                            const float* __restrict__ W3)
{
    int tid = blockIdx.x * blockDim.x + threadIdx.x;
    if (tid < 384) { ((double*)g_sum)[tid] = 0.0; ((double*)g_sq)[tid] = 0.0; }
    if (tid >= 5120 + 4096 + 8192) return;
    float w;
    __nv_bfloat16 *ph, *pl;
    int idx;
    if (tid < 5120) {                   // W0: [64][80] = feats(64)+xyz(3)+pad
        int n = tid / 80, k = tid % 80;
        if (k < 64)      w = W1[n*67 + k + 3];
        else if (k < 67) w = W1[n*67 + (k - 64)];
        else             w = 0.f;
        ph = g_Wh0; pl = g_Wl0; idx = tid;
    } else if (tid < 9216) {            // W1: [64][64]
        int t = tid - 5120;
        w = W2[t];
        ph = g_Wh1; pl = g_Wl1; idx = t;
    } else {                            // W2: [128][64]
        int t = tid - 9216;
        w = W3[t];
        ph = g_Wh2; pl = g_Wl2; idx = t;
    }
    __nv_bfloat16 h, l; wsplit(w, h, l);
    ph[idx] = h; pl[idx] = l;
}

// ---------------- xyz -> float4 (x,y,z,|x|^2) -----------------------------
__global__ void pad_kernel(const float* __restrict__ xyz)
{
    int i = blockIdx.x * blockDim.x + threadIdx.x;   // Bb*Pp
    const float* s = xyz + (size_t)i*3;
    float x = s[0], y = s[1], z = s[2];
    float n = __fadd_rn(__fadd_rn(__fmul_rn(x,x), __fmul_rn(y,y)), __fmul_rn(z,z));
    g_xyz4[i] = make_float4(x, y, z, n);
}

// ---------------- feats (B,C,P) -> bf16 hi/lo (B,P,C) ---------------------
__global__ void transpose_kernel(const float* __restrict__ f)
{
    __shared__ float tile[32][33];
    int b  = blockIdx.z;
    int c0 = blockIdx.y * 32;
    int p0 = blockIdx.x * 32;
    int tx = threadIdx.x, ty = threadIdx.y;
    #pragma unroll
    for (int i = ty; i < 32; i += 8)
        tile[i][tx] = f[((size_t)b*CIN + c0 + i)*Pp + p0 + tx];
    __syncthreads();
    #pragma unroll
    for (int i = ty; i < 32; i += 8) {
        float v = tile[tx][i];
        __nv_bfloat16 h, l; wsplit(v, h, l);
        size_t o = ((size_t)b*Pp + p0 + i)*CIN + c0 + tx;
        g_fh[o] = h;
        g_fl[o] = l;
    }
}

// ---------------- KNN: 4 q/block, sample pivot, packed f32x2 sweep --------
#define CAPQ 1280
__global__ void __launch_bounds__(256, 4) knn_kernel(float* __restrict__ centers_out)
{
    int blk = blockIdx.x;          // 0..4095
    int b   = blk >> 9;
    int mbase = (blk & 511) * 4;

    extern __shared__ char sm[];
    unsigned* hist    = (unsigned*)sm;                 // 1024 bins (4 x 256)
    unsigned* cand_dm = hist + 1024;                   // 4*CAPQ
    int*      cand_id = (int*)(cand_dm + 4*CAPQ);      // 4*CAPQ
    __shared__ float    ctr[4][4];
    __shared__ float    sTf[4];
    __shared__ unsigned s_prefix[4];
    __shared__ int s_remaining[4], s_ncand[4], s_cnt[4];
    __shared__ int s_min, s_last;

    int tid  = threadIdx.x;
    int wid  = tid >> 5;
    int lane = tid & 31;
    const float4* X4 = g_xyz4 + ((size_t)b << 13);

    if (tid < 4) {
        int m = mbase + tid;
        int ci = (m == 2047) ? 8191
               : (int)(__fmul_rn(8191.0f, __fdiv_rn((float)m, 2047.0f)));
        float4 cp = X4[ci];
        ctr[tid][0] = cp.x; ctr[tid][1] = cp.y; ctr[tid][2] = cp.z; ctr[tid][3] = cp.w;
        float* co = centers_out + (size_t)(b*2048 + m)*3;
        co[0] = cp.x; co[1] = cp.y; co[2] = cp.z;
        s_prefix[tid] = 0u; s_remaining[tid] = KK;
        s_ncand[tid] = 0; s_cnt[tid] = 0;
    }
    __syncthreads();
    float cxq[4], cyq[4], czq[4], cnq[4];
    #pragma unroll
    for (int q = 0; q < 4; q++) {
        cxq[q] = ctr[q][0]; cyq[q] = ctr[q][1]; czq[q] = ctr[q][2]; cnq[q] = ctr[q][3];
    }
    // scalar distance (reference chain) — sample + fallback
    auto distq = [&](int q, float4 X) -> float {
        float dt = __fadd_rn(__fadd_rn(__fmul_rn(cxq[q],X.x), __fmul_rn(cyq[q],X.y)),
                             __fmul_rn(czq[q],X.z));
        return __fsub_rn(__fadd_rn(cnq[q], X.w), __fmul_rn(2.0f, dt));
    };
    auto hadd = [&](bool ok, unsigned bkt) {
        unsigned mask = __ballot_sync(0xffffffffu, ok);
        if (ok) {
            unsigned peers = __match_any_sync(mask, bkt);
            if ((peers & ((1u << lane) - 1u)) == 0u)
                atomicAdd(&hist[bkt], __popc(peers));
        }
    };
    auto scanq = [&](int q, int base) {
        unsigned cum[8];
        unsigned run = 0;
        #pragma unroll
        for (int i = 0; i < 8; i++) { run += hist[base + lane*8 + i]; cum[i] = run; }
        unsigned tot = run;
        unsigned off = tot;
        #pragma unroll
        for (int dd = 1; dd < 32; dd <<= 1) {
            unsigned v = __shfl_up_sync(0xffffffffu, off, dd);
            if (lane >= dd) off += v;
        }
        off -= tot;
        unsigned rem = (unsigned)s_remaining[q];
        #pragma unroll
        for (int i = 0; i < 8; i++) {
            unsigned prev = off + (i ? cum[i-1] : 0u);
            unsigned cu   = off + cum[i];
            if (prev < rem && cu >= rem) {
                s_prefix[q] = (s_prefix[q] << 8) | (unsigned)(lane*8 + i);
                s_remaining[q] = (int)(rem - prev);
            }
        }
    };

    // ---- sample phase: 512 points {16t,16t+1}; 4 queries in parallel ----
    unsigned sd[4][2];
    {
        float4 A = __ldg(X4 + 16*tid);
        float4 Bp = __ldg(X4 + 16*tid + 1);
        #pragma unroll
        for (int q = 0; q < 4; q++) {
            sd[q][0] = mapu(distq(q, A));
            sd[q][1] = mapu(distq(q, Bp));
        }
    }
    for (int pass = 0; pass < 4; pass++) {
        #pragma unroll
        for (int t = tid; t < 1024; t += 256) hist[t] = 0;
        __syncthreads();
        unsigned prefq[4];
        #pragma unroll
        for (int q = 0; q < 4; q++) prefq[q] = s_prefix[q];
        int sh = 24 - 8*pass;
        #pragma unroll
        for (int q = 0; q < 4; q++) {
            #pragma unroll
            for (int k = 0; k < 2; k++) {
                bool ok = (pass == 0) || ((sd[q][k] >> (sh + 8)) == prefq[q]);
                hadd(ok, (unsigned)(q*256) + ((sd[q][k] >> sh) & 255u));
            }
        }
        __syncthreads();
        if (wid < 4) scanq(wid, wid*256);
        __syncthreads();
    }
    if (tid < 4) {
        unsigned mv = s_prefix[tid];
        unsigned u  = (mv & 0x80000000u) ? (mv ^ 0x80000000u) : ~mv;
        sTf[tid] = __uint_as_float(u);
        s_prefix[tid] = 0u; s_remaining[tid] = KK;
    }
    __syncthreads();
    float Tf[4] = {sTf[0], sTf[1], sTf[2], sTf[3]};

    // packed query constants: {q0,q1} and {q2,q3}
    unsigned long long qx01, qx23, qy01, qy23, qz01, qz23, qn01, qn23;
    PACK2(qx01, cxq[0], cxq[1]); PACK2(qx23, cxq[2], cxq[3]);
    PACK2(qy01, cyq[0], cyq[1]); PACK2(qy23, cyq[2], cyq[3]);
    PACK2(qz01, czq[0], czq[1]); PACK2(qz23, czq[2], czq[3]);
    PACK2(qn01, cnq[0], cnq[1]); PACK2(qn23, cnq[2], cnq[3]);

    // ---- main sweep: 1 LDG.128/point, packed f32x2 distances ----
    #pragma unroll 4
    for (int jj = 0; jj < 32; jj++) {
        int p = tid + jj*256;
        float4 X = __ldg(X4 + p);
        unsigned long long Xx, Xy, Xz, Xw;
        PACK2(Xx, X.x, X.x); PACK2(Xy, X.y, X.y);
        PACK2(Xz, X.z, X.z); PACK2(Xw, X.w, X.w);
        unsigned long long t, u, d01, d23;
        // q0,q1: dt = (cx*x + cy*y) + cz*z; d = (cn+xn) + (-(dt+dt))
        MUL2(t, qx01, Xx); MUL2(u, qy01, Xy); ADD2(t, t, u);
        MUL2(u, qz01, Xz); ADD2(t, t, u);
        ADD2(t, t, t); t ^= 0x8000000080000000ULL;
        ADD2(u, qn01, Xw); ADD2(d01, u, t);
        // q2,q3
        MUL2(t, qx23, Xx); MUL2(u, qy23, Xy); ADD2(t, t, u);
        MUL2(u, qz23, Xz); ADD2(t, t, u);
        ADD2(t, t, t); t ^= 0x8000000080000000ULL;
        ADD2(u, qn23, Xw); ADD2(d23, u, t);
        float d0, d1, d2, d3;
        UNPACK2F(d0, d1, d01);
        UNPACK2F(d2, d3, d23);
        if (d0 <= Tf[0]) {
            int pos = atomicAdd(&s_ncand[0], 1);
            if (pos < CAPQ) { cand_dm[0*CAPQ + pos] = mapu(d0); cand_id[0*CAPQ + pos] = p; }
        }
        if (d1 <= Tf[1]) {
            int pos = atomicAdd(&s_ncand[1], 1);
            if (pos < CAPQ) { cand_dm[1*CAPQ + pos] = mapu(d1); cand_id[1*CAPQ + pos] = p; }
        }
        if (d2 <= Tf[2]) {
            int pos = atomicAdd(&s_ncand[2], 1);
            if (pos < CAPQ) { cand_dm[2*CAPQ + pos] = mapu(d2); cand_id[2*CAPQ + pos] = p; }
        }
        if (d3 <= Tf[3]) {
            int pos = atomicAdd(&s_ncand[3], 1);
            if (pos < CAPQ) { cand_dm[3*CAPQ + pos] = mapu(d3); cand_id[3*CAPQ + pos] = p; }
        }
    }
    __syncthreads();

    // ---- per query: exact radix over candidates + selection (serial) ----
    for (int q = 0; q < 4; q++) {
        int nc = s_ncand[q];
        int* selg = g_sel + (size_t)(b*2048 + mbase + q) * KK;
        if (nc <= CAPQ) {
            int nIter = (nc + 255) >> 8;
            for (int pass = 0; pass < 4; pass++) {
                hist[tid] = 0;
                __syncthreads();
                unsigned pref = s_prefix[q];
                int sh = 24 - 8*pass;
                for (int it = 0; it < nIter; it++) {
                    int t = it*256 + tid;
                    unsigned dv = (t < nc) ? cand_dm[q*CAPQ + t] : 0u;
                    bool ok = (t < nc) && ((pass == 0) || ((dv >> (sh + 8)) == pref));
                    hadd(ok, (dv >> sh) & 255u);
                }
                __syncthreads();
                if (wid == 0) scanq(q, 0);
                __syncthreads();
            }
            unsigned thr = s_prefix[q];
            int rem = s_remaining[q];
            for (int it = 0; it < nIter; it++) {
                int t = it*256 + tid;
                if (t < nc && cand_dm[q*CAPQ + t] < thr) {
                    int s = atomicAdd(&s_cnt[q], 1);
                    selg[s] = cand_id[q*CAPQ + t];
                }
            }
            if (tid == 0) s_last = -1;
            __syncthreads();
            int base = s_cnt[q];
            for (int r = 0; r < rem; r++) {
                if (tid == 0) s_min = 0x7fffffff;
                __syncthreads();
                int last = s_last;
                for (int it = 0; it < nIter; it++) {
                    int t = it*256 + tid;
                    if (t < nc && cand_dm[q*CAPQ + t] == thr && cand_id[q*CAPQ + t] > last)
                        atomicMin(&s_min, cand_id[q*CAPQ + t]);
                }
                __syncthreads();
                if (tid == 0) { selg[base + r] = s_min; s_last = s_min; }
                __syncthreads();
            }
        } else {
            // ---- exact fallback: full recompute radix for this query ----
            __syncthreads();
            if (tid == 0) { s_prefix[q] = 0u; s_remaining[q] = KK; s_cnt[q] = 0; s_last = -1; }
            __syncthreads();
            for (int pass = 0; pass < 4; pass++) {
                hist[tid] = 0;
                __syncthreads();
                unsigned pref = s_prefix[q];
                int sh = 24 - 8*pass;
                for (int jj = 0; jj < 32; jj++) {
                    float4 X = __ldg(X4 + tid + jj*256);
                    unsigned u = mapu(distq(q, X));
                    bool ok = (pass == 0) || ((u >> (sh + 8)) == pref);
                    hadd(ok, (u >> sh) & 255u);
                }
                __syncthreads();
                if (wid == 0) scanq(q, 0);
                __syncthreads();
            }
            unsigned thr = s_prefix[q];
            int rem = s_remaining[q];
            for (int jj = 0; jj < 32; jj++) {
                int p = tid + jj*256;
                float4 X = __ldg(X4 + p);
                if (mapu(distq(q, X)) < thr) {
                    int s = atomicAdd(&s_cnt[q], 1);
                    selg[s] = p;
                }
            }
            __syncthreads();
            int base = s_cnt[q];
            for (int r = 0; r < rem; r++) {
                if (tid == 0) s_min = 0x7fffffff;
                __syncthreads();
                int last = s_last;
                for (int jj = 0; jj < 32; jj++) {
                    int p = tid + jj*256;
                    float4 X = __ldg(X4 + p);
                    if (mapu(distq(q, X)) == thr && p > last) atomicMin(&s_min, p);
                }
                __syncthreads();
                if (tid == 0) { selg[base + r] = s_min; s_last = s_min; }
                __syncthreads();
            }
        }
    }
}

// ---------------- bf16x3 GEMM via mma.sync (HMMA tensor pipe) -------------
template<int LAYER>
__global__ void __launch_bounds__(256) mma_kernel(const float* __restrict__ bias,
                                                  const float* __restrict__ centers)
{
    constexpr int CO    = (LAYER == 2) ? 128 : 64;
    constexpr int K     = (LAYER == 0) ? 80 : 64;
    constexpr int KC    = K / 8;
    constexpr int NKCH  = K / 16;
    constexpr int ST    = (LAYER == 0) ? 24 : 16;
    constexpr int ASZ   = 128 * ST * 16;
    constexpr int WCOLS = CO / 2;
    constexpr int NT    = WCOLS / 8;
    constexpr int HC    = KC / 2;

    extern __shared__ __align__(16) char dyn[];
    char* Asm = dyn;
    char* Bsm = dyn + ASZ;
    __shared__ float sb[CO], ssum[CO], ssq[CO];
    __shared__ float sS[64], sT[64];

    const int tid = threadIdx.x;
    const size_t rowBase = (size_t)blockIdx.x * 128;
    const int bBat = (int)(rowBase >> 16);

    if (tid < CO) { sb[tid] = bias[tid]; ssum[tid] = 0.f; ssq[tid] = 0.f; }
    if (LAYER > 0 && tid < 64) { sS[tid] = g_s[LAYER-1][tid]; sT[tid] = g_t[LAYER-1][tid]; }
    __syncthreads();

    // ---- A build: 2 threads per row ----
    {
        int row = tid >> 1, half = tid & 1;
        int rx = row & 7;
        unsigned rowOff = (unsigned)row * (ST*16);
        if (LAYER == 0) {
            int p = g_sel[rowBase + row];
            const uint4* FH = (const uint4*)g_fh + (((size_t)bBat << 13) + (unsigned)p) * 8;
            const uint4* FL = (const uint4*)g_fl + (((size_t)bBat << 13) + (unsigned)p) * 8;
            #pragma unroll
            for (int j = 0; j < HC; j++) {
                int c = half*HC + j;
                uint4 hv4, lv4;
                if (c < 8) {
                    hv4 = __ldg(FH + c);
                    lv4 = __ldg(FL + c);
                } else if (c == 8) {
                    float4 X = g_xyz4[((size_t)bBat << 13) + (unsigned)p];
                    int bm = (int)((rowBase + row) >> 5);
                    float dx = X.x - centers[bm*3 + 0];
                    float dy = X.y - centers[bm*3 + 1];
                    float dz = X.z - centers[bm*3 + 2];
                    unsigned h01 = cvt2bf(dy, dx);
                    float h0f = __uint_as_float(h01 << 16);
                    float h1f = __uint_as_float(h01 & 0xffff0000u);
                    unsigned l01 = cvt2bf(dy - h1f, dx - h0f);
                    unsigned h2 = cvt2bf(0.f, dz);
                    float h2f = __uint_as_float(h2 << 16);
                    unsigned l2 = cvt2bf(0.f, dz - h2f);
                    hv4 = make_uint4(h01, h2, 0u, 0u);
                    lv4 = make_uint4(l01, l2, 0u, 0u);
                } else {
                    hv4 = make_uint4(0u, 0u, 0u, 0u);
                    lv4 = make_uint4(0u, 0u, 0u, 0u);
                }
                unsigned ch = (unsigned)(c ^ rx);
                unsigned cl = (unsigned)((KC + c) ^ rx);
                *(uint4*)(Asm + rowOff + ch*16) = hv4;
                *(uint4*)(Asm + rowOff + cl*16) = lv4;
            }
        } else {
            const float* srcf = ((LAYER == 1) ? g_y1 : g_y2) + (rowBase + row) * 64;
            #pragma unroll
            for (int j = 0; j < HC; j++) {
                int c  = half*HC + j;
                int k0 = c*8;
                float4 v0 = *(const float4*)(srcf + k0);
                float4 v1 = *(const float4*)(srcf + k0 + 4);
                float f[8] = {v0.x,v0.y,v0.z,v0.w,v1.x,v1.y,v1.z,v1.w};
                #pragma unroll
                for (int i = 0; i < 8; i++)
                    f[i] = fmaxf(fmaf(f[i], sS[k0+i], sT[k0+i]), 0.f);
                unsigned hv[4], lv[4];
                #pragma unroll
                for (int q = 0; q < 4; q++) {
                    float f0 = f[2*q], f1 = f[2*q+1];
                    unsigned h = cvt2bf(f1, f0);
                    float h0f = __uint_as_float(h << 16);
                    float h1f = __uint_as_float(h & 0xffff0000u);
                    hv[q] = h;
                    lv[q] = cvt2bf(f1 - h1f, f0 - h0f);
                }
                unsigned ch = (unsigned)(c ^ rx);
                unsigned cl = (unsigned)((KC + c) ^ rx);
                *(uint4*)(Asm + rowOff + ch*16) = make_uint4(hv[0],hv[1],hv[2],hv[3]);
                *(uint4*)(Asm + rowOff + cl*16) = make_uint4(lv[0],lv[1],lv[2],lv[3]);
            }
        }
    }
    // ---- B copy: hi/lo images -> swizzled smem ----
    {
        const __nv_bfloat16* Wh = (LAYER==0) ? g_Wh0 : (LAYER==1) ? g_Wh1 : g_Wh2;
        const __nv_bfloat16* Wl = (LAYER==0) ? g_Wl0 : (LAYER==1) ? g_Wl1 : g_Wl2;
        for (int i = tid; i < CO * 2 * KC; i += 256) {
            int n = i / (2*KC), c = i % (2*KC);
            const __nv_bfloat16* src = (c < KC) ? (Wh + n*K + c*8)
                                                : (Wl + n*K + (c - KC)*8);
            uint4 v = *(const uint4*)src;
            unsigned cs = (unsigned)(c ^ (n & 7));
            *(uint4*)(Bsm + (unsigned)n*(ST*16) + cs*16) = v;
        }
    }
    __syncthreads();

    // ---- MMA main loop ----
    const uint32_t Abase = smem_u32(Asm);
    const uint32_t Bbase = smem_u32(Bsm);
    const int warp = tid >> 5, lane = tid & 31;
    const int wm = warp >> 1, wn = warp & 1;
    const int Rw = wm*32, Cw = wn*WCOLS;

    const int arow = lane & 15;
    const uint32_t aAddr0 = Abase + (unsigned)(Rw + arow)      * (ST*16);
    const uint32_t aAddr1 = Abase + (unsigned)(Rw + 16 + arow) * (ST*16);
    const unsigned axr = (unsigned)(arow & 7);
    const unsigned aHi = (unsigned)(lane >> 4);
    const int nro  = (lane & 7) + ((lane & 16) >> 1);
    const unsigned bxr = (unsigned)(nro & 7);
    const unsigned bHi = (unsigned)((lane >> 3) & 1);

    float cc[2][NT][4];
    #pragma unroll
    for (int mi = 0; mi < 2; mi++)
        #pragma unroll
        for (int ni = 0; ni < NT; ni++)
            #pragma unroll
            for (int q = 0; q < 4; q++) cc[mi][ni][q] = 0.f;

    #pragma unroll
    for (int s = 0; s < 3; s++) {
        const unsigned sa = (s == 1) ? KC : 0;
        const unsigned sbc = (s == 2) ? KC : 0;
        #pragma unroll
        for (int kc = 0; kc < NKCH; kc++) {
            unsigned ca = sa + kc*2 + aHi;
            unsigned a0r[4], a1r[4];
            ldsm4(a0r, aAddr0 + ((ca ^ axr) << 4));
            ldsm4(a1r, aAddr1 + ((ca ^ axr) << 4));
            unsigned cb = sbc + kc*2 + bHi;
            #pragma unroll
            for (int ntp = 0; ntp < NT/2; ntp++) {
                int brow = Cw + ntp*16 + nro;
                unsigned br[4];
                ldsm4(br, Bbase + (unsigned)brow*(ST*16) + ((cb ^ bxr) << 4));
                mma16816(cc[0][ntp*2],   a0r, br[0], br[1]);
                mma16816(cc[0][ntp*2+1], a0r, br[2], br[3]);
                mma16816(cc[1][ntp*2],   a1r, br[0], br[1]);
                mma16816(cc[1][ntp*2+1], a1r, br[2], br[3]);
            }
        }
    }

    // ---- epilogue: bias, Y store, stats, L2 max ----
    float* Y = (LAYER == 0) ? g_y1 : g_y2;
    const int tq = lane >> 2, tr = lane & 3;
    #pragma unroll
    for (int ni = 0; ni < NT; ni++) {
        int cn = Cw + ni*8 + tr*2;
        float b0 = sb[cn], b1 = sb[cn+1];
        float s0=0.f, s1=0.f, q0=0.f, q1=0.f, m0=-3.4e38f, m1=-3.4e38f;
        #pragma unroll
        for (int mi = 0; mi < 2; mi++) {
            float d0 = cc[mi][ni][0] + b0;
            float d1 = cc[mi][ni][1] + b1;
            float d2 = cc[mi][ni][2] + b0;
            float d3 = cc[mi][ni][3] + b1;
            if (LAYER < 2) {
                size_t r = rowBase + Rw + mi*16 + tq;
                *(float2*)&Y[r*64 + cn]     = make_float2(d0, d1);
                *(float2*)&Y[(r+8)*64 + cn] = make_float2(d2, d3);
            }
            s0 += d0 + d2;  s1 += d1 + d3;
            q0 += d0*d0 + d2*d2;  q1 += d1*d1 + d3*d3;
            m0 = fmaxf(m0, fmaxf(d0, d2));  m1 = fmaxf(m1, fmaxf(d1, d3));
        }
        #pragma unroll
        for (int o = 4; o <= 16; o <<= 1) {
            s0 += __shfl_xor_sync(0xffffffffu, s0, o);
            s1 += __shfl_xor_sync(0xffffffffu, s1, o);
            q0 += __shfl_xor_sync(0xffffffffu, q0, o);
            q1 += __shfl_xor_sync(0xffffffffu, q1, o);
            if (LAYER == 2) {
                m0 = fmaxf(m0, __shfl_xor_sync(0xffffffffu, m0, o));
                m1 = fmaxf(m1, __shfl_xor_sync(0xffffffffu, m1, o));
            }
        }
        if (lane < 4) {
            atomicAdd(&ssum[cn],   s0);
            atomicAdd(&ssum[cn+1], s1);
            atomicAdd(&ssq[cn],    q0);
            atomicAdd(&ssq[cn+1],  q1);
            if (LAYER == 2) {
                int bm = (int)(rowBase >> 5) + wm;
                size_t o0 = ((size_t)(bm >> 11)*128 + (unsigned)cn)*2048 + (unsigned)(bm & 2047);
                g_maxf[o0]        = m0;
                g_maxf[o0 + 2048] = m1;
            }
        }
    }
    __syncthreads();
    if (tid < CO) {
        atomicAdd(&g_sum[LAYER][tid], (double)ssum[tid]);
        atomicAdd(&g_sq [LAYER][tid], (double)ssq [tid]);
    }
}

// ---------------- BN stats -> scale/shift --------------------------------
__global__ void finalize_kernel(int L, const float* __restrict__ g,
                                const float* __restrict__ beta, int Co)
{
    int c = threadIdx.x;
    if (c >= Co) return;
    double inv = 1.0 / (double)NROWS;
    double mu  = g_sum[L][c] * inv;
    double var = g_sq[L][c] * inv - mu*mu;
    if (var < 0.0) var = 0.0;
    float s = g[c] / sqrtf((float)var + BN_EPS);
    g_s[L][c] = s;
    g_t[L][c] = fmaf(-(float)mu, s, beta[c]);
}

// ---------------- BN+ReLU on pre-pooled max, transposed layout -----------
__global__ void maxpool_kernel(float* __restrict__ out)
{
    int i = blockIdx.x * blockDim.x + threadIdx.x;   // over B*128*M = 2M
    int c = (i >> 11) & 127;
    float s = g_s[2][c], t = g_t[2][c];
    out[(size_t)Bb*Mm*3 + i] = fmaxf(fmaf(g_maxf[i], s, t), 0.f);
}

// ---------------- launch ---------------------------------------------------
extern "C" void kernel_launch(void* const* d_in, const int* in_sizes, int n_in,
                              void* d_out, int out_size)
{
    (void)in_sizes; (void)n_in; (void)out_size;
    const float* xyz  = (const float*)d_in[0];
    const float* feats= (const float*)d_in[1];
    const float* W1   = (const float*)d_in[2];
    const float* b1   = (const float*)d_in[3];
    const float* g1   = (const float*)d_in[4];
    const float* be1  = (const float*)d_in[5];
    const float* W2   = (const float*)d_in[6];
    const float* b2   = (const float*)d_in[7];
    const float* g2   = (const float*)d_in[8];
    const float* be2  = (const float*)d_in[9];
    const float* W3   = (const float*)d_in[10];
    const float* b3   = (const float*)d_in[11];
    const float* g3   = (const float*)d_in[12];
    const float* be3  = (const float*)d_in[13];
    float* out = (float*)d_out;
    const float* centers = out;   // knn writes centers into d_out[0 : B*M*3)

    const int SM0 = 128*24*16 + 64*24*16;     // 73728
    const int SM1 = 128*16*16 + 64*16*16;     // 49152
    const int SM2 = 128*16*16 + 128*16*16;    // 65536
    cudaFuncSetAttribute(mma_kernel<0>, cudaFuncAttributeMaxDynamicSharedMemorySize, SM0);
    cudaFuncSetAttribute(mma_kernel<1>, cudaFuncAttributeMaxDynamicSharedMemorySize, SM1);
    cudaFuncSetAttribute(mma_kernel<2>, cudaFuncAttributeMaxDynamicSharedMemorySize, SM2);

    const int KNN_SMEM = 1024*4 + 4*CAPQ*4*2;   // hist + cand arrays = 45056 B

    prep_kernel<<<68, 256>>>(W1, W2, W3);
    pad_kernel<<<(Bb*Pp)/256, 256>>>(xyz);
    transpose_kernel<<<dim3(Pp/32, CIN/32, Bb), dim3(32, 8)>>>(feats);
    knn_kernel<<<Bb*512, 256, KNN_SMEM>>>(out);

    mma_kernel<0><<<NROWS/128, 256, SM0>>>(b1, centers);
    finalize_kernel<<<1, 64>>>(0, g1, be1, 64);
    mma_kernel<1><<<NROWS/128, 256, SM1>>>(b2, centers);
    finalize_kernel<<<1, 64>>>(1, g2, be2, 64);
    mma_kernel<2><<<NROWS/128, 256, SM2>>>(b3, centers);
    finalize_kernel<<<1, 128>>>(2, g3, be3, 128);

    maxpool_kernel<<<(Bb*Mm*128)/256, 256>>>(out);
}